// round 5
// baseline (speedup 1.0000x reference)
#include <cuda_runtime.h>
#include <cuda_bf16.h>
#include <math.h>

#define BATCHN 2
#define SEQ    2048
#define BLTOT  4096
#define DM     1024
#define DIN    2048
#define NH     32
#define HD     64
#define NK     32
#define CONVD  2176
#define DPROJ  4256
#define NCH    32
#define CH     64
#define LR     48
#define XBC_OFF 2048
#define DT_OFF  4224
#define THETA_CLIPF 1.5707963267948966f

#define K3_IN  (3*DM)     // 3072
#define K3_OUT (3*DIN)    // 6144
#define NPAD_W 4352       // 34*128

// ---------------- scratch (static device globals; no allocation) ----------------
__device__ __align__(256) float g_zx [BLTOT*DPROJ];
__device__ __align__(256) float g_dt [BLTOT*NH];
__device__ __align__(256) float g_xs [BLTOT*DIN];
__device__ __align__(256) float g_Br [BLTOT*NK];
__device__ __align__(256) float g_Bi [BLTOT*NK];
__device__ __align__(256) float g_Cr [BLTOT*NK];
__device__ __align__(256) float g_Ci [BLTOT*NK];
__device__ __align__(256) float g_t1 [BLTOT*LR];
__device__ __align__(256) float g_lzr[BLTOT*NH*NK];
__device__ __align__(256) float g_lzi[BLTOT*NH*NK];
__device__ __align__(256) float g_Pr [BATCHN*NCH*NH*CH*NK];
__device__ __align__(256) float g_Pi [BATCHN*NCH*NH*CH*NK];
__device__ __align__(256) float g_Er [BATCHN*NCH*NH*NK];
__device__ __align__(256) float g_Ei [BATCHN*NCH*NH*NK];
__device__ __align__(256) float g_Dr [BATCHN*NCH*NH*HD*NK];
__device__ __align__(256) float g_Di [BATCHN*NCH*NH*HD*NK];
__device__ __align__(256) float g_Sr [BATCHN*NCH*NH*HD*NK];
__device__ __align__(256) float g_Si [BATCHN*NCH*NH*HD*NK];
__device__ __align__(256) float g_y  [BLTOT*DIN];

// bf16 3-segment split buffers
__device__ __align__(256) __nv_bfloat16 g_x3 [BLTOT*K3_IN];     // x split  [hi,lo,hi]
__device__ __align__(256) __nv_bfloat16 g_wi3[NPAD_W*K3_IN];    // in_w     [hi,hi,lo]
__device__ __align__(256) __nv_bfloat16 g_w13[128*K3_IN];       // w1^T     [hi,hi,lo]
__device__ __align__(256) __nv_bfloat16 g_g3 [BLTOT*K3_OUT];    // gated    [hi,lo,hi]
__device__ __align__(256) __nv_bfloat16 g_wo3[DM*K3_OUT];       // out_w    [hi,hi,lo]

// ================= helpers ======================================================
#define LDSM4(R0,R1,R2,R3,ADDR) \
    asm volatile("ldmatrix.sync.aligned.m8n8.x4.shared.b16 {%0,%1,%2,%3}, [%4];" \
                 : "=r"(R0),"=r"(R1),"=r"(R2),"=r"(R3) : "r"(ADDR))

#define CP_ASYNC16(DST,SRC) \
    asm volatile("cp.async.cg.shared.global [%0], [%1], 16;" :: "r"(DST), "l"(SRC))
#define CP_COMMIT asm volatile("cp.async.commit_group;")
#define CP_WAIT1  asm volatile("cp.async.wait_group 1;")
#define CP_WAIT0  asm volatile("cp.async.wait_group 0;")

__device__ __forceinline__ void mma_bf16(float* d, const unsigned* a,
                                         unsigned b0, unsigned b1)
{
    asm volatile("mma.sync.aligned.m16n8k16.row.col.f32.bf16.bf16.f32 "
                 "{%0,%1,%2,%3}, {%4,%5,%6,%7}, {%8,%9}, {%0,%1,%2,%3};"
                 : "+f"(d[0]), "+f"(d[1]), "+f"(d[2]), "+f"(d[3])
                 : "r"(a[0]), "r"(a[1]), "r"(a[2]), "r"(a[3]), "r"(b0), "r"(b1));
}

__device__ __forceinline__ unsigned smem_u32(const void* p)
{
    return (unsigned)__cvta_generic_to_shared(p);
}

// ---------------- split fp32 -> 3-segment bf16 ----------------------------------
// loSeg=1 : [hi, lo, hi]  (activations)   loSeg=2 : [hi, hi, lo]  (weights)
__global__ void split3_kernel(const float* __restrict__ src,
                              __nv_bfloat16* __restrict__ dst,
                              int n4, int K, int loSeg)
{
    int i = blockIdx.x * blockDim.x + threadIdx.x;
    if (i >= n4) return;
    int base = i * 4;
    int r = base / K, k = base - r * K;
    float4 v = *(const float4*)(src + base);
    float xs[4] = {v.x, v.y, v.z, v.w};
    __nv_bfloat16 h[4], l[4];
    #pragma unroll
    for (int j = 0; j < 4; j++) {
        h[j] = __float2bfloat16(xs[j]);
        l[j] = __float2bfloat16(xs[j] - __bfloat162float(h[j]));
    }
    size_t ro = (size_t)r * 3 * K + k;
    __nv_bfloat162 hp0, hp1, lp0, lp1;
    hp0.x = h[0]; hp0.y = h[1]; hp1.x = h[2]; hp1.y = h[3];
    lp0.x = l[0]; lp0.y = l[1]; lp1.x = l[2]; lp1.y = l[3];
    int hiSeg = (loSeg == 1) ? 2 : 1;
    ((__nv_bfloat162*)(dst + ro))[0] = hp0;
    ((__nv_bfloat162*)(dst + ro))[1] = hp1;
    ((__nv_bfloat162*)(dst + ro + (size_t)hiSeg*K))[0] = hp0;
    ((__nv_bfloat162*)(dst + ro + (size_t)hiSeg*K))[1] = hp1;
    ((__nv_bfloat162*)(dst + ro + (size_t)loSeg*K))[0] = lp0;
    ((__nv_bfloat162*)(dst + ro + (size_t)loSeg*K))[1] = lp1;
}

// ---------------- w1 (DM x LR) -> transposed 3-seg [128][3*DM] ------------------
__global__ void splitW1_kernel(const float* __restrict__ w1)
{
    int idx = blockIdx.x * blockDim.x + threadIdx.x;
    if (idx >= DM * LR) return;
    int k = idx / LR, n = idx % LR;
    float v = w1[idx];
    __nv_bfloat16 h = __float2bfloat16(v);
    __nv_bfloat16 l = __float2bfloat16(v - __bfloat162float(h));
    size_t ro = (size_t)n * K3_IN + k;
    g_w13[ro]        = h;
    g_w13[ro + DM]   = h;
    g_w13[ro + 2*DM] = l;
}

// ================= bf16 GEMM: C[M,N] = A[M,K3] * B[N,K3]^T ======================
#define GSTR 40

__global__ __launch_bounds__(256) void gemm_bf16(const __nv_bfloat16* __restrict__ A,
                                                 const __nv_bfloat16* __restrict__ B,
                                                 float* __restrict__ C,
                                                 int M, int N, int K3)
{
    __shared__ __nv_bfloat16 sA[2][128*GSTR];
    __shared__ __nv_bfloat16 sB[2][128*GSTR];

    int tid = threadIdx.x, lane = tid & 31, wid = tid >> 5;
    int wm = wid & 3;          // m offset = 32*wm
    int wn = wid >> 2;         // n offset = 64*wn
    int row0 = blockIdx.y * 128, col0 = blockIdx.x * 128;

    float acc[2][8][4];
    #pragma unroll
    for (int a = 0; a < 2; a++)
        #pragma unroll
        for (int b = 0; b < 8; b++)
            #pragma unroll
            for (int c = 0; c < 4; c++) acc[a][b][c] = 0.f;

    int NT = K3 >> 5;

    // prologue: async-load tile 0 into stage 0
    {
        #pragma unroll
        for (int i = 0; i < 2; i++) {
            int f = tid + i*256, r = f >> 2, kc = (f & 3) << 3;
            CP_ASYNC16(smem_u32(&sA[0][r*GSTR + kc]), A + (size_t)(row0+r)*K3 + kc);
            CP_ASYNC16(smem_u32(&sB[0][r*GSTR + kc]), B + (size_t)(col0+r)*K3 + kc);
        }
        CP_COMMIT;
    }

    for (int kt = 0; kt < NT; kt++) {
        if (kt + 1 < NT) {
            int k0 = (kt + 1) << 5, st = (kt + 1) & 1;
            #pragma unroll
            for (int i = 0; i < 2; i++) {
                int f = tid + i*256, r = f >> 2, kc = (f & 3) << 3;
                CP_ASYNC16(smem_u32(&sA[st][r*GSTR + kc]), A + (size_t)(row0+r)*K3 + k0 + kc);
                CP_ASYNC16(smem_u32(&sB[st][r*GSTR + kc]), B + (size_t)(col0+r)*K3 + k0 + kc);
            }
            CP_COMMIT;
            CP_WAIT1;
        } else {
            CP_WAIT0;
        }
        __syncthreads();

        const __nv_bfloat16* a_s = sA[kt & 1];
        const __nv_bfloat16* b_s = sB[kt & 1];

        #pragma unroll
        for (int kh = 0; kh < 32; kh += 16) {
            unsigned ah[2][4];
            #pragma unroll
            for (int mf = 0; mf < 2; mf++) {
                int r = wm*32 + mf*16 + (lane & 15);
                int cc = kh + ((lane >> 4) << 3);
                LDSM4(ah[mf][0], ah[mf][1], ah[mf][2], ah[mf][3],
                      smem_u32(&a_s[r*GSTR + cc]));
            }
            #pragma unroll
            for (int np = 0; np < 4; np++) {
                int nr  = wn*64 + np*16 + (lane & 7) + ((lane >> 4) << 3);
                int kof = kh + (((lane >> 3) & 1) << 3);
                unsigned bh[4];
                LDSM4(bh[0], bh[1], bh[2], bh[3], smem_u32(&b_s[nr*GSTR + kof]));
                #pragma unroll
                for (int mf = 0; mf < 2; mf++) {
                    mma_bf16(acc[mf][np*2+0], ah[mf], bh[0], bh[1]);
                    mma_bf16(acc[mf][np*2+1], ah[mf], bh[2], bh[3]);
                }
            }
        }
        __syncthreads();
    }

    #pragma unroll
    for (int mf = 0; mf < 2; mf++) {
        int r = row0 + wm*32 + mf*16 + (lane >> 2);
        #pragma unroll
        for (int nf = 0; nf < 8; nf++) {
            int c = col0 + wn*64 + nf*8 + ((lane & 3) << 1);
            if (c + 1 < N) {
                *(float2*)&C[(size_t)r*N + c]     = make_float2(acc[mf][nf][0], acc[mf][nf][1]);
                *(float2*)&C[(size_t)(r+8)*N + c] = make_float2(acc[mf][nf][2], acc[mf][nf][3]);
            } else if (c < N) {
                C[(size_t)r*N + c]     = acc[mf][nf][0];
                C[(size_t)(r+8)*N + c] = acc[mf][nf][2];
            }
        }
    }
}

// ---------------- dt = softplus(zx[:, DT_OFF+h] + dt_bias[h]) --------------------
__global__ void dt_kernel(const float* __restrict__ dt_bias)
{
    int idx = blockIdx.x * blockDim.x + threadIdx.x;
    if (idx >= BLTOT * NH) return;
    int bl = idx >> 5, hh = idx & 31;
    float v = g_zx[(size_t)bl * DPROJ + DT_OFF + hh] + dt_bias[hh];
    float sp = (v > 20.f) ? v : log1pf(expf(v));
    g_dt[idx] = sp;
}

// ---------------- depthwise causal conv (width 4) + silu + split -----------------
__global__ void conv_kernel(const float* __restrict__ conv_w,
                            const float* __restrict__ conv_b)
{
    int c = blockIdx.x * blockDim.x + threadIdx.x;
    if (c >= CONVD) return;
    int bl = blockIdx.y;
    int l = bl & (SEQ - 1);
    float acc = conv_b[c];
    #pragma unroll
    for (int kk = 0; kk < 4; kk++) {
        int lt = l + kk - 3;
        if (lt >= 0)
            acc += g_zx[(size_t)(bl + kk - 3) * DPROJ + XBC_OFF + c] * conv_w[c*4 + kk];
    }
    float a = acc / (1.f + __expf(-acc));
    if (c < DIN) {
        g_xs[(size_t)bl * DIN + c] = a;
    } else {
        int c2 = c - DIN;
        if (c2 < 64) {
            int k = c2 >> 1;
            if (c2 & 1) g_Bi[bl*NK + k] = a; else g_Br[bl*NK + k] = a;
        } else {
            int c3 = c2 - 64;
            int k = c3 >> 1;
            if (c3 & 1) g_Ci[bl*NK + k] = a; else g_Cr[bl*NK + k] = a;
        }
    }
}

// ---------------- lora2 (tanh applied on load) -----------------------------------
__global__ __launch_bounds__(256) void lora2_kernel(const float* __restrict__ w2,
                                                    const float* __restrict__ theta_base,
                                                    const float* __restrict__ lambda_base,
                                                    const float* __restrict__ eta)
{
    __shared__ float t1s[64][LR];
    __shared__ float w2s[LR][256];
    int tid = threadIdx.x;
    int row0 = blockIdx.y * 64;
    int col0 = blockIdx.x * 256;
    int n = col0 + tid;

    for (int idx = tid; idx < 64*LR; idx += 256) {
        int r = idx / LR, j = idx % LR;
        t1s[r][j] = tanhf(g_t1[(size_t)(row0 + r)*LR + j]);
    }
    for (int idx = tid; idx < LR*256; idx += 256) {
        int j = idx >> 8, cc = idx & 255;
        w2s[j][cc] = w2[(size_t)j*(NH*NK) + col0 + cc];
    }
    __syncthreads();

    float tb = theta_base[n];
    float lb = lambda_base[n];
    float et = eta[n];
    int hh = n >> 5;

    for (int r = 0; r < 64; r++) {
        float acc = 0.f;
        #pragma unroll
        for (int j = 0; j < LR; j++) acc += t1s[r][j] * w2s[j][tid];
        float th = tb + acc;
        th = fminf(fmaxf(th, -THETA_CLIPF), THETA_CLIPF);
        float lam = lb + et * th * th;
        int bl = row0 + r;
        float dtv = g_dt[bl*NH + hh];
        g_lzr[(size_t)bl*(NH*NK) + n] = -lam * dtv;
        g_lzi[(size_t)bl*(NH*NK) + n] =  th * dtv;
    }
}

// ---------------- per-chunk kernel: cumlog, G, y_intra, P/E, D -------------------
__global__ __launch_bounds__(256) void chunk_kernel(const float* __restrict__ Dvec)
{
    extern __shared__ float sm[];
    float* clr = sm;                 // 64 x 33
    float* cli = sm + 2112;
    float* Bre = sm + 2*2112;
    float* Bim = sm + 3*2112;
    float* Cre = sm + 4*2112;
    float* Cim = sm + 5*2112;
    float* xd  = sm + 6*2112;        // 64 x 65
    float* G   = sm + 6*2112 + 4160; // 64 x 65

    int tid = threadIdx.x;
    int bid = blockIdx.x;
    int h = bid & 31;
    int c = (bid >> 5) & 31;
    int b = bid >> 10;
    int blbase = b * SEQ + c * CH;

    for (int e = tid; e < CH*NK; e += 256) {
        int t = e >> 5, k = e & 31;
        int bl = blbase + t;
        clr[t*33+k] = g_lzr[(size_t)bl*(NH*NK) + h*NK + k];
        cli[t*33+k] = g_lzi[(size_t)bl*(NH*NK) + h*NK + k];
        Bre[t*33+k] = g_Br[bl*NK + k];
        Bim[t*33+k] = g_Bi[bl*NK + k];
        Cre[t*33+k] = g_Cr[bl*NK + k];
        Cim[t*33+k] = g_Ci[bl*NK + k];
    }
    for (int e = tid; e < CH*HD; e += 256) {
        int t = e >> 6, p = e & 63;
        int bl = blbase + t;
        xd[t*65+p] = g_xs[(size_t)bl*DIN + h*HD + p] * g_dt[bl*NH + h];
    }
    __syncthreads();

    if (tid < 32) {
        float sr = 0.f, si = 0.f;
        for (int t = 0; t < CH; t++) {
            sr += clr[t*33+tid]; si += cli[t*33+tid];
            clr[t*33+tid] = sr;  cli[t*33+tid] = si;
        }
    }
    __syncthreads();

    for (int e = tid; e < CH*NK; e += 256) {
        int t = e >> 5, k = e & 31;
        float er = __expf(clr[t*33+k]);
        float sn, cs; __sincosf(cli[t*33+k], &sn, &cs);
        float exr = er*cs, exi = er*sn;
        float cr = Cre[t*33+k], ci = Cim[t*33+k];
        size_t base = (size_t)bid*(CH*NK) + t*NK + k;
        g_Pr[base] = cr*exr - ci*exi;
        g_Pi[base] = cr*exi + ci*exr;
        if (t == CH-1) { g_Er[bid*NK + k] = exr; g_Ei[bid*NK + k] = exi; }
    }
    __syncthreads();

    for (int e = tid; e < CH*NK; e += 256) {
        int t = e >> 5, k = e & 31;
        float cr = Cre[t*33+k], ci = Cim[t*33+k];
        float br = Bre[t*33+k], bi = Bim[t*33+k];
        Cre[t*33+k] = cr*br - ci*bi;
        Cim[t*33+k] = cr*bi + ci*br;
    }
    __syncthreads();

    for (int e = tid; e < CH*CH; e += 256) {
        int t = e >> 6, s = e & 63;
        float acc = 0.f;
        if (s <= t) {
            #pragma unroll 4
            for (int k = 0; k < NK; k++) {
                float dr = clr[t*33+k] - clr[s*33+k];
                if (dr > -27.f) {
                    float di = cli[t*33+k] - cli[s*33+k];
                    float er = __expf(dr);
                    float sn, cs; __sincosf(di, &sn, &cs);
                    acc += er * (Cre[t*33+k]*cs - Cim[t*33+k]*sn);
                }
            }
        }
        G[t*65+s] = acc;
    }
    __syncthreads();

    float Dh = Dvec[h];
    for (int e = tid; e < CH*HD; e += 256) {
        int t = e >> 6, p = e & 63;
        float acc = 0.f;
        for (int s = 0; s <= t; s++) acc += G[t*65+s] * xd[s*65+p];
        size_t yi = (size_t)(blbase + t)*DIN + h*HD + p;
        g_y[yi] = acc + Dh * g_xs[yi];
    }

    for (int e = tid; e < CH*NK; e += 256) {
        int s = e >> 5, k = e & 31;
        float dr = clr[(CH-1)*33+k] - clr[s*33+k];
        float di = cli[(CH-1)*33+k] - cli[s*33+k];
        float er = __expf(dr);
        float sn, cs; __sincosf(di, &sn, &cs);
        Cre[s*33+k] = er*cs;
        Cim[s*33+k] = er*sn;
    }
    __syncthreads();

    for (int e = tid; e < HD*NK; e += 256) {
        int p = e >> 5, k = e & 31;
        float ar = 0.f, ai = 0.f;
        #pragma unroll 8
        for (int s = 0; s < CH; s++) {
            float xv = xd[s*65+p];
            ar += xv * Cre[s*33+k];
            ai += xv * Cim[s*33+k];
        }
        float br = Bre[(CH-1)*33+k], bi = Bim[(CH-1)*33+k];
        size_t di_ = (size_t)bid*(HD*NK) + p*NK + k;
        g_Dr[di_] = br*ar - bi*ai;
        g_Di[di_] = br*ai + bi*ar;
    }
}

// ---------------- sequential scan over chunks (per b,h,p,k) ----------------------
__global__ void scan_kernel()
{
    int idx = blockIdx.x * blockDim.x + threadIdx.x;
    int k = idx & 31;
    int p = (idx >> 5) & 63;
    int h = (idx >> 11) & 31;
    int b = idx >> 16;
    float sr = 0.f, si = 0.f;
    for (int c = 0; c < NCH; c++) {
        int bidl = (b*NCH + c)*NH + h;
        size_t di_ = (size_t)bidl*(HD*NK) + p*NK + k;
        g_Sr[di_] = sr; g_Si[di_] = si;
        float er = g_Er[bidl*NK + k], ei = g_Ei[bidl*NK + k];
        float dr = g_Dr[di_], dimg = g_Di[di_];
        float nr = er*sr - ei*si + dr;
        float ni = er*si + ei*sr + dimg;
        sr = nr; si = ni;
    }
}

// ---------------- y += Re( P[t,k] * S_entry[p,k] ) -------------------------------
__global__ __launch_bounds__(256) void yinter_kernel()
{
    __shared__ float Pr[2112], Pi[2112], Sr[2112], Si[2112];
    int tid = threadIdx.x, bid = blockIdx.x;
    int h = bid & 31, c = (bid >> 5) & 31, b = bid >> 10;
    size_t base = (size_t)bid * (CH*NK);
    for (int e = tid; e < CH*NK; e += 256) {
        int t = e >> 5, k = e & 31;
        Pr[t*33+k] = g_Pr[base + e];
        Pi[t*33+k] = g_Pi[base + e];
        Sr[t*33+k] = g_Sr[base + e];
        Si[t*33+k] = g_Si[base + e];
    }
    __syncthreads();
    int blbase = b*SEQ + c*CH;
    for (int e = tid; e < CH*HD; e += 256) {
        int t = e >> 6, p = e & 63;
        float acc = 0.f;
        #pragma unroll 8
        for (int k = 0; k < NK; k++)
            acc += Pr[t*33+k]*Sr[p*33+k] - Pi[t*33+k]*Si[p*33+k];
        size_t yi = (size_t)(blbase + t)*DIN + h*HD + p;
        g_y[yi] += acc;
    }
}

// ---------------- gating + RMSNorm -> split bf16 ---------------------------------
__global__ __launch_bounds__(256) void gatenorm_kernel(const float* __restrict__ norm_w)
{
    __shared__ float red[8];
    int bl = blockIdx.x, tid = threadIdx.x;
    float gv[8];
    float local = 0.f;
    #pragma unroll
    for (int i = 0; i < 8; i++) {
        int j = tid + i*256;
        float z = g_zx[(size_t)bl*DPROJ + j];
        float y = g_y[(size_t)bl*DIN + j];
        float sig = 1.f / (1.f + __expf(-z));
        float g = y * z * sig;
        gv[i] = g;
        local += g * g;
    }
    #pragma unroll
    for (int o = 16; o; o >>= 1) local += __shfl_xor_sync(0xffffffffu, local, o);
    if ((tid & 31) == 0) red[tid >> 5] = local;
    __syncthreads();
    if (tid == 0) {
        float s = 0.f;
        for (int i = 0; i < 8; i++) s += red[i];
        red[0] = rsqrtf(s / (float)DIN + 1e-5f);
    }
    __syncthreads();
    float sc = red[0];
    size_t ro = (size_t)bl * K3_OUT;
    #pragma unroll
    for (int i = 0; i < 8; i++) {
        int j = tid + i*256;
        float g = gv[i] * sc * norm_w[j];
        __nv_bfloat16 h = __float2bfloat16(g);
        __nv_bfloat16 l = __float2bfloat16(g - __bfloat162float(h));
        g_g3[ro + j]          = h;   // seg0 hi
        g_g3[ro + DIN + j]    = l;   // seg1 lo
        g_g3[ro + 2*DIN + j]  = h;   // seg2 hi
    }
}

// ---------------- launch ---------------------------------------------------------
extern "C" void kernel_launch(void* const* d_in, const int* in_sizes, int n_in,
                              void* d_out, int out_size)
{
    (void)in_sizes; (void)n_in; (void)out_size;
    const float* x       = (const float*)d_in[0];
    const float* in_w    = (const float*)d_in[1];
    const float* conv_w  = (const float*)d_in[2];
    const float* conv_b  = (const float*)d_in[3];
    const float* dt_bias = (const float*)d_in[4];
    const float* lam_b   = (const float*)d_in[5];
    const float* th_b    = (const float*)d_in[6];
    const float* w1      = (const float*)d_in[7];
    const float* w2      = (const float*)d_in[8];
    const float* eta     = (const float*)d_in[9];
    const float* Dv      = (const float*)d_in[10];
    const float* nw      = (const float*)d_in[11];
    const float* out_w   = (const float*)d_in[12];
    float* out = (float*)d_out;

    float *zx = nullptr, *t1 = nullptr;
    __nv_bfloat16 *x3, *wi3, *w13, *g3, *wo3;
    cudaGetSymbolAddress((void**)&zx,  g_zx);
    cudaGetSymbolAddress((void**)&t1,  g_t1);
    cudaGetSymbolAddress((void**)&x3,  g_x3);
    cudaGetSymbolAddress((void**)&wi3, g_wi3);
    cudaGetSymbolAddress((void**)&w13, g_w13);
    cudaGetSymbolAddress((void**)&g3,  g_g3);
    cudaGetSymbolAddress((void**)&wo3, g_wo3);

    // 0) splits
    {
        int n4 = BLTOT*DM/4;
        split3_kernel<<<(n4+255)/256, 256>>>(x, x3, n4, DM, 1);
    }
    {
        int n4 = DPROJ*DM/4;
        split3_kernel<<<(n4+255)/256, 256>>>(in_w, wi3, n4, DM, 2);
    }
    splitW1_kernel<<<(DM*LR+255)/256, 256>>>(w1);
    {
        int n4 = DM*DIN/4;
        split3_kernel<<<(n4+255)/256, 256>>>(out_w, wo3, n4, DIN, 2);
    }

    // 1) in_proj: [4096,3072] x [4352,3072]^T -> [4096,4256]
    gemm_bf16<<<dim3(34, BLTOT/128), 256>>>(x3, wi3, zx, BLTOT, DPROJ, K3_IN);
    // 2) dt
    dt_kernel<<<(BLTOT*NH + 255)/256, 256>>>(dt_bias);
    // 3) conv + silu + split
    conv_kernel<<<dim3((CONVD + 255)/256, BLTOT), 256>>>(conv_w, conv_b);
    // 4) lora stage 1 as GEMM: [4096,3072] x [128,3072]^T -> [4096,48]
    gemm_bf16<<<dim3(1, BLTOT/128), 256>>>(x3, w13, t1, BLTOT, LR, K3_IN);
    // 5) lora stage 2 (tanh on load) + log_z
    lora2_kernel<<<dim3(4, BLTOT/64), 256>>>(w2, th_b, lam_b, eta);
    // 6) chunk-parallel heavy kernel
    cudaFuncSetAttribute(chunk_kernel, cudaFuncAttributeMaxDynamicSharedMemorySize, 84*1024);
    chunk_kernel<<<BATCHN*NCH*NH, 256, 83968>>>(Dv);
    // 7) inter-chunk state scan
    scan_kernel<<<(BATCHN*NH*HD*NK)/256, 256>>>();
    // 8) y += P * S_entry
    yinter_kernel<<<BATCHN*NCH*NH, 256>>>();
    // 9) gate + rmsnorm -> split bf16
    gatenorm_kernel<<<BLTOT, 256>>>(nw);
    // 10) out_proj: [4096,6144] x [1024,6144]^T -> [4096,1024]
    gemm_bf16<<<dim3(DM/128, BLTOT/128), 256>>>(g3, wo3, out, BLTOT, DM, K3_OUT);
}

// round 7
// speedup vs baseline: 1.0573x; 1.0573x over previous
#include <cuda_runtime.h>
#include <cuda_bf16.h>
#include <math.h>

#define BATCHN 2
#define SEQ    2048
#define BLTOT  4096
#define DM     1024
#define DIN    2048
#define NH     32
#define HD     64
#define NK     32
#define CONVD  2176
#define DPROJ  4256
#define NCH    32
#define CH     64
#define LR     48
#define XBC_OFF 2048
#define DT_OFF  4224
#define THETA_CLIPF 1.5707963267948966f

#define K3_IN  (3*DM)     // 3072
#define K3_OUT (3*DIN)    // 6144
#define NPAD_W 4352       // 34*128

// ---------------- scratch (static device globals; no allocation) ----------------
__device__ __align__(256) float g_zx [BLTOT*DPROJ];
__device__ __align__(256) float g_dt [BLTOT*NH];
__device__ __align__(256) float g_xs [BLTOT*DIN];
__device__ __align__(256) float g_Br [BLTOT*NK];
__device__ __align__(256) float g_Bi [BLTOT*NK];
__device__ __align__(256) float g_Cr [BLTOT*NK];
__device__ __align__(256) float g_Ci [BLTOT*NK];
__device__ __align__(256) float g_t1 [BLTOT*LR];
__device__ __align__(256) float g_lzr[BLTOT*NH*NK];
__device__ __align__(256) float g_lzi[BLTOT*NH*NK];
__device__ __align__(256) float g_Pr [BATCHN*NCH*NH*CH*NK];
__device__ __align__(256) float g_Pi [BATCHN*NCH*NH*CH*NK];
__device__ __align__(256) float g_Er [BATCHN*NCH*NH*NK];
__device__ __align__(256) float g_Ei [BATCHN*NCH*NH*NK];
__device__ __align__(256) float g_Dr [BATCHN*NCH*NH*HD*NK];
__device__ __align__(256) float g_Di [BATCHN*NCH*NH*HD*NK];
__device__ __align__(256) float g_Sr [BATCHN*NCH*NH*HD*NK];
__device__ __align__(256) float g_Si [BATCHN*NCH*NH*HD*NK];
__device__ __align__(256) float g_y  [BLTOT*DIN];

// bf16 3-segment split buffers (zero-initialized device globals => pad rows are 0)
__device__ __align__(256) __nv_bfloat16 g_x3 [BLTOT*K3_IN];     // x split  [hi,lo,hi]
__device__ __align__(256) __nv_bfloat16 g_wi3[NPAD_W*K3_IN];    // in_w     [hi,hi,lo]
__device__ __align__(256) __nv_bfloat16 g_w13[128*K3_IN];       // w1^T     [hi,hi,lo]
__device__ __align__(256) __nv_bfloat16 g_g3 [BLTOT*K3_OUT];    // gated    [hi,lo,hi]
__device__ __align__(256) __nv_bfloat16 g_wo3[DM*K3_OUT];       // out_w    [hi,hi,lo]

// ================= asm helpers ==================================================
#define LDSM4(R0,R1,R2,R3,ADDR) \
    asm volatile("ldmatrix.sync.aligned.m8n8.x4.shared.b16 {%0,%1,%2,%3}, [%4];" \
                 : "=r"(R0),"=r"(R1),"=r"(R2),"=r"(R3) : "r"(ADDR))

#define CP_ASYNC16(DST,SRC) \
    asm volatile("cp.async.cg.shared.global [%0], [%1], 16;" :: "r"(DST), "l"(SRC))
#define CP_COMMIT asm volatile("cp.async.commit_group;")
#define CP_WAIT2  asm volatile("cp.async.wait_group 2;")

__device__ __forceinline__ unsigned smem_u32(const void* p)
{
    return (unsigned)__cvta_generic_to_shared(p);
}

__device__ __forceinline__ void mma_bf16(float* d, const unsigned* a,
                                         unsigned b0, unsigned b1)
{
    asm volatile("mma.sync.aligned.m16n8k16.row.col.f32.bf16.bf16.f32 "
                 "{%0,%1,%2,%3}, {%4,%5,%6,%7}, {%8,%9}, {%0,%1,%2,%3};"
                 : "+f"(d[0]), "+f"(d[1]), "+f"(d[2]), "+f"(d[3])
                 : "r"(a[0]), "r"(a[1]), "r"(a[2]), "r"(a[3]), "r"(b0), "r"(b1));
}

// ================= bf16 GEMM: C[M,N] = A[M,K3] * B[N,K3]^T ======================
// 128x128 tile, BK=32, 4-stage cp.async ring, ONE syncthreads per K-tile.
#define GSTR 40
#define NSTG 4
#define STG_ELE (128*GSTR)                 // per matrix per stage (bf16)
#define GEMM_SMEM (NSTG * 2 * STG_ELE * 2) // 81920 bytes

__global__ __launch_bounds__(256, 2) void gemm_bf16(const __nv_bfloat16* __restrict__ A,
                                                    const __nv_bfloat16* __restrict__ B,
                                                    float* __restrict__ C,
                                                    int M, int N, int K3)
{
    extern __shared__ __align__(16) __nv_bfloat16 smg[];
    __nv_bfloat16* sA = smg;                    // [NSTG][128*GSTR]
    __nv_bfloat16* sB = smg + NSTG*STG_ELE;

    int tid = threadIdx.x, lane = tid & 31, wid = tid >> 5;
    int wm = wid & 3;          // m offset = 32*wm
    int wn = wid >> 2;         // n offset = 64*wn
    int row0 = blockIdx.y * 128, col0 = blockIdx.x * 128;

    float acc[2][8][4];
    #pragma unroll
    for (int a = 0; a < 2; a++)
        #pragma unroll
        for (int b = 0; b < 8; b++)
            #pragma unroll
            for (int c = 0; c < 4; c++) acc[a][b][c] = 0.f;

    int NT = K3 >> 5;

    // prologue: stages 0..NSTG-2, one commit group each
    #pragma unroll
    for (int s = 0; s < NSTG-1; s++) {
        int k0 = s << 5;
        #pragma unroll
        for (int i = 0; i < 2; i++) {
            int f = tid + i*256, r = f >> 2, kc = (f & 3) << 3;
            CP_ASYNC16(smem_u32(&sA[s*STG_ELE + r*GSTR + kc]), A + (size_t)(row0+r)*K3 + k0 + kc);
            CP_ASYNC16(smem_u32(&sB[s*STG_ELE + r*GSTR + kc]), B + (size_t)(col0+r)*K3 + k0 + kc);
        }
        CP_COMMIT;
    }

    for (int kt = 0; kt < NT; kt++) {
        CP_WAIT2;            // exactly stages kt+1..kt+3 outstanding -> stage kt done
        __syncthreads();     // data visible to all; no warp >1 iter ahead

        // prefetch stage kt+NSTG-1 (overwrites stage used by tile kt-1 - safe after sync)
        {
            int kf = kt + NSTG - 1;
            if (kf < NT) {
                int s = kf & (NSTG-1), k0 = kf << 5;
                #pragma unroll
                for (int i = 0; i < 2; i++) {
                    int f = tid + i*256, r = f >> 2, kc = (f & 3) << 3;
                    CP_ASYNC16(smem_u32(&sA[s*STG_ELE + r*GSTR + kc]), A + (size_t)(row0+r)*K3 + k0 + kc);
                    CP_ASYNC16(smem_u32(&sB[s*STG_ELE + r*GSTR + kc]), B + (size_t)(col0+r)*K3 + k0 + kc);
                }
            }
            CP_COMMIT;       // empty group when past the end keeps the count exact
        }

        const __nv_bfloat16* a_s = sA + (kt & (NSTG-1))*STG_ELE;
        const __nv_bfloat16* b_s = sB + (kt & (NSTG-1))*STG_ELE;

        #pragma unroll
        for (int kh = 0; kh < 32; kh += 16) {
            unsigned ah[2][4];
            #pragma unroll
            for (int mf = 0; mf < 2; mf++) {
                int r = wm*32 + mf*16 + (lane & 15);
                int cc = kh + ((lane >> 4) << 3);
                LDSM4(ah[mf][0], ah[mf][1], ah[mf][2], ah[mf][3],
                      smem_u32(&a_s[r*GSTR + cc]));
            }
            #pragma unroll
            for (int np = 0; np < 4; np++) {
                int nr  = wn*64 + np*16 + (lane & 7) + ((lane >> 4) << 3);
                int kof = kh + (((lane >> 3) & 1) << 3);
                unsigned bh[4];
                LDSM4(bh[0], bh[1], bh[2], bh[3], smem_u32(&b_s[nr*GSTR + kof]));
                #pragma unroll
                for (int mf = 0; mf < 2; mf++) {
                    mma_bf16(acc[mf][np*2+0], ah[mf], bh[0], bh[1]);
                    mma_bf16(acc[mf][np*2+1], ah[mf], bh[2], bh[3]);
                }
            }
        }
    }

    #pragma unroll
    for (int mf = 0; mf < 2; mf++) {
        int r = row0 + wm*32 + mf*16 + (lane >> 2);
        #pragma unroll
        for (int nf = 0; nf < 8; nf++) {
            int c = col0 + wn*64 + nf*8 + ((lane & 3) << 1);
            if (c + 1 < N) {
                *(float2*)&C[(size_t)r*N + c]     = make_float2(acc[mf][nf][0], acc[mf][nf][1]);
                *(float2*)&C[(size_t)(r+8)*N + c] = make_float2(acc[mf][nf][2], acc[mf][nf][3]);
            } else if (c < N) {
                C[(size_t)r*N + c]     = acc[mf][nf][0];
                C[(size_t)(r+8)*N + c] = acc[mf][nf][2];
            }
        }
    }
}

// ---------------- split fp32 -> 3-segment bf16 ----------------------------------
__global__ void split3_kernel(const float* __restrict__ src,
                              __nv_bfloat16* __restrict__ dst,
                              int n4, int K, int loSeg)
{
    int i = blockIdx.x * blockDim.x + threadIdx.x;
    if (i >= n4) return;
    int base = i * 4;
    int r = base / K, k = base - r * K;
    float4 v = *(const float4*)(src + base);
    float xs[4] = {v.x, v.y, v.z, v.w};
    __nv_bfloat16 h[4], l[4];
    #pragma unroll
    for (int j = 0; j < 4; j++) {
        h[j] = __float2bfloat16(xs[j]);
        l[j] = __float2bfloat16(xs[j] - __bfloat162float(h[j]));
    }
    size_t ro = (size_t)r * 3 * K + k;
    __nv_bfloat162 hp0, hp1, lp0, lp1;
    hp0.x = h[0]; hp0.y = h[1]; hp1.x = h[2]; hp1.y = h[3];
    lp0.x = l[0]; lp0.y = l[1]; lp1.x = l[2]; lp1.y = l[3];
    int hiSeg = (loSeg == 1) ? 2 : 1;
    ((__nv_bfloat162*)(dst + ro))[0] = hp0;
    ((__nv_bfloat162*)(dst + ro))[1] = hp1;
    ((__nv_bfloat162*)(dst + ro + (size_t)hiSeg*K))[0] = hp0;
    ((__nv_bfloat162*)(dst + ro + (size_t)hiSeg*K))[1] = hp1;
    ((__nv_bfloat162*)(dst + ro + (size_t)loSeg*K))[0] = lp0;
    ((__nv_bfloat162*)(dst + ro + (size_t)loSeg*K))[1] = lp1;
}

// ---------------- w1 (DM x LR) -> transposed 3-seg [128][3*DM] ------------------
__global__ void splitW1_kernel(const float* __restrict__ w1)
{
    int idx = blockIdx.x * blockDim.x + threadIdx.x;
    if (idx >= DM * LR) return;
    int k = idx / LR, n = idx % LR;
    float v = w1[idx];
    __nv_bfloat16 h = __float2bfloat16(v);
    __nv_bfloat16 l = __float2bfloat16(v - __bfloat162float(h));
    size_t ro = (size_t)n * K3_IN + k;
    g_w13[ro]        = h;
    g_w13[ro + DM]   = h;
    g_w13[ro + 2*DM] = l;
}

// ---------------- dt = softplus(zx[:, DT_OFF+h] + dt_bias[h]) --------------------
__global__ void dt_kernel(const float* __restrict__ dt_bias)
{
    int idx = blockIdx.x * blockDim.x + threadIdx.x;
    if (idx >= BLTOT * NH) return;
    int bl = idx >> 5, hh = idx & 31;
    float v = g_zx[(size_t)bl * DPROJ + DT_OFF + hh] + dt_bias[hh];
    float sp = (v > 20.f) ? v : log1pf(expf(v));
    g_dt[idx] = sp;
}

// ---------------- depthwise causal conv (width 4) + silu + split -----------------
__global__ void conv_kernel(const float* __restrict__ conv_w,
                            const float* __restrict__ conv_b)
{
    int c = blockIdx.x * blockDim.x + threadIdx.x;
    if (c >= CONVD) return;
    int bl = blockIdx.y;
    int l = bl & (SEQ - 1);
    float acc = conv_b[c];
    #pragma unroll
    for (int kk = 0; kk < 4; kk++) {
        int lt = l + kk - 3;
        if (lt >= 0)
            acc += g_zx[(size_t)(bl + kk - 3) * DPROJ + XBC_OFF + c] * conv_w[c*4 + kk];
    }
    float a = acc / (1.f + __expf(-acc));
    if (c < DIN) {
        g_xs[(size_t)bl * DIN + c] = a;
    } else {
        int c2 = c - DIN;
        if (c2 < 64) {
            int k = c2 >> 1;
            if (c2 & 1) g_Bi[bl*NK + k] = a; else g_Br[bl*NK + k] = a;
        } else {
            int c3 = c2 - 64;
            int k = c3 >> 1;
            if (c3 & 1) g_Ci[bl*NK + k] = a; else g_Cr[bl*NK + k] = a;
        }
    }
}

// ---------------- lora2 (tanh applied on load) -----------------------------------
__global__ __launch_bounds__(256) void lora2_kernel(const float* __restrict__ w2,
                                                    const float* __restrict__ theta_base,
                                                    const float* __restrict__ lambda_base,
                                                    const float* __restrict__ eta)
{
    __shared__ float t1s[64][LR];
    __shared__ float w2s[LR][256];
    int tid = threadIdx.x;
    int row0 = blockIdx.y * 64;
    int col0 = blockIdx.x * 256;
    int n = col0 + tid;

    for (int idx = tid; idx < 64*LR; idx += 256) {
        int r = idx / LR, j = idx % LR;
        t1s[r][j] = tanhf(g_t1[(size_t)(row0 + r)*LR + j]);
    }
    for (int idx = tid; idx < LR*256; idx += 256) {
        int j = idx >> 8, cc = idx & 255;
        w2s[j][cc] = w2[(size_t)j*(NH*NK) + col0 + cc];
    }
    __syncthreads();

    float tb = theta_base[n];
    float lb = lambda_base[n];
    float et = eta[n];
    int hh = n >> 5;

    for (int r = 0; r < 64; r++) {
        float acc = 0.f;
        #pragma unroll
        for (int j = 0; j < LR; j++) acc += t1s[r][j] * w2s[j][tid];
        float th = tb + acc;
        th = fminf(fmaxf(th, -THETA_CLIPF), THETA_CLIPF);
        float lam = lb + et * th * th;
        int bl = row0 + r;
        float dtv = g_dt[bl*NH + hh];
        g_lzr[(size_t)bl*(NH*NK) + n] = -lam * dtv;
        g_lzi[(size_t)bl*(NH*NK) + n] =  th * dtv;
    }
}

// ---------------- per-chunk kernel: cumlog, G, y_intra, P/E, D -------------------
__global__ __launch_bounds__(256) void chunk_kernel(const float* __restrict__ Dvec)
{
    extern __shared__ float sm[];
    float* clr = sm;                 // 64 x 33
    float* cli = sm + 2112;
    float* Bre = sm + 2*2112;
    float* Bim = sm + 3*2112;
    float* Cre = sm + 4*2112;
    float* Cim = sm + 5*2112;
    float* xd  = sm + 6*2112;        // 64 x 65
    float* G   = sm + 6*2112 + 4160; // 64 x 65

    int tid = threadIdx.x;
    int bid = blockIdx.x;
    int h = bid & 31;
    int c = (bid >> 5) & 31;
    int b = bid >> 10;
    int blbase = b * SEQ + c * CH;

    for (int e = tid; e < CH*NK; e += 256) {
        int t = e >> 5, k = e & 31;
        int bl = blbase + t;
        clr[t*33+k] = g_lzr[(size_t)bl*(NH*NK) + h*NK + k];
        cli[t*33+k] = g_lzi[(size_t)bl*(NH*NK) + h*NK + k];
        Bre[t*33+k] = g_Br[bl*NK + k];
        Bim[t*33+k] = g_Bi[bl*NK + k];
        Cre[t*33+k] = g_Cr[bl*NK + k];
        Cim[t*33+k] = g_Ci[bl*NK + k];
    }
    for (int e = tid; e < CH*HD; e += 256) {
        int t = e >> 6, p = e & 63;
        int bl = blbase + t;
        xd[t*65+p] = g_xs[(size_t)bl*DIN + h*HD + p] * g_dt[bl*NH + h];
    }
    __syncthreads();

    if (tid < 32) {
        float sr = 0.f, si = 0.f;
        for (int t = 0; t < CH; t++) {
            sr += clr[t*33+tid]; si += cli[t*33+tid];
            clr[t*33+tid] = sr;  cli[t*33+tid] = si;
        }
    }
    __syncthreads();

    for (int e = tid; e < CH*NK; e += 256) {
        int t = e >> 5, k = e & 31;
        float er = __expf(clr[t*33+k]);
        float sn, cs; __sincosf(cli[t*33+k], &sn, &cs);
        float exr = er*cs, exi = er*sn;
        float cr = Cre[t*33+k], ci = Cim[t*33+k];
        size_t base = (size_t)bid*(CH*NK) + t*NK + k;
        g_Pr[base] = cr*exr - ci*exi;
        g_Pi[base] = cr*exi + ci*exr;
        if (t == CH-1) { g_Er[bid*NK + k] = exr; g_Ei[bid*NK + k] = exi; }
    }
    __syncthreads();

    for (int e = tid; e < CH*NK; e += 256) {
        int t = e >> 5, k = e & 31;
        float cr = Cre[t*33+k], ci = Cim[t*33+k];
        float br = Bre[t*33+k], bi = Bim[t*33+k];
        Cre[t*33+k] = cr*br - ci*bi;
        Cim[t*33+k] = cr*bi + ci*br;
    }
    __syncthreads();

    for (int e = tid; e < CH*CH; e += 256) {
        int t = e >> 6, s = e & 63;
        float acc = 0.f;
        if (s <= t) {
            #pragma unroll 4
            for (int k = 0; k < NK; k++) {
                float dr = clr[t*33+k] - clr[s*33+k];
                if (dr > -27.f) {
                    float di = cli[t*33+k] - cli[s*33+k];
                    float er = __expf(dr);
                    float sn, cs; __sincosf(di, &sn, &cs);
                    acc += er * (Cre[t*33+k]*cs - Cim[t*33+k]*sn);
                }
            }
        }
        G[t*65+s] = acc;
    }
    __syncthreads();

    float Dh = Dvec[h];
    for (int e = tid; e < CH*HD; e += 256) {
        int t = e >> 6, p = e & 63;
        float acc = 0.f;
        for (int s = 0; s <= t; s++) acc += G[t*65+s] * xd[s*65+p];
        size_t yi = (size_t)(blbase + t)*DIN + h*HD + p;
        g_y[yi] = acc + Dh * g_xs[yi];
    }

    for (int e = tid; e < CH*NK; e += 256) {
        int s = e >> 5, k = e & 31;
        float dr = clr[(CH-1)*33+k] - clr[s*33+k];
        float di = cli[(CH-1)*33+k] - cli[s*33+k];
        float er = __expf(dr);
        float sn, cs; __sincosf(di, &sn, &cs);
        Cre[s*33+k] = er*cs;
        Cim[s*33+k] = er*sn;
    }
    __syncthreads();

    for (int e = tid; e < HD*NK; e += 256) {
        int p = e >> 5, k = e & 31;
        float ar = 0.f, ai = 0.f;
        #pragma unroll 8
        for (int s = 0; s < CH; s++) {
            float xv = xd[s*65+p];
            ar += xv * Cre[s*33+k];
            ai += xv * Cim[s*33+k];
        }
        float br = Bre[(CH-1)*33+k], bi = Bim[(CH-1)*33+k];
        size_t di_ = (size_t)bid*(HD*NK) + p*NK + k;
        g_Dr[di_] = br*ar - bi*ai;
        g_Di[di_] = br*ai + bi*ar;
    }
}

// ---------------- sequential scan over chunks (per b,h,p,k) ----------------------
__global__ void scan_kernel()
{
    int idx = blockIdx.x * blockDim.x + threadIdx.x;
    int k = idx & 31;
    int p = (idx >> 5) & 63;
    int h = (idx >> 11) & 31;
    int b = idx >> 16;
    float sr = 0.f, si = 0.f;
    for (int c = 0; c < NCH; c++) {
        int bidl = (b*NCH + c)*NH + h;
        size_t di_ = (size_t)bidl*(HD*NK) + p*NK + k;
        g_Sr[di_] = sr; g_Si[di_] = si;
        float er = g_Er[bidl*NK + k], ei = g_Ei[bidl*NK + k];
        float dr = g_Dr[di_], dimg = g_Di[di_];
        float nr = er*sr - ei*si + dr;
        float ni = er*si + ei*sr + dimg;
        sr = nr; si = ni;
    }
}

// ---------------- y += Re( P[t,k] * S_entry[p,k] ) -------------------------------
__global__ __launch_bounds__(256) void yinter_kernel()
{
    __shared__ float Pr[2112], Pi[2112], Sr[2112], Si[2112];
    int tid = threadIdx.x, bid = blockIdx.x;
    int h = bid & 31, c = (bid >> 5) & 31, b = bid >> 10;
    size_t base = (size_t)bid * (CH*NK);
    for (int e = tid; e < CH*NK; e += 256) {
        int t = e >> 5, k = e & 31;
        Pr[t*33+k] = g_Pr[base + e];
        Pi[t*33+k] = g_Pi[base + e];
        Sr[t*33+k] = g_Sr[base + e];
        Si[t*33+k] = g_Si[base + e];
    }
    __syncthreads();
    int blbase = b*SEQ + c*CH;
    for (int e = tid; e < CH*HD; e += 256) {
        int t = e >> 6, p = e & 63;
        float acc = 0.f;
        #pragma unroll 8
        for (int k = 0; k < NK; k++)
            acc += Pr[t*33+k]*Sr[p*33+k] - Pi[t*33+k]*Si[p*33+k];
        size_t yi = (size_t)(blbase + t)*DIN + h*HD + p;
        g_y[yi] += acc;
    }
}

// ---------------- gating + RMSNorm -> split bf16 ---------------------------------
__global__ __launch_bounds__(256) void gatenorm_kernel(const float* __restrict__ norm_w)
{
    __shared__ float red[8];
    int bl = blockIdx.x, tid = threadIdx.x;
    float gv[8];
    float local = 0.f;
    #pragma unroll
    for (int i = 0; i < 8; i++) {
        int j = tid + i*256;
        float z = g_zx[(size_t)bl*DPROJ + j];
        float y = g_y[(size_t)bl*DIN + j];
        float sig = 1.f / (1.f + __expf(-z));
        float g = y * z * sig;
        gv[i] = g;
        local += g * g;
    }
    #pragma unroll
    for (int o = 16; o; o >>= 1) local += __shfl_xor_sync(0xffffffffu, local, o);
    if ((tid & 31) == 0) red[tid >> 5] = local;
    __syncthreads();
    if (tid == 0) {
        float s = 0.f;
        for (int i = 0; i < 8; i++) s += red[i];
        red[0] = rsqrtf(s / (float)DIN + 1e-5f);
    }
    __syncthreads();
    float sc = red[0];
    size_t ro = (size_t)bl * K3_OUT;
    #pragma unroll
    for (int i = 0; i < 8; i++) {
        int j = tid + i*256;
        float g = gv[i] * sc * norm_w[j];
        __nv_bfloat16 h = __float2bfloat16(g);
        __nv_bfloat16 l = __float2bfloat16(g - __bfloat162float(h));
        g_g3[ro + j]          = h;   // seg0 hi
        g_g3[ro + DIN + j]    = l;   // seg1 lo
        g_g3[ro + 2*DIN + j]  = h;   // seg2 hi
    }
}

// ---------------- launch ---------------------------------------------------------
extern "C" void kernel_launch(void* const* d_in, const int* in_sizes, int n_in,
                              void* d_out, int out_size)
{
    (void)in_sizes; (void)n_in; (void)out_size;
    const float* x       = (const float*)d_in[0];
    const float* in_w    = (const float*)d_in[1];
    const float* conv_w  = (const float*)d_in[2];
    const float* conv_b  = (const float*)d_in[3];
    const float* dt_bias = (const float*)d_in[4];
    const float* lam_b   = (const float*)d_in[5];
    const float* th_b    = (const float*)d_in[6];
    const float* w1      = (const float*)d_in[7];
    const float* w2      = (const float*)d_in[8];
    const float* eta     = (const float*)d_in[9];
    const float* Dv      = (const float*)d_in[10];
    const float* nw      = (const float*)d_in[11];
    const float* out_w   = (const float*)d_in[12];
    float* out = (float*)d_out;

    float *zx = nullptr, *t1 = nullptr;
    __nv_bfloat16 *x3, *wi3, *w13, *g3, *wo3;
    cudaGetSymbolAddress((void**)&zx,  g_zx);
    cudaGetSymbolAddress((void**)&t1,  g_t1);
    cudaGetSymbolAddress((void**)&x3,  g_x3);
    cudaGetSymbolAddress((void**)&wi3, g_wi3);
    cudaGetSymbolAddress((void**)&w13, g_w13);
    cudaGetSymbolAddress((void**)&g3,  g_g3);
    cudaGetSymbolAddress((void**)&wo3, g_wo3);

    cudaFuncSetAttribute(gemm_bf16, cudaFuncAttributeMaxDynamicSharedMemorySize, GEMM_SMEM);

    // 0) splits
    {
        int n4 = BLTOT*DM/4;
        split3_kernel<<<(n4+255)/256, 256>>>(x, x3, n4, DM, 1);
    }
    {
        int n4 = DPROJ*DM/4;
        split3_kernel<<<(n4+255)/256, 256>>>(in_w, wi3, n4, DM, 2);
    }
    splitW1_kernel<<<(DM*LR+255)/256, 256>>>(w1);
    {
        int n4 = DM*DIN/4;
        split3_kernel<<<(n4+255)/256, 256>>>(out_w, wo3, n4, DIN, 2);
    }

    // 1) in_proj: [4096,3072] x [4352,3072]^T -> [4096,4256]
    gemm_bf16<<<dim3(34, BLTOT/128), 256, GEMM_SMEM>>>(x3, wi3, zx, BLTOT, DPROJ, K3_IN);
    // 2) dt
    dt_kernel<<<(BLTOT*NH + 255)/256, 256>>>(dt_bias);
    // 3) conv + silu + split
    conv_kernel<<<dim3((CONVD + 255)/256, BLTOT), 256>>>(conv_w, conv_b);
    // 4) lora stage 1 as GEMM: [4096,3072] x [128,3072]^T -> [4096,48]
    gemm_bf16<<<dim3(1, BLTOT/128), 256, GEMM_SMEM>>>(x3, w13, t1, BLTOT, LR, K3_IN);
    // 5) lora stage 2 (tanh on load) + log_z
    lora2_kernel<<<dim3(4, BLTOT/64), 256>>>(w2, th_b, lam_b, eta);
    // 6) chunk-parallel heavy kernel
    cudaFuncSetAttribute(chunk_kernel, cudaFuncAttributeMaxDynamicSharedMemorySize, 84*1024);
    chunk_kernel<<<BATCHN*NCH*NH, 256, 83968>>>(Dv);
    // 7) inter-chunk state scan
    scan_kernel<<<(BATCHN*NH*HD*NK)/256, 256>>>();
    // 8) y += P * S_entry
    yinter_kernel<<<BATCHN*NCH*NH, 256>>>();
    // 9) gate + rmsnorm -> split bf16
    gatenorm_kernel<<<BLTOT, 256>>>(nw);
    // 10) out_proj: [4096,6144] x [1024,6144]^T -> [4096,1024]
    gemm_bf16<<<dim3(DM/128, BLTOT/128), 256, GEMM_SMEM>>>(g3, wo3, out, BLTOT, DM, K3_OUT);
}

// round 8
// speedup vs baseline: 1.2496x; 1.1819x over previous
#include <cuda_runtime.h>
#include <cuda_fp16.h>
#include <math.h>

#define BATCHN 2
#define SEQ    2048
#define BLTOT  4096
#define DM     1024
#define DIN    2048
#define NH     32
#define HD     64
#define NK     32
#define CONVD  2176
#define DPROJ  4256
#define NCH    32
#define CH     64
#define LR     48
#define XBC_OFF 2048
#define DT_OFF  4224
#define THETA_CLIPF 1.5707963267948966f

#define K2_IN  (2*DM)     // 2048
#define K2_OUT (2*DIN)    // 4096
#define NPAD_W 4352       // 34*128

// ---------------- scratch (static device globals; no allocation) ----------------
__device__ __align__(256) float g_zx [BLTOT*DPROJ];
__device__ __align__(256) float g_dt [BLTOT*NH];
__device__ __align__(256) float g_xs [BLTOT*DIN];
__device__ __align__(256) float g_Br [BLTOT*NK];
__device__ __align__(256) float g_Bi [BLTOT*NK];
__device__ __align__(256) float g_Cr [BLTOT*NK];
__device__ __align__(256) float g_Ci [BLTOT*NK];
__device__ __align__(256) float g_t1 [BLTOT*LR];
__device__ __align__(256) float g_lzr[BLTOT*NH*NK];
__device__ __align__(256) float g_lzi[BLTOT*NH*NK];
__device__ __align__(256) float g_Pr [BATCHN*NCH*NH*CH*NK];
__device__ __align__(256) float g_Pi [BATCHN*NCH*NH*CH*NK];
__device__ __align__(256) float g_Er [BATCHN*NCH*NH*NK];
__device__ __align__(256) float g_Ei [BATCHN*NCH*NH*NK];
__device__ __align__(256) float g_Dr [BATCHN*NCH*NH*HD*NK];
__device__ __align__(256) float g_Di [BATCHN*NCH*NH*HD*NK];
__device__ __align__(256) float g_Sr [BATCHN*NCH*NH*HD*NK];
__device__ __align__(256) float g_Si [BATCHN*NCH*NH*HD*NK];
__device__ __align__(256) float g_y  [BLTOT*DIN];

// fp16 2-segment split buffers (zero-initialized => pad rows are 0)
__device__ __align__(256) __half g_x2 [BLTOT*K2_IN];     // x       [hi,lo]
__device__ __align__(256) __half g_wi2[NPAD_W*K2_IN];    // in_w    [hi,hi]
__device__ __align__(256) __half g_w12[128*K2_IN];       // w1^T    [hi,hi]
__device__ __align__(256) __half g_g2 [BLTOT*K2_OUT];    // gated   [hi,lo]
__device__ __align__(256) __half g_wo2[DM*K2_OUT];       // out_w   [hi,hi]

// ================= asm helpers ==================================================
#define LDSM4(R0,R1,R2,R3,ADDR) \
    asm volatile("ldmatrix.sync.aligned.m8n8.x4.shared.b16 {%0,%1,%2,%3}, [%4];" \
                 : "=r"(R0),"=r"(R1),"=r"(R2),"=r"(R3) : "r"(ADDR))

#define CP_ASYNC16(DST,SRC) \
    asm volatile("cp.async.cg.shared.global [%0], [%1], 16;" :: "r"(DST), "l"(SRC))
#define CP_COMMIT asm volatile("cp.async.commit_group;")
#define CP_WAIT1  asm volatile("cp.async.wait_group 1;")

__device__ __forceinline__ unsigned smem_u32(const void* p)
{
    return (unsigned)__cvta_generic_to_shared(p);
}

__device__ __forceinline__ void mma_f16(float* d, const unsigned* a,
                                        unsigned b0, unsigned b1)
{
    asm volatile("mma.sync.aligned.m16n8k16.row.col.f32.f16.f16.f32 "
                 "{%0,%1,%2,%3}, {%4,%5,%6,%7}, {%8,%9}, {%0,%1,%2,%3};"
                 : "+f"(d[0]), "+f"(d[1]), "+f"(d[2]), "+f"(d[3])
                 : "r"(a[0]), "r"(a[1]), "r"(a[2]), "r"(a[3]), "r"(b0), "r"(b1));
}

// ================= fp16 GEMM: C[M,N] = A[M,K2] * B[N,K2]^T ======================
// 128x128 tile, BK=64, 3-stage cp.async ring, one syncthreads per K-tile.
#define GSTR 72
#define NSTG 3
#define STG_ELE (128*GSTR)                  // per matrix per stage (halves)
#define GEMM_SMEM (NSTG * 2 * STG_ELE * 2)  // 110592 bytes

__global__ __launch_bounds__(256) void gemm_half(const __half* __restrict__ A,
                                                 const __half* __restrict__ B,
                                                 float* __restrict__ C,
                                                 int M, int N, int K2)
{
    extern __shared__ __align__(16) __half smg[];
    __half* sA = smg;                    // [NSTG][128*GSTR]
    __half* sB = smg + NSTG*STG_ELE;

    int tid = threadIdx.x, lane = tid & 31, wid = tid >> 5;
    int wm = wid & 3;          // m offset = 32*wm
    int wn = wid >> 2;         // n offset = 64*wn
    int row0 = blockIdx.y * 128, col0 = blockIdx.x * 128;

    float acc[2][8][4];
    #pragma unroll
    for (int a = 0; a < 2; a++)
        #pragma unroll
        for (int b = 0; b < 8; b++)
            #pragma unroll
            for (int c = 0; c < 4; c++) acc[a][b][c] = 0.f;

    int NT = K2 >> 6;

    // prologue: stages 0,1
    #pragma unroll
    for (int s = 0; s < NSTG-1; s++) {
        int k0 = s << 6;
        #pragma unroll
        for (int i = 0; i < 4; i++) {
            int f = tid + i*256, r = f >> 3, kc = (f & 7) << 3;   // 8 halves = 16B
            CP_ASYNC16(smem_u32(&sA[s*STG_ELE + r*GSTR + kc]), A + (size_t)(row0+r)*K2 + k0 + kc);
            CP_ASYNC16(smem_u32(&sB[s*STG_ELE + r*GSTR + kc]), B + (size_t)(col0+r)*K2 + k0 + kc);
        }
        CP_COMMIT;
    }

    for (int kt = 0; kt < NT; kt++) {
        CP_WAIT1;            // stage kt complete (only kt+1 may remain in flight)
        __syncthreads();

        // prefetch stage kt+2 into ring slot (safe: that slot was consumed at kt-1)
        {
            int kf = kt + NSTG - 1;
            if (kf < NT) {
                int s = kf % NSTG, k0 = kf << 6;
                #pragma unroll
                for (int i = 0; i < 4; i++) {
                    int f = tid + i*256, r = f >> 3, kc = (f & 7) << 3;
                    CP_ASYNC16(smem_u32(&sA[s*STG_ELE + r*GSTR + kc]), A + (size_t)(row0+r)*K2 + k0 + kc);
                    CP_ASYNC16(smem_u32(&sB[s*STG_ELE + r*GSTR + kc]), B + (size_t)(col0+r)*K2 + k0 + kc);
                }
            }
            CP_COMMIT;       // empty group keeps wait count exact past the end
        }

        const __half* a_s = sA + (kt % NSTG)*STG_ELE;
        const __half* b_s = sB + (kt % NSTG)*STG_ELE;

        #pragma unroll
        for (int kh = 0; kh < 64; kh += 16) {
            unsigned ah[2][4];
            #pragma unroll
            for (int mf = 0; mf < 2; mf++) {
                int r = wm*32 + mf*16 + (lane & 15);
                int cc = kh + ((lane >> 4) << 3);
                LDSM4(ah[mf][0], ah[mf][1], ah[mf][2], ah[mf][3],
                      smem_u32(&a_s[r*GSTR + cc]));
            }
            #pragma unroll
            for (int np = 0; np < 4; np++) {
                int nr  = wn*64 + np*16 + (lane & 7) + ((lane >> 4) << 3);
                int kof = kh + (((lane >> 3) & 1) << 3);
                unsigned bh[4];
                LDSM4(bh[0], bh[1], bh[2], bh[3], smem_u32(&b_s[nr*GSTR + kof]));
                #pragma unroll
                for (int mf = 0; mf < 2; mf++) {
                    mma_f16(acc[mf][np*2+0], ah[mf], bh[0], bh[1]);
                    mma_f16(acc[mf][np*2+1], ah[mf], bh[2], bh[3]);
                }
            }
        }
    }

    #pragma unroll
    for (int mf = 0; mf < 2; mf++) {
        int r = row0 + wm*32 + mf*16 + (lane >> 2);
        #pragma unroll
        for (int nf = 0; nf < 8; nf++) {
            int c = col0 + wn*64 + nf*8 + ((lane & 3) << 1);
            if (c + 1 < N) {
                *(float2*)&C[(size_t)r*N + c]     = make_float2(acc[mf][nf][0], acc[mf][nf][1]);
                *(float2*)&C[(size_t)(r+8)*N + c] = make_float2(acc[mf][nf][2], acc[mf][nf][3]);
            } else if (c < N) {
                C[(size_t)r*N + c]     = acc[mf][nf][0];
                C[(size_t)(r+8)*N + c] = acc[mf][nf][2];
            }
        }
    }
}

// ---------------- split fp32 -> 2-segment fp16 ----------------------------------
// mode 0 (activations): [hi, lo]    mode 1 (weights): [hi, hi]
__global__ void split2_kernel(const float* __restrict__ src,
                              __half* __restrict__ dst,
                              int n4, int K, int wmode)
{
    int i = blockIdx.x * blockDim.x + threadIdx.x;
    if (i >= n4) return;
    int base = i * 4;
    int r = base / K, k = base - r * K;
    float4 v = *(const float4*)(src + base);
    float xs[4] = {v.x, v.y, v.z, v.w};
    __half h[4], l[4];
    #pragma unroll
    for (int j = 0; j < 4; j++) {
        h[j] = __float2half(xs[j]);
        l[j] = wmode ? h[j] : __float2half(xs[j] - __half2float(h[j]));
    }
    size_t ro = (size_t)r * 2 * K + k;
    __half2 hp0, hp1, lp0, lp1;
    hp0.x = h[0]; hp0.y = h[1]; hp1.x = h[2]; hp1.y = h[3];
    lp0.x = l[0]; lp0.y = l[1]; lp1.x = l[2]; lp1.y = l[3];
    ((__half2*)(dst + ro))[0] = hp0;
    ((__half2*)(dst + ro))[1] = hp1;
    ((__half2*)(dst + ro + (size_t)K))[0] = lp0;
    ((__half2*)(dst + ro + (size_t)K))[1] = lp1;
}

// ---------------- w1 (DM x LR) -> transposed 2-seg [128][2*DM] ------------------
__global__ void splitW1_kernel(const float* __restrict__ w1)
{
    int idx = blockIdx.x * blockDim.x + threadIdx.x;
    if (idx >= DM * LR) return;
    int k = idx / LR, n = idx % LR;
    __half h = __float2half(w1[idx]);
    size_t ro = (size_t)n * K2_IN + k;
    g_w12[ro]      = h;
    g_w12[ro + DM] = h;
}

// ---------------- dt = softplus(zx[:, DT_OFF+h] + dt_bias[h]) --------------------
__global__ void dt_kernel(const float* __restrict__ dt_bias)
{
    int idx = blockIdx.x * blockDim.x + threadIdx.x;
    if (idx >= BLTOT * NH) return;
    int bl = idx >> 5, hh = idx & 31;
    float v = g_zx[(size_t)bl * DPROJ + DT_OFF + hh] + dt_bias[hh];
    float sp = (v > 20.f) ? v : log1pf(expf(v));
    g_dt[idx] = sp;
}

// ---------------- depthwise causal conv (width 4) + silu + split -----------------
__global__ void conv_kernel(const float* __restrict__ conv_w,
                            const float* __restrict__ conv_b)
{
    int c = blockIdx.x * blockDim.x + threadIdx.x;
    if (c >= CONVD) return;
    int bl = blockIdx.y;
    int l = bl & (SEQ - 1);
    float acc = conv_b[c];
    #pragma unroll
    for (int kk = 0; kk < 4; kk++) {
        int lt = l + kk - 3;
        if (lt >= 0)
            acc += g_zx[(size_t)(bl + kk - 3) * DPROJ + XBC_OFF + c] * conv_w[c*4 + kk];
    }
    float a = acc / (1.f + __expf(-acc));
    if (c < DIN) {
        g_xs[(size_t)bl * DIN + c] = a;
    } else {
        int c2 = c - DIN;
        if (c2 < 64) {
            int k = c2 >> 1;
            if (c2 & 1) g_Bi[bl*NK + k] = a; else g_Br[bl*NK + k] = a;
        } else {
            int c3 = c2 - 64;
            int k = c3 >> 1;
            if (c3 & 1) g_Ci[bl*NK + k] = a; else g_Cr[bl*NK + k] = a;
        }
    }
}

// ---------------- lora2 (tanh applied on load) -----------------------------------
__global__ __launch_bounds__(256) void lora2_kernel(const float* __restrict__ w2,
                                                    const float* __restrict__ theta_base,
                                                    const float* __restrict__ lambda_base,
                                                    const float* __restrict__ eta)
{
    __shared__ float t1s[64][LR];
    __shared__ float w2s[LR][256];
    int tid = threadIdx.x;
    int row0 = blockIdx.y * 64;
    int col0 = blockIdx.x * 256;
    int n = col0 + tid;

    for (int idx = tid; idx < 64*LR; idx += 256) {
        int r = idx / LR, j = idx % LR;
        t1s[r][j] = tanhf(g_t1[(size_t)(row0 + r)*LR + j]);
    }
    for (int idx = tid; idx < LR*256; idx += 256) {
        int j = idx >> 8, cc = idx & 255;
        w2s[j][cc] = w2[(size_t)j*(NH*NK) + col0 + cc];
    }
    __syncthreads();

    float tb = theta_base[n];
    float lb = lambda_base[n];
    float et = eta[n];
    int hh = n >> 5;

    for (int r = 0; r < 64; r++) {
        float acc = 0.f;
        #pragma unroll
        for (int j = 0; j < LR; j++) acc += t1s[r][j] * w2s[j][tid];
        float th = tb + acc;
        th = fminf(fmaxf(th, -THETA_CLIPF), THETA_CLIPF);
        float lam = lb + et * th * th;
        int bl = row0 + r;
        float dtv = g_dt[bl*NH + hh];
        g_lzr[(size_t)bl*(NH*NK) + n] = -lam * dtv;
        g_lzi[(size_t)bl*(NH*NK) + n] =  th * dtv;
    }
}

// ---------------- per-chunk kernel: cumlog, G, y_intra, P/E, D -------------------
__global__ __launch_bounds__(256) void chunk_kernel(const float* __restrict__ Dvec)
{
    extern __shared__ float sm[];
    float* clr = sm;                 // 64 x 33
    float* cli = sm + 2112;
    float* Bre = sm + 2*2112;
    float* Bim = sm + 3*2112;
    float* Cre = sm + 4*2112;
    float* Cim = sm + 5*2112;
    float* xd  = sm + 6*2112;        // 64 x 65
    float* G   = sm + 6*2112 + 4160; // 64 x 65

    int tid = threadIdx.x;
    int bid = blockIdx.x;
    int h = bid & 31;
    int c = (bid >> 5) & 31;
    int b = bid >> 10;
    int blbase = b * SEQ + c * CH;

    for (int e = tid; e < CH*NK; e += 256) {
        int t = e >> 5, k = e & 31;
        int bl = blbase + t;
        clr[t*33+k] = g_lzr[(size_t)bl*(NH*NK) + h*NK + k];
        cli[t*33+k] = g_lzi[(size_t)bl*(NH*NK) + h*NK + k];
        Bre[t*33+k] = g_Br[bl*NK + k];
        Bim[t*33+k] = g_Bi[bl*NK + k];
        Cre[t*33+k] = g_Cr[bl*NK + k];
        Cim[t*33+k] = g_Ci[bl*NK + k];
    }
    for (int e = tid; e < CH*HD; e += 256) {
        int t = e >> 6, p = e & 63;
        int bl = blbase + t;
        xd[t*65+p] = g_xs[(size_t)bl*DIN + h*HD + p] * g_dt[bl*NH + h];
    }
    __syncthreads();

    if (tid < 32) {
        float sr = 0.f, si = 0.f;
        for (int t = 0; t < CH; t++) {
            sr += clr[t*33+tid]; si += cli[t*33+tid];
            clr[t*33+tid] = sr;  cli[t*33+tid] = si;
        }
    }
    __syncthreads();

    for (int e = tid; e < CH*NK; e += 256) {
        int t = e >> 5, k = e & 31;
        float er = __expf(clr[t*33+k]);
        float sn, cs; __sincosf(cli[t*33+k], &sn, &cs);
        float exr = er*cs, exi = er*sn;
        float cr = Cre[t*33+k], ci = Cim[t*33+k];
        size_t base = (size_t)bid*(CH*NK) + t*NK + k;
        g_Pr[base] = cr*exr - ci*exi;
        g_Pi[base] = cr*exi + ci*exr;
        if (t == CH-1) { g_Er[bid*NK + k] = exr; g_Ei[bid*NK + k] = exi; }
    }
    __syncthreads();

    for (int e = tid; e < CH*NK; e += 256) {
        int t = e >> 5, k = e & 31;
        float cr = Cre[t*33+k], ci = Cim[t*33+k];
        float br = Bre[t*33+k], bi = Bim[t*33+k];
        Cre[t*33+k] = cr*br - ci*bi;
        Cim[t*33+k] = cr*bi + ci*br;
    }
    __syncthreads();

    for (int e = tid; e < CH*CH; e += 256) {
        int t = e >> 6, s = e & 63;
        float acc = 0.f;
        if (s <= t) {
            #pragma unroll 4
            for (int k = 0; k < NK; k++) {
                float dr = clr[t*33+k] - clr[s*33+k];
                if (dr > -27.f) {
                    float di = cli[t*33+k] - cli[s*33+k];
                    float er = __expf(dr);
                    float sn, cs; __sincosf(di, &sn, &cs);
                    acc += er * (Cre[t*33+k]*cs - Cim[t*33+k]*sn);
                }
            }
        }
        G[t*65+s] = acc;
    }
    __syncthreads();

    float Dh = Dvec[h];
    for (int e = tid; e < CH*HD; e += 256) {
        int t = e >> 6, p = e & 63;
        float acc = 0.f;
        for (int s = 0; s <= t; s++) acc += G[t*65+s] * xd[s*65+p];
        size_t yi = (size_t)(blbase + t)*DIN + h*HD + p;
        g_y[yi] = acc + Dh * g_xs[yi];
    }

    for (int e = tid; e < CH*NK; e += 256) {
        int s = e >> 5, k = e & 31;
        float dr = clr[(CH-1)*33+k] - clr[s*33+k];
        float di = cli[(CH-1)*33+k] - cli[s*33+k];
        float er = __expf(dr);
        float sn, cs; __sincosf(di, &sn, &cs);
        Cre[s*33+k] = er*cs;
        Cim[s*33+k] = er*sn;
    }
    __syncthreads();

    for (int e = tid; e < HD*NK; e += 256) {
        int p = e >> 5, k = e & 31;
        float ar = 0.f, ai = 0.f;
        #pragma unroll 8
        for (int s = 0; s < CH; s++) {
            float xv = xd[s*65+p];
            ar += xv * Cre[s*33+k];
            ai += xv * Cim[s*33+k];
        }
        float br = Bre[(CH-1)*33+k], bi = Bim[(CH-1)*33+k];
        size_t di_ = (size_t)bid*(HD*NK) + p*NK + k;
        g_Dr[di_] = br*ar - bi*ai;
        g_Di[di_] = br*ai + bi*ar;
    }
}

// ---------------- sequential scan over chunks (per b,h,p,k) ----------------------
__global__ void scan_kernel()
{
    int idx = blockIdx.x * blockDim.x + threadIdx.x;
    int k = idx & 31;
    int p = (idx >> 5) & 63;
    int h = (idx >> 11) & 31;
    int b = idx >> 16;
    float sr = 0.f, si = 0.f;
    for (int c = 0; c < NCH; c++) {
        int bidl = (b*NCH + c)*NH + h;
        size_t di_ = (size_t)bidl*(HD*NK) + p*NK + k;
        g_Sr[di_] = sr; g_Si[di_] = si;
        float er = g_Er[bidl*NK + k], ei = g_Ei[bidl*NK + k];
        float dr = g_Dr[di_], dimg = g_Di[di_];
        float nr = er*sr - ei*si + dr;
        float ni = er*si + ei*sr + dimg;
        sr = nr; si = ni;
    }
}

// ---------------- y += Re( P[t,k] * S_entry[p,k] ) -------------------------------
__global__ __launch_bounds__(256) void yinter_kernel()
{
    __shared__ float Pr[2112], Pi[2112], Sr[2112], Si[2112];
    int tid = threadIdx.x, bid = blockIdx.x;
    int h = bid & 31, c = (bid >> 5) & 31, b = bid >> 10;
    size_t base = (size_t)bid * (CH*NK);
    for (int e = tid; e < CH*NK; e += 256) {
        int t = e >> 5, k = e & 31;
        Pr[t*33+k] = g_Pr[base + e];
        Pi[t*33+k] = g_Pi[base + e];
        Sr[t*33+k] = g_Sr[base + e];
        Si[t*33+k] = g_Si[base + e];
    }
    __syncthreads();
    int blbase = b*SEQ + c*CH;
    for (int e = tid; e < CH*HD; e += 256) {
        int t = e >> 6, p = e & 63;
        float acc = 0.f;
        #pragma unroll 8
        for (int k = 0; k < NK; k++)
            acc += Pr[t*33+k]*Sr[p*33+k] - Pi[t*33+k]*Si[p*33+k];
        size_t yi = (size_t)(blbase + t)*DIN + h*HD + p;
        g_y[yi] += acc;
    }
}

// ---------------- gating + RMSNorm -> split fp16 ---------------------------------
__global__ __launch_bounds__(256) void gatenorm_kernel(const float* __restrict__ norm_w)
{
    __shared__ float red[8];
    int bl = blockIdx.x, tid = threadIdx.x;
    float gv[8];
    float local = 0.f;
    #pragma unroll
    for (int i = 0; i < 8; i++) {
        int j = tid + i*256;
        float z = g_zx[(size_t)bl*DPROJ + j];
        float y = g_y[(size_t)bl*DIN + j];
        float sig = 1.f / (1.f + __expf(-z));
        float g = y * z * sig;
        gv[i] = g;
        local += g * g;
    }
    #pragma unroll
    for (int o = 16; o; o >>= 1) local += __shfl_xor_sync(0xffffffffu, local, o);
    if ((tid & 31) == 0) red[tid >> 5] = local;
    __syncthreads();
    if (tid == 0) {
        float s = 0.f;
        for (int i = 0; i < 8; i++) s += red[i];
        red[0] = rsqrtf(s / (float)DIN + 1e-5f);
    }
    __syncthreads();
    float sc = red[0];
    size_t ro = (size_t)bl * K2_OUT;
    #pragma unroll
    for (int i = 0; i < 8; i++) {
        int j = tid + i*256;
        float g = gv[i] * sc * norm_w[j];
        __half h = __float2half(g);
        __half l = __float2half(g - __half2float(h));
        g_g2[ro + j]       = h;   // hi
        g_g2[ro + DIN + j] = l;   // lo
    }
}

// ---------------- launch ---------------------------------------------------------
extern "C" void kernel_launch(void* const* d_in, const int* in_sizes, int n_in,
                              void* d_out, int out_size)
{
    (void)in_sizes; (void)n_in; (void)out_size;
    const float* x       = (const float*)d_in[0];
    const float* in_w    = (const float*)d_in[1];
    const float* conv_w  = (const float*)d_in[2];
    const float* conv_b  = (const float*)d_in[3];
    const float* dt_bias = (const float*)d_in[4];
    const float* lam_b   = (const float*)d_in[5];
    const float* th_b    = (const float*)d_in[6];
    const float* w1      = (const float*)d_in[7];
    const float* w2      = (const float*)d_in[8];
    const float* eta     = (const float*)d_in[9];
    const float* Dv      = (const float*)d_in[10];
    const float* nw      = (const float*)d_in[11];
    const float* out_w   = (const float*)d_in[12];
    float* out = (float*)d_out;

    float *zx = nullptr, *t1 = nullptr;
    __half *x2, *wi2, *w12, *g2, *wo2;
    cudaGetSymbolAddress((void**)&zx,  g_zx);
    cudaGetSymbolAddress((void**)&t1,  g_t1);
    cudaGetSymbolAddress((void**)&x2,  g_x2);
    cudaGetSymbolAddress((void**)&wi2, g_wi2);
    cudaGetSymbolAddress((void**)&w12, g_w12);
    cudaGetSymbolAddress((void**)&g2,  g_g2);
    cudaGetSymbolAddress((void**)&wo2, g_wo2);

    cudaFuncSetAttribute(gemm_half, cudaFuncAttributeMaxDynamicSharedMemorySize, GEMM_SMEM);

    // 0) splits
    {
        int n4 = BLTOT*DM/4;
        split2_kernel<<<(n4+255)/256, 256>>>(x, x2, n4, DM, 0);
    }
    {
        int n4 = DPROJ*DM/4;
        split2_kernel<<<(n4+255)/256, 256>>>(in_w, wi2, n4, DM, 1);
    }
    splitW1_kernel<<<(DM*LR+255)/256, 256>>>(w1);
    {
        int n4 = DM*DIN/4;
        split2_kernel<<<(n4+255)/256, 256>>>(out_w, wo2, n4, DIN, 1);
    }

    // 1) in_proj: [4096,2048] x [4352,2048]^T -> [4096,4256]
    gemm_half<<<dim3(34, BLTOT/128), 256, GEMM_SMEM>>>(x2, wi2, zx, BLTOT, DPROJ, K2_IN);
    // 2) dt
    dt_kernel<<<(BLTOT*NH + 255)/256, 256>>>(dt_bias);
    // 3) conv + silu + split
    conv_kernel<<<dim3((CONVD + 255)/256, BLTOT), 256>>>(conv_w, conv_b);
    // 4) lora stage 1 as GEMM: [4096,2048] x [128,2048]^T -> [4096,48]
    gemm_half<<<dim3(1, BLTOT/128), 256, GEMM_SMEM>>>(x2, w12, t1, BLTOT, LR, K2_IN);
    // 5) lora stage 2 (tanh on load) + log_z
    lora2_kernel<<<dim3(4, BLTOT/64), 256>>>(w2, th_b, lam_b, eta);
    // 6) chunk-parallel heavy kernel
    cudaFuncSetAttribute(chunk_kernel, cudaFuncAttributeMaxDynamicSharedMemorySize, 84*1024);
    chunk_kernel<<<BATCHN*NCH*NH, 256, 83968>>>(Dv);
    // 7) inter-chunk state scan
    scan_kernel<<<(BATCHN*NH*HD*NK)/256, 256>>>();
    // 8) y += P * S_entry
    yinter_kernel<<<BATCHN*NCH*NH, 256>>>();
    // 9) gate + rmsnorm -> split fp16
    gatenorm_kernel<<<BLTOT, 256>>>(nw);
    // 10) out_proj: [4096,4096] x [1024,4096]^T -> [4096,1024]
    gemm_half<<<dim3(DM/128, BLTOT/128), 256, GEMM_SMEM>>>(g2, wo2, out, BLTOT, DM, K2_OUT);
}

// round 9
// speedup vs baseline: 1.3611x; 1.0892x over previous
#include <cuda_runtime.h>
#include <cuda_fp16.h>
#include <math.h>

#define BATCHN 2
#define SEQ    2048
#define BLTOT  4096
#define DM     1024
#define DIN    2048
#define NH     32
#define HD     64
#define NK     32
#define CONVD  2176
#define DPROJ  4256
#define NCH    32
#define CH     64
#define LR     48
#define XBC_OFF 2048
#define DT_OFF  4224
#define T1_OFF  4256
#define ZXSTR   4352
#define THETA_CLIPF 1.5707963267948966f

#define K2_IN  (2*DM)     // 2048
#define NPAD_W 4352       // 34*128

// ---------------- scratch (static device globals; no allocation) ----------------
__device__ __align__(256) float g_zx [BLTOT*ZXSTR];
__device__ __align__(256) float g_dt [BLTOT*NH];
__device__ __align__(256) float g_xs [BLTOT*DIN];
__device__ __align__(256) float g_Br [BLTOT*NK];
__device__ __align__(256) float g_Bi [BLTOT*NK];
__device__ __align__(256) float g_Cr [BLTOT*NK];
__device__ __align__(256) float g_Ci [BLTOT*NK];
__device__ __align__(256) float g_lzr[BLTOT*NH*NK];
__device__ __align__(256) float g_lzi[BLTOT*NH*NK];
__device__ __align__(256) float g_Pr [BATCHN*NCH*NH*CH*NK];
__device__ __align__(256) float g_Pi [BATCHN*NCH*NH*CH*NK];
__device__ __align__(256) float g_Er [BATCHN*NCH*NH*NK];
__device__ __align__(256) float g_Ei [BATCHN*NCH*NH*NK];
__device__ __align__(256) float g_Dr [BATCHN*NCH*NH*HD*NK];
__device__ __align__(256) float g_Di [BATCHN*NCH*NH*HD*NK];
__device__ __align__(256) float g_Sr [BATCHN*NCH*NH*HD*NK];
__device__ __align__(256) float g_Si [BATCHN*NCH*NH*HD*NK];
__device__ __align__(256) float g_y  [BLTOT*DIN];

// fp16 buffers (zero-initialized => pad rows are 0)
__device__ __align__(256) __half g_x2 [BLTOT*K2_IN];     // x       [hi,lo]
__device__ __align__(256) __half g_wi2[NPAD_W*K2_IN];    // in_w+w1 [hi,hi]
__device__ __align__(256) __half g_gh [BLTOT*DIN];       // gated hi only
__device__ __align__(256) __half g_woh[DM*DIN];          // out_w hi only

// ================= asm helpers ==================================================
#define LDSM4(R0,R1,R2,R3,ADDR) \
    asm volatile("ldmatrix.sync.aligned.m8n8.x4.shared.b16 {%0,%1,%2,%3}, [%4];" \
                 : "=r"(R0),"=r"(R1),"=r"(R2),"=r"(R3) : "r"(ADDR))

#define CP_ASYNC16(DST,SRC) \
    asm volatile("cp.async.cg.shared.global [%0], [%1], 16;" :: "r"(DST), "l"(SRC))
#define CP_COMMIT asm volatile("cp.async.commit_group;")
#define CP_WAIT1  asm volatile("cp.async.wait_group 1;")

__device__ __forceinline__ unsigned smem_u32(const void* p)
{
    return (unsigned)__cvta_generic_to_shared(p);
}

__device__ __forceinline__ void mma_f16(float* d, const unsigned* a,
                                        unsigned b0, unsigned b1)
{
    asm volatile("mma.sync.aligned.m16n8k16.row.col.f32.f16.f16.f32 "
                 "{%0,%1,%2,%3}, {%4,%5,%6,%7}, {%8,%9}, {%0,%1,%2,%3};"
                 : "+f"(d[0]), "+f"(d[1]), "+f"(d[2]), "+f"(d[3])
                 : "r"(a[0]), "r"(a[1]), "r"(a[2]), "r"(a[3]), "r"(b0), "r"(b1));
}

// ================= fp16 GEMM: C[M,N] = A[M,K2] * B[N,K2]^T ======================
#define GSTR 72
#define NSTG 3
#define STG_ELE (128*GSTR)
#define GEMM_SMEM (NSTG * 2 * STG_ELE * 2)  // 110592 bytes

__global__ __launch_bounds__(256) void gemm_half(const __half* __restrict__ A,
                                                 const __half* __restrict__ B,
                                                 float* __restrict__ C,
                                                 int M, int N, int K2)
{
    extern __shared__ __align__(16) __half smg[];
    __half* sA = smg;
    __half* sB = smg + NSTG*STG_ELE;

    int tid = threadIdx.x, lane = tid & 31, wid = tid >> 5;
    int wm = wid & 3;
    int wn = wid >> 2;
    int row0 = blockIdx.y * 128, col0 = blockIdx.x * 128;

    float acc[2][8][4];
    #pragma unroll
    for (int a = 0; a < 2; a++)
        #pragma unroll
        for (int b = 0; b < 8; b++)
            #pragma unroll
            for (int c = 0; c < 4; c++) acc[a][b][c] = 0.f;

    int NT = K2 >> 6;

    #pragma unroll
    for (int s = 0; s < NSTG-1; s++) {
        int k0 = s << 6;
        #pragma unroll
        for (int i = 0; i < 4; i++) {
            int f = tid + i*256, r = f >> 3, kc = (f & 7) << 3;
            CP_ASYNC16(smem_u32(&sA[s*STG_ELE + r*GSTR + kc]), A + (size_t)(row0+r)*K2 + k0 + kc);
            CP_ASYNC16(smem_u32(&sB[s*STG_ELE + r*GSTR + kc]), B + (size_t)(col0+r)*K2 + k0 + kc);
        }
        CP_COMMIT;
    }

    for (int kt = 0; kt < NT; kt++) {
        CP_WAIT1;
        __syncthreads();

        {
            int kf = kt + NSTG - 1;
            if (kf < NT) {
                int s = kf % NSTG, k0 = kf << 6;
                #pragma unroll
                for (int i = 0; i < 4; i++) {
                    int f = tid + i*256, r = f >> 3, kc = (f & 7) << 3;
                    CP_ASYNC16(smem_u32(&sA[s*STG_ELE + r*GSTR + kc]), A + (size_t)(row0+r)*K2 + k0 + kc);
                    CP_ASYNC16(smem_u32(&sB[s*STG_ELE + r*GSTR + kc]), B + (size_t)(col0+r)*K2 + k0 + kc);
                }
            }
            CP_COMMIT;
        }

        const __half* a_s = sA + (kt % NSTG)*STG_ELE;
        const __half* b_s = sB + (kt % NSTG)*STG_ELE;

        #pragma unroll
        for (int kh = 0; kh < 64; kh += 16) {
            unsigned ah[2][4];
            #pragma unroll
            for (int mf = 0; mf < 2; mf++) {
                int r = wm*32 + mf*16 + (lane & 15);
                int cc = kh + ((lane >> 4) << 3);
                LDSM4(ah[mf][0], ah[mf][1], ah[mf][2], ah[mf][3],
                      smem_u32(&a_s[r*GSTR + cc]));
            }
            #pragma unroll
            for (int np = 0; np < 4; np++) {
                int nr  = wn*64 + np*16 + (lane & 7) + ((lane >> 4) << 3);
                int kof = kh + (((lane >> 3) & 1) << 3);
                unsigned bh[4];
                LDSM4(bh[0], bh[1], bh[2], bh[3], smem_u32(&b_s[nr*GSTR + kof]));
                #pragma unroll
                for (int mf = 0; mf < 2; mf++) {
                    mma_f16(acc[mf][np*2+0], ah[mf], bh[0], bh[1]);
                    mma_f16(acc[mf][np*2+1], ah[mf], bh[2], bh[3]);
                }
            }
        }
    }

    #pragma unroll
    for (int mf = 0; mf < 2; mf++) {
        int r = row0 + wm*32 + mf*16 + (lane >> 2);
        #pragma unroll
        for (int nf = 0; nf < 8; nf++) {
            int c = col0 + wn*64 + nf*8 + ((lane & 3) << 1);
            if (c + 1 < N) {
                *(float2*)&C[(size_t)r*N + c]     = make_float2(acc[mf][nf][0], acc[mf][nf][1]);
                *(float2*)&C[(size_t)(r+8)*N + c] = make_float2(acc[mf][nf][2], acc[mf][nf][3]);
            } else if (c < N) {
                C[(size_t)r*N + c]     = acc[mf][nf][0];
                C[(size_t)(r+8)*N + c] = acc[mf][nf][2];
            }
        }
    }
}

// ---------------- split fp32 -> 2-segment fp16 ----------------------------------
__global__ void split2_kernel(const float* __restrict__ src,
                              __half* __restrict__ dst,
                              int n4, int K, int wmode)
{
    int i = blockIdx.x * blockDim.x + threadIdx.x;
    if (i >= n4) return;
    int base = i * 4;
    int r = base / K, k = base - r * K;
    float4 v = *(const float4*)(src + base);
    float xs[4] = {v.x, v.y, v.z, v.w};
    __half h[4], l[4];
    #pragma unroll
    for (int j = 0; j < 4; j++) {
        h[j] = __float2half(xs[j]);
        l[j] = wmode ? h[j] : __float2half(xs[j] - __half2float(h[j]));
    }
    size_t ro = (size_t)r * 2 * K + k;
    __half2 hp0, hp1, lp0, lp1;
    hp0.x = h[0]; hp0.y = h[1]; hp1.x = h[2]; hp1.y = h[3];
    lp0.x = l[0]; lp0.y = l[1]; lp1.x = l[2]; lp1.y = l[3];
    ((__half2*)(dst + ro))[0] = hp0;
    ((__half2*)(dst + ro))[1] = hp1;
    ((__half2*)(dst + ro + (size_t)K))[0] = lp0;
    ((__half2*)(dst + ro + (size_t)K))[1] = lp1;
}

// ---------------- plain fp32 -> fp16 convert ------------------------------------
__global__ void tofp16_kernel(const float* __restrict__ src,
                              __half* __restrict__ dst, int n4)
{
    int i = blockIdx.x * blockDim.x + threadIdx.x;
    if (i >= n4) return;
    float4 v = *(const float4*)(src + i*4);
    __half2 a, b;
    a.x = __float2half(v.x); a.y = __float2half(v.y);
    b.x = __float2half(v.z); b.y = __float2half(v.w);
    ((__half2*)(dst + i*4))[0] = a;
    ((__half2*)(dst + i*4))[1] = b;
}

// ---------------- w1 (DM x LR) -> rows T1_OFF.. of g_wi2 [hi,hi] ----------------
__global__ void splitW1_kernel(const float* __restrict__ w1)
{
    int idx = blockIdx.x * blockDim.x + threadIdx.x;
    if (idx >= DM * LR) return;
    int k = idx / LR, n = idx % LR;
    __half h = __float2half(w1[idx]);
    size_t ro = (size_t)(T1_OFF + n) * K2_IN + k;
    g_wi2[ro]      = h;
    g_wi2[ro + DM] = h;
}

// ---------------- dt = softplus(zx[:, DT_OFF+h] + dt_bias[h]) --------------------
__global__ void dt_kernel(const float* __restrict__ dt_bias)
{
    int idx = blockIdx.x * blockDim.x + threadIdx.x;
    if (idx >= BLTOT * NH) return;
    int bl = idx >> 5, hh = idx & 31;
    float v = g_zx[(size_t)bl * ZXSTR + DT_OFF + hh] + dt_bias[hh];
    float sp = (v > 20.f) ? v : log1pf(expf(v));
    g_dt[idx] = sp;
}

// ---------------- depthwise causal conv (width 4) + silu + split -----------------
__global__ void conv_kernel(const float* __restrict__ conv_w,
                            const float* __restrict__ conv_b)
{
    int c = blockIdx.x * blockDim.x + threadIdx.x;
    if (c >= CONVD) return;
    int bl = blockIdx.y;
    int l = bl & (SEQ - 1);
    float acc = conv_b[c];
    #pragma unroll
    for (int kk = 0; kk < 4; kk++) {
        int lt = l + kk - 3;
        if (lt >= 0)
            acc += g_zx[(size_t)(bl + kk - 3) * ZXSTR + XBC_OFF + c] * conv_w[c*4 + kk];
    }
    float a = acc / (1.f + __expf(-acc));
    if (c < DIN) {
        g_xs[(size_t)bl * DIN + c] = a;
    } else {
        int c2 = c - DIN;
        if (c2 < 64) {
            int k = c2 >> 1;
            if (c2 & 1) g_Bi[bl*NK + k] = a; else g_Br[bl*NK + k] = a;
        } else {
            int c3 = c2 - 64;
            int k = c3 >> 1;
            if (c3 & 1) g_Ci[bl*NK + k] = a; else g_Cr[bl*NK + k] = a;
        }
    }
}

// ---------------- lora2 (tanh applied on load, t1 from zx columns) ---------------
__global__ __launch_bounds__(256) void lora2_kernel(const float* __restrict__ w2,
                                                    const float* __restrict__ theta_base,
                                                    const float* __restrict__ lambda_base,
                                                    const float* __restrict__ eta)
{
    __shared__ float t1s[64][LR];
    __shared__ float w2s[LR][256];
    int tid = threadIdx.x;
    int row0 = blockIdx.y * 64;
    int col0 = blockIdx.x * 256;
    int n = col0 + tid;

    for (int idx = tid; idx < 64*LR; idx += 256) {
        int r = idx / LR, j = idx % LR;
        t1s[r][j] = tanhf(g_zx[(size_t)(row0 + r)*ZXSTR + T1_OFF + j]);
    }
    for (int idx = tid; idx < LR*256; idx += 256) {
        int j = idx >> 8, cc = idx & 255;
        w2s[j][cc] = w2[(size_t)j*(NH*NK) + col0 + cc];
    }
    __syncthreads();

    float tb = theta_base[n];
    float lb = lambda_base[n];
    float et = eta[n];
    int hh = n >> 5;

    for (int r = 0; r < 64; r++) {
        float acc = 0.f;
        #pragma unroll
        for (int j = 0; j < LR; j++) acc += t1s[r][j] * w2s[j][tid];
        float th = tb + acc;
        th = fminf(fmaxf(th, -THETA_CLIPF), THETA_CLIPF);
        float lam = lb + et * th * th;
        int bl = row0 + r;
        float dtv = g_dt[bl*NH + hh];
        g_lzr[(size_t)bl*(NH*NK) + n] = -lam * dtv;
        g_lzi[(size_t)bl*(NH*NK) + n] =  th * dtv;
    }
}

// ---------------- per-chunk kernel: cumlog, G, y_intra, P/E, D -------------------
#define CHUNK_SMEM ((6*2112 + 2*4160 + 64) * 4)   // 84480 B

__global__ __launch_bounds__(256) void chunk_kernel(const float* __restrict__ Dvec)
{
    extern __shared__ float sm[];
    float* clr = sm;                 // 64 x 33
    float* cli = sm + 2112;
    float* Bre = sm + 2*2112;
    float* Bim = sm + 3*2112;
    float* Cre = sm + 4*2112;
    float* Cim = sm + 5*2112;
    float* xd  = sm + 6*2112;        // 64 x 65
    float* G   = sm + 6*2112 + 4160; // 64 x 65
    float* mx  = sm + 6*2112 + 2*4160;  // 64: cumsum of rowmax(lzr)

    int tid = threadIdx.x;
    int bid = blockIdx.x;
    int h = bid & 31;
    int c = (bid >> 5) & 31;
    int b = bid >> 10;
    int blbase = b * SEQ + c * CH;

    for (int e = tid; e < CH*NK; e += 256) {
        int t = e >> 5, k = e & 31;
        int bl = blbase + t;
        clr[t*33+k] = g_lzr[(size_t)bl*(NH*NK) + h*NK + k];
        cli[t*33+k] = g_lzi[(size_t)bl*(NH*NK) + h*NK + k];
        Bre[t*33+k] = g_Br[bl*NK + k];
        Bim[t*33+k] = g_Bi[bl*NK + k];
        Cre[t*33+k] = g_Cr[bl*NK + k];
        Cim[t*33+k] = g_Ci[bl*NK + k];
    }
    for (int e = tid; e < CH*HD; e += 256) {
        int t = e >> 6, p = e & 63;
        int bl = blbase + t;
        xd[t*65+p] = g_xs[(size_t)bl*DIN + h*HD + p] * g_dt[bl*NH + h];
    }
    __syncthreads();

    // rowmax of raw lzr
    if (tid < CH) {
        float m = -1e30f;
        #pragma unroll 8
        for (int k = 0; k < NK; k++) m = fmaxf(m, clr[tid*33+k]);
        mx[tid] = m;
    }
    __syncthreads();

    // cumsum of log_z (warp 0, per-k lanes) + cumsum of rowmax (thread 32)
    if (tid < 32) {
        float sr = 0.f, si = 0.f;
        for (int t = 0; t < CH; t++) {
            sr += clr[t*33+tid]; si += cli[t*33+tid];
            clr[t*33+tid] = sr;  cli[t*33+tid] = si;
        }
    } else if (tid == 32) {
        float s = 0.f;
        for (int t = 0; t < CH; t++) { s += mx[t]; mx[t] = s; }
    }
    __syncthreads();

    for (int e = tid; e < CH*NK; e += 256) {
        int t = e >> 5, k = e & 31;
        float er = __expf(clr[t*33+k]);
        float sn, cs; __sincosf(cli[t*33+k], &sn, &cs);
        float exr = er*cs, exi = er*sn;
        float cr = Cre[t*33+k], ci = Cim[t*33+k];
        size_t base = (size_t)bid*(CH*NK) + t*NK + k;
        g_Pr[base] = cr*exr - ci*exi;
        g_Pi[base] = cr*exi + ci*exr;
        if (t == CH-1) { g_Er[bid*NK + k] = exr; g_Ei[bid*NK + k] = exi; }
    }
    __syncthreads();

    // cb = C*B (overwrite C)
    for (int e = tid; e < CH*NK; e += 256) {
        int t = e >> 5, k = e & 31;
        float cr = Cre[t*33+k], ci = Cim[t*33+k];
        float br = Bre[t*33+k], bi = Bim[t*33+k];
        Cre[t*33+k] = cr*br - ci*bi;
        Cim[t*33+k] = cr*bi + ci*br;
    }
    __syncthreads();

    // G[t,s] = Re( sum_k cb[t,k]*exp(cl[t]-cl[s]) ), s<=t, banded
    for (int e = tid; e < CH*CH; e += 256) {
        int t = e >> 6, s = e & 63;
        float acc = 0.f;
        if (s <= t && (s == t || mx[t] - mx[s] > -13.8f)) {
            #pragma unroll 4
            for (int k = 0; k < NK; k++) {
                float dr = clr[t*33+k] - clr[s*33+k];
                if (dr > -13.8f) {
                    float di = cli[t*33+k] - cli[s*33+k];
                    float er = __expf(dr);
                    float sn, cs; __sincosf(di, &sn, &cs);
                    acc += er * (Cre[t*33+k]*cs - Cim[t*33+k]*sn);
                }
            }
        }
        G[t*65+s] = acc;
    }
    __syncthreads();

    float Dh = Dvec[h];
    for (int e = tid; e < CH*HD; e += 256) {
        int t = e >> 6, p = e & 63;
        float acc = 0.f;
        for (int s = 0; s <= t; s++) acc += G[t*65+s] * xd[s*65+p];
        size_t yi = (size_t)(blbase + t)*DIN + h*HD + p;
        g_y[yi] = acc + Dh * g_xs[yi];
    }

    for (int e = tid; e < CH*NK; e += 256) {
        int s = e >> 5, k = e & 31;
        float dr = clr[(CH-1)*33+k] - clr[s*33+k];
        float di = cli[(CH-1)*33+k] - cli[s*33+k];
        float er = __expf(dr);
        float sn, cs; __sincosf(di, &sn, &cs);
        Cre[s*33+k] = er*cs;
        Cim[s*33+k] = er*sn;
    }
    __syncthreads();

    for (int e = tid; e < HD*NK; e += 256) {
        int p = e >> 5, k = e & 31;
        float ar = 0.f, ai = 0.f;
        #pragma unroll 8
        for (int s = 0; s < CH; s++) {
            float xv = xd[s*65+p];
            ar += xv * Cre[s*33+k];
            ai += xv * Cim[s*33+k];
        }
        float br = Bre[(CH-1)*33+k], bi = Bim[(CH-1)*33+k];
        size_t di_ = (size_t)bid*(HD*NK) + p*NK + k;
        g_Dr[di_] = br*ar - bi*ai;
        g_Di[di_] = br*ai + bi*ar;
    }
}

// ---------------- sequential scan over chunks (per b,h,p,k) ----------------------
__global__ void scan_kernel()
{
    int idx = blockIdx.x * blockDim.x + threadIdx.x;
    int k = idx & 31;
    int p = (idx >> 5) & 63;
    int h = (idx >> 11) & 31;
    int b = idx >> 16;
    float sr = 0.f, si = 0.f;
    for (int c = 0; c < NCH; c++) {
        int bidl = (b*NCH + c)*NH + h;
        size_t di_ = (size_t)bidl*(HD*NK) + p*NK + k;
        g_Sr[di_] = sr; g_Si[di_] = si;
        float er = g_Er[bidl*NK + k], ei = g_Ei[bidl*NK + k];
        float dr = g_Dr[di_], dimg = g_Di[di_];
        float nr = er*sr - ei*si + dr;
        float ni = er*si + ei*sr + dimg;
        sr = nr; si = ni;
    }
}

// ---------------- y += Re( P[t,k] * S_entry[p,k] ) -------------------------------
__global__ __launch_bounds__(256) void yinter_kernel()
{
    __shared__ float Pr[2112], Pi[2112], Sr[2112], Si[2112];
    int tid = threadIdx.x, bid = blockIdx.x;
    int h = bid & 31, c = (bid >> 5) & 31, b = bid >> 10;
    size_t base = (size_t)bid * (CH*NK);
    for (int e = tid; e < CH*NK; e += 256) {
        int t = e >> 5, k = e & 31;
        Pr[t*33+k] = g_Pr[base + e];
        Pi[t*33+k] = g_Pi[base + e];
        Sr[t*33+k] = g_Sr[base + e];
        Si[t*33+k] = g_Si[base + e];
    }
    __syncthreads();
    int blbase = b*SEQ + c*CH;
    for (int e = tid; e < CH*HD; e += 256) {
        int t = e >> 6, p = e & 63;
        float acc = 0.f;
        #pragma unroll 8
        for (int k = 0; k < NK; k++)
            acc += Pr[t*33+k]*Sr[p*33+k] - Pi[t*33+k]*Si[p*33+k];
        size_t yi = (size_t)(blbase + t)*DIN + h*HD + p;
        g_y[yi] += acc;
    }
}

// ---------------- gating + RMSNorm -> fp16 ---------------------------------------
__global__ __launch_bounds__(256) void gatenorm_kernel(const float* __restrict__ norm_w)
{
    __shared__ float red[8];
    int bl = blockIdx.x, tid = threadIdx.x;
    float gv[8];
    float local = 0.f;
    #pragma unroll
    for (int i = 0; i < 8; i++) {
        int j = tid + i*256;
        float z = g_zx[(size_t)bl*ZXSTR + j];
        float y = g_y[(size_t)bl*DIN + j];
        float sig = 1.f / (1.f + __expf(-z));
        float g = y * z * sig;
        gv[i] = g;
        local += g * g;
    }
    #pragma unroll
    for (int o = 16; o; o >>= 1) local += __shfl_xor_sync(0xffffffffu, local, o);
    if ((tid & 31) == 0) red[tid >> 5] = local;
    __syncthreads();
    if (tid == 0) {
        float s = 0.f;
        for (int i = 0; i < 8; i++) s += red[i];
        red[0] = rsqrtf(s / (float)DIN + 1e-5f);
    }
    __syncthreads();
    float sc = red[0];
    size_t ro = (size_t)bl * DIN;
    #pragma unroll
    for (int i = 0; i < 8; i++) {
        int j = tid + i*256;
        g_gh[ro + j] = __float2half(gv[i] * sc * norm_w[j]);
    }
}

// ---------------- launch ---------------------------------------------------------
extern "C" void kernel_launch(void* const* d_in, const int* in_sizes, int n_in,
                              void* d_out, int out_size)
{
    (void)in_sizes; (void)n_in; (void)out_size;
    const float* x       = (const float*)d_in[0];
    const float* in_w    = (const float*)d_in[1];
    const float* conv_w  = (const float*)d_in[2];
    const float* conv_b  = (const float*)d_in[3];
    const float* dt_bias = (const float*)d_in[4];
    const float* lam_b   = (const float*)d_in[5];
    const float* th_b    = (const float*)d_in[6];
    const float* w1      = (const float*)d_in[7];
    const float* w2      = (const float*)d_in[8];
    const float* eta     = (const float*)d_in[9];
    const float* Dv      = (const float*)d_in[10];
    const float* nw      = (const float*)d_in[11];
    const float* out_w   = (const float*)d_in[12];
    float* out = (float*)d_out;

    float *zx = nullptr;
    __half *x2, *wi2, *gh, *woh;
    cudaGetSymbolAddress((void**)&zx,  g_zx);
    cudaGetSymbolAddress((void**)&x2,  g_x2);
    cudaGetSymbolAddress((void**)&wi2, g_wi2);
    cudaGetSymbolAddress((void**)&gh,  g_gh);
    cudaGetSymbolAddress((void**)&woh, g_woh);

    cudaFuncSetAttribute(gemm_half, cudaFuncAttributeMaxDynamicSharedMemorySize, GEMM_SMEM);

    // 0) splits / converts
    {
        int n4 = BLTOT*DM/4;
        split2_kernel<<<(n4+255)/256, 256>>>(x, x2, n4, DM, 0);
    }
    {
        int n4 = DPROJ*DM/4;
        split2_kernel<<<(n4+255)/256, 256>>>(in_w, wi2, n4, DM, 1);
    }
    splitW1_kernel<<<(DM*LR+255)/256, 256>>>(w1);
    {
        int n4 = DM*DIN/4;
        tofp16_kernel<<<(n4+255)/256, 256>>>(out_w, woh, n4);
    }

    // 1) in_proj (+fused lora1): [4096,2048] x [4352,2048]^T -> [4096,4352]
    gemm_half<<<dim3(NPAD_W/128, BLTOT/128), 256, GEMM_SMEM>>>(x2, wi2, zx, BLTOT, ZXSTR, K2_IN);
    // 2) dt
    dt_kernel<<<(BLTOT*NH + 255)/256, 256>>>(dt_bias);
    // 3) conv + silu + split
    conv_kernel<<<dim3((CONVD + 255)/256, BLTOT), 256>>>(conv_w, conv_b);
    // 4) lora stage 2 (tanh on load) + log_z
    lora2_kernel<<<dim3(4, BLTOT/64), 256>>>(w2, th_b, lam_b, eta);
    // 5) chunk-parallel heavy kernel
    cudaFuncSetAttribute(chunk_kernel, cudaFuncAttributeMaxDynamicSharedMemorySize, CHUNK_SMEM);
    chunk_kernel<<<BATCHN*NCH*NH, 256, CHUNK_SMEM>>>(Dv);
    // 6) inter-chunk state scan
    scan_kernel<<<(BATCHN*NH*HD*NK)/256, 256>>>();
    // 7) y += P * S_entry
    yinter_kernel<<<BATCHN*NCH*NH, 256>>>();
    // 8) gate + rmsnorm -> fp16
    gatenorm_kernel<<<BLTOT, 256>>>(nw);
    // 9) out_proj (pure fp16): [4096,2048] x [1024,2048]^T -> [4096,1024]
    gemm_half<<<dim3(DM/128, BLTOT/128), 256, GEMM_SMEM>>>(gh, woh, out, BLTOT, DM, DIN);
}

// round 10
// speedup vs baseline: 1.5284x; 1.1229x over previous
#include <cuda_runtime.h>
#include <cuda_fp16.h>
#include <math.h>

#define BATCHN 2
#define SEQ    2048
#define BLTOT  4096
#define DM     1024
#define DIN    2048
#define NH     32
#define HD     64
#define NK     32
#define CONVD  2176
#define DPROJ  4256
#define NCH    32
#define CH     64
#define LR     48
#define XBC_OFF 2048
#define DT_OFF  4224
#define T1_OFF  4256
#define ZXSTR   4352
#define THETA_CLIPF 1.5707963267948966f

#define NPAD_W 4352       // 34*128

// ---------------- scratch (static device globals; no allocation) ----------------
__device__ __align__(256) float g_zx [BLTOT*ZXSTR];
__device__ __align__(256) float g_dt [BLTOT*NH];
__device__ __align__(256) float g_xs [BLTOT*DIN];
__device__ __align__(256) float g_Br [BLTOT*NK];
__device__ __align__(256) float g_Bi [BLTOT*NK];
__device__ __align__(256) float g_Cr [BLTOT*NK];
__device__ __align__(256) float g_Ci [BLTOT*NK];
__device__ __align__(256) float g_lzr[BLTOT*NH*NK];
__device__ __align__(256) float g_lzi[BLTOT*NH*NK];
__device__ __align__(256) float g_Pr [BATCHN*NCH*NH*CH*NK];
__device__ __align__(256) float g_Pi [BATCHN*NCH*NH*CH*NK];
__device__ __align__(256) float g_Er [BATCHN*NCH*NH*NK];
__device__ __align__(256) float g_Ei [BATCHN*NCH*NH*NK];
__device__ __align__(256) float g_Dr [BATCHN*NCH*NH*HD*NK];
__device__ __align__(256) float g_Di [BATCHN*NCH*NH*HD*NK];
__device__ __align__(256) float g_Sr [BATCHN*NCH*NH*HD*NK];
__device__ __align__(256) float g_Si [BATCHN*NCH*NH*HD*NK];
__device__ __align__(256) float g_y  [BLTOT*DIN];

// fp16 buffers (zero-initialized => pad rows are 0)
__device__ __align__(256) __half g_xh [BLTOT*DM];        // x   (fp16)
__device__ __align__(256) __half g_wih[NPAD_W*DM];       // in_w rows + w1^T rows
__device__ __align__(256) __half g_gh [BLTOT*DIN];       // gated (fp16)
__device__ __align__(256) __half g_woh[DM*DIN];          // out_w (fp16)

// ================= asm helpers ==================================================
#define LDSM4(R0,R1,R2,R3,ADDR) \
    asm volatile("ldmatrix.sync.aligned.m8n8.x4.shared.b16 {%0,%1,%2,%3}, [%4];" \
                 : "=r"(R0),"=r"(R1),"=r"(R2),"=r"(R3) : "r"(ADDR))

#define CP_ASYNC16(DST,SRC) \
    asm volatile("cp.async.cg.shared.global [%0], [%1], 16;" :: "r"(DST), "l"(SRC))
#define CP_COMMIT asm volatile("cp.async.commit_group;")
#define CP_WAITP  asm volatile("cp.async.wait_group 0;")

__device__ __forceinline__ unsigned smem_u32(const void* p)
{
    return (unsigned)__cvta_generic_to_shared(p);
}

__device__ __forceinline__ void mma_f16(float* d, const unsigned* a,
                                        unsigned b0, unsigned b1)
{
    asm volatile("mma.sync.aligned.m16n8k16.row.col.f32.f16.f16.f32 "
                 "{%0,%1,%2,%3}, {%4,%5,%6,%7}, {%8,%9}, {%0,%1,%2,%3};"
                 : "+f"(d[0]), "+f"(d[1]), "+f"(d[2]), "+f"(d[3])
                 : "r"(a[0]), "r"(a[1]), "r"(a[2]), "r"(a[3]), "r"(b0), "r"(b1));
}

// ================= fp16 GEMM: C[M,N] = A[M,K] * B[N,K]^T ========================
// 128x128 tile, BK=64, 2-stage cp.async double buffer, 2 CTAs/SM.
#define GSTR 72
#define NSTG 2
#define STG_ELE (128*GSTR)
#define GEMM_SMEM (NSTG * 2 * STG_ELE * 2)  // 73728 bytes

__global__ __launch_bounds__(256, 2) void gemm_half(const __half* __restrict__ A,
                                                    const __half* __restrict__ B,
                                                    float* __restrict__ C,
                                                    int M, int N, int K)
{
    extern __shared__ __align__(16) __half smg[];
    __half* sA = smg;
    __half* sB = smg + NSTG*STG_ELE;

    int tid = threadIdx.x, lane = tid & 31, wid = tid >> 5;
    int wm = wid & 3;
    int wn = wid >> 2;
    int row0 = blockIdx.y * 128, col0 = blockIdx.x * 128;

    float acc[2][8][4];
    #pragma unroll
    for (int a = 0; a < 2; a++)
        #pragma unroll
        for (int b = 0; b < 8; b++)
            #pragma unroll
            for (int c = 0; c < 4; c++) acc[a][b][c] = 0.f;

    int NT = K >> 6;

    // prologue: stage 0
    {
        #pragma unroll
        for (int i = 0; i < 4; i++) {
            int f = tid + i*256, r = f >> 3, kc = (f & 7) << 3;
            CP_ASYNC16(smem_u32(&sA[r*GSTR + kc]), A + (size_t)(row0+r)*K + kc);
            CP_ASYNC16(smem_u32(&sB[r*GSTR + kc]), B + (size_t)(col0+r)*K + kc);
        }
        CP_COMMIT;
    }

    for (int kt = 0; kt < NT; kt++) {
        CP_WAITP;            // stage kt complete
        __syncthreads();

        {
            int kf = kt + 1;
            if (kf < NT) {
                int s = kf & 1, k0 = kf << 6;
                #pragma unroll
                for (int i = 0; i < 4; i++) {
                    int f = tid + i*256, r = f >> 3, kc = (f & 7) << 3;
                    CP_ASYNC16(smem_u32(&sA[s*STG_ELE + r*GSTR + kc]), A + (size_t)(row0+r)*K + k0 + kc);
                    CP_ASYNC16(smem_u32(&sB[s*STG_ELE + r*GSTR + kc]), B + (size_t)(col0+r)*K + k0 + kc);
                }
                CP_COMMIT;
            }
        }

        const __half* a_s = sA + (kt & 1)*STG_ELE;
        const __half* b_s = sB + (kt & 1)*STG_ELE;

        #pragma unroll
        for (int kh = 0; kh < 64; kh += 16) {
            unsigned ah[2][4];
            #pragma unroll
            for (int mf = 0; mf < 2; mf++) {
                int r = wm*32 + mf*16 + (lane & 15);
                int cc = kh + ((lane >> 4) << 3);
                LDSM4(ah[mf][0], ah[mf][1], ah[mf][2], ah[mf][3],
                      smem_u32(&a_s[r*GSTR + cc]));
            }
            #pragma unroll
            for (int np = 0; np < 4; np++) {
                int nr  = wn*64 + np*16 + (lane & 7) + ((lane >> 4) << 3);
                int kof = kh + (((lane >> 3) & 1) << 3);
                unsigned bh[4];
                LDSM4(bh[0], bh[1], bh[2], bh[3], smem_u32(&b_s[nr*GSTR + kof]));
                #pragma unroll
                for (int mf = 0; mf < 2; mf++) {
                    mma_f16(acc[mf][np*2+0], ah[mf], bh[0], bh[1]);
                    mma_f16(acc[mf][np*2+1], ah[mf], bh[2], bh[3]);
                }
            }
        }
    }

    #pragma unroll
    for (int mf = 0; mf < 2; mf++) {
        int r = row0 + wm*32 + mf*16 + (lane >> 2);
        #pragma unroll
        for (int nf = 0; nf < 8; nf++) {
            int c = col0 + wn*64 + nf*8 + ((lane & 3) << 1);
            if (c + 1 < N) {
                *(float2*)&C[(size_t)r*N + c]     = make_float2(acc[mf][nf][0], acc[mf][nf][1]);
                *(float2*)&C[(size_t)(r+8)*N + c] = make_float2(acc[mf][nf][2], acc[mf][nf][3]);
            } else if (c < N) {
                C[(size_t)r*N + c]     = acc[mf][nf][0];
                C[(size_t)(r+8)*N + c] = acc[mf][nf][2];
            }
        }
    }
}

// ---------------- plain fp32 -> fp16 convert ------------------------------------
__global__ void tofp16_kernel(const float* __restrict__ src,
                              __half* __restrict__ dst, int n4)
{
    int i = blockIdx.x * blockDim.x + threadIdx.x;
    if (i >= n4) return;
    float4 v = *(const float4*)(src + i*4);
    __half2 a, b;
    a.x = __float2half(v.x); a.y = __float2half(v.y);
    b.x = __float2half(v.z); b.y = __float2half(v.w);
    ((__half2*)(dst + i*4))[0] = a;
    ((__half2*)(dst + i*4))[1] = b;
}

// ---------------- w1 (DM x LR) -> rows T1_OFF.. of g_wih ------------------------
__global__ void splitW1_kernel(const float* __restrict__ w1)
{
    int idx = blockIdx.x * blockDim.x + threadIdx.x;
    if (idx >= DM * LR) return;
    int k = idx / LR, n = idx % LR;
    g_wih[(size_t)(T1_OFF + n) * DM + k] = __float2half(w1[idx]);
}

// ---------------- dt = softplus(zx[:, DT_OFF+h] + dt_bias[h]) --------------------
__global__ void dt_kernel(const float* __restrict__ dt_bias)
{
    int idx = blockIdx.x * blockDim.x + threadIdx.x;
    if (idx >= BLTOT * NH) return;
    int bl = idx >> 5, hh = idx & 31;
    float v = g_zx[(size_t)bl * ZXSTR + DT_OFF + hh] + dt_bias[hh];
    float sp = (v > 20.f) ? v : log1pf(expf(v));
    g_dt[idx] = sp;
}

// ---------------- depthwise causal conv (width 4) + silu + split -----------------
__global__ void conv_kernel(const float* __restrict__ conv_w,
                            const float* __restrict__ conv_b)
{
    int c = blockIdx.x * blockDim.x + threadIdx.x;
    if (c >= CONVD) return;
    int bl = blockIdx.y;
    int l = bl & (SEQ - 1);
    float acc = conv_b[c];
    #pragma unroll
    for (int kk = 0; kk < 4; kk++) {
        int lt = l + kk - 3;
        if (lt >= 0)
            acc += g_zx[(size_t)(bl + kk - 3) * ZXSTR + XBC_OFF + c] * conv_w[c*4 + kk];
    }
    float a = acc / (1.f + __expf(-acc));
    if (c < DIN) {
        g_xs[(size_t)bl * DIN + c] = a;
    } else {
        int c2 = c - DIN;
        if (c2 < 64) {
            int k = c2 >> 1;
            if (c2 & 1) g_Bi[bl*NK + k] = a; else g_Br[bl*NK + k] = a;
        } else {
            int c3 = c2 - 64;
            int k = c3 >> 1;
            if (c3 & 1) g_Ci[bl*NK + k] = a; else g_Cr[bl*NK + k] = a;
        }
    }
}

// ---------------- lora2 (tanh applied on load, t1 from zx columns) ---------------
__global__ __launch_bounds__(256) void lora2_kernel(const float* __restrict__ w2,
                                                    const float* __restrict__ theta_base,
                                                    const float* __restrict__ lambda_base,
                                                    const float* __restrict__ eta)
{
    __shared__ float t1s[64][LR];
    __shared__ float w2s[LR][256];
    int tid = threadIdx.x;
    int row0 = blockIdx.y * 64;
    int col0 = blockIdx.x * 256;
    int n = col0 + tid;

    for (int idx = tid; idx < 64*LR; idx += 256) {
        int r = idx / LR, j = idx % LR;
        t1s[r][j] = tanhf(g_zx[(size_t)(row0 + r)*ZXSTR + T1_OFF + j]);
    }
    for (int idx = tid; idx < LR*256; idx += 256) {
        int j = idx >> 8, cc = idx & 255;
        w2s[j][cc] = w2[(size_t)j*(NH*NK) + col0 + cc];
    }
    __syncthreads();

    float tb = theta_base[n];
    float lb = lambda_base[n];
    float et = eta[n];
    int hh = n >> 5;

    for (int r = 0; r < 64; r++) {
        float acc = 0.f;
        #pragma unroll
        for (int j = 0; j < LR; j++) acc += t1s[r][j] * w2s[j][tid];
        float th = tb + acc;
        th = fminf(fmaxf(th, -THETA_CLIPF), THETA_CLIPF);
        float lam = lb + et * th * th;
        int bl = row0 + r;
        float dtv = g_dt[bl*NH + hh];
        g_lzr[(size_t)bl*(NH*NK) + n] = -lam * dtv;
        g_lzi[(size_t)bl*(NH*NK) + n] =  th * dtv;
    }
}

// ---------------- per-chunk kernel: cumlog, G, y_intra, P/E, D -------------------
#define CHUNK_SMEM ((6*2112 + 2*4160 + 64) * 4)   // 84480 B

__global__ __launch_bounds__(256) void chunk_kernel(const float* __restrict__ Dvec)
{
    extern __shared__ float sm[];
    float* clr = sm;                 // 64 x 33
    float* cli = sm + 2112;
    float* Bre = sm + 2*2112;
    float* Bim = sm + 3*2112;
    float* Cre = sm + 4*2112;
    float* Cim = sm + 5*2112;
    float* xd  = sm + 6*2112;        // 64 x 65
    float* G   = sm + 6*2112 + 4160; // 64 x 65
    float* mx  = sm + 6*2112 + 2*4160;  // 64

    int tid = threadIdx.x;
    int bid = blockIdx.x;
    int h = bid & 31;
    int c = (bid >> 5) & 31;
    int b = bid >> 10;
    int blbase = b * SEQ + c * CH;

    for (int e = tid; e < CH*NK; e += 256) {
        int t = e >> 5, k = e & 31;
        int bl = blbase + t;
        clr[t*33+k] = g_lzr[(size_t)bl*(NH*NK) + h*NK + k];
        cli[t*33+k] = g_lzi[(size_t)bl*(NH*NK) + h*NK + k];
        Bre[t*33+k] = g_Br[bl*NK + k];
        Bim[t*33+k] = g_Bi[bl*NK + k];
        Cre[t*33+k] = g_Cr[bl*NK + k];
        Cim[t*33+k] = g_Ci[bl*NK + k];
    }
    for (int e = tid; e < CH*HD; e += 256) {
        int t = e >> 6, p = e & 63;
        int bl = blbase + t;
        xd[t*65+p] = g_xs[(size_t)bl*DIN + h*HD + p] * g_dt[bl*NH + h];
    }
    __syncthreads();

    if (tid < CH) {
        float m = -1e30f;
        #pragma unroll 8
        for (int k = 0; k < NK; k++) m = fmaxf(m, clr[tid*33+k]);
        mx[tid] = m;
    }
    __syncthreads();

    if (tid < 32) {
        float sr = 0.f, si = 0.f;
        for (int t = 0; t < CH; t++) {
            sr += clr[t*33+tid]; si += cli[t*33+tid];
            clr[t*33+tid] = sr;  cli[t*33+tid] = si;
        }
    } else if (tid == 32) {
        float s = 0.f;
        for (int t = 0; t < CH; t++) { s += mx[t]; mx[t] = s; }
    }
    __syncthreads();

    for (int e = tid; e < CH*NK; e += 256) {
        int t = e >> 5, k = e & 31;
        float er = __expf(clr[t*33+k]);
        float sn, cs; __sincosf(cli[t*33+k], &sn, &cs);
        float exr = er*cs, exi = er*sn;
        float cr = Cre[t*33+k], ci = Cim[t*33+k];
        size_t base = (size_t)bid*(CH*NK) + t*NK + k;
        g_Pr[base] = cr*exr - ci*exi;
        g_Pi[base] = cr*exi + ci*exr;
        if (t == CH-1) { g_Er[bid*NK + k] = exr; g_Ei[bid*NK + k] = exi; }
    }
    __syncthreads();

    for (int e = tid; e < CH*NK; e += 256) {
        int t = e >> 5, k = e & 31;
        float cr = Cre[t*33+k], ci = Cim[t*33+k];
        float br = Bre[t*33+k], bi = Bim[t*33+k];
        Cre[t*33+k] = cr*br - ci*bi;
        Cim[t*33+k] = cr*bi + ci*br;
    }
    __syncthreads();

    for (int e = tid; e < CH*CH; e += 256) {
        int t = e >> 6, s = e & 63;
        float acc = 0.f;
        if (s <= t && (s == t || mx[t] - mx[s] > -13.8f)) {
            #pragma unroll 4
            for (int k = 0; k < NK; k++) {
                float dr = clr[t*33+k] - clr[s*33+k];
                if (dr > -13.8f) {
                    float di = cli[t*33+k] - cli[s*33+k];
                    float er = __expf(dr);
                    float sn, cs; __sincosf(di, &sn, &cs);
                    acc += er * (Cre[t*33+k]*cs - Cim[t*33+k]*sn);
                }
            }
        }
        G[t*65+s] = acc;
    }
    __syncthreads();

    float Dh = Dvec[h];
    for (int e = tid; e < CH*HD; e += 256) {
        int t = e >> 6, p = e & 63;
        float acc = 0.f;
        for (int s = 0; s <= t; s++) acc += G[t*65+s] * xd[s*65+p];
        size_t yi = (size_t)(blbase + t)*DIN + h*HD + p;
        g_y[yi] = acc + Dh * g_xs[yi];
    }

    for (int e = tid; e < CH*NK; e += 256) {
        int s = e >> 5, k = e & 31;
        float dr = clr[(CH-1)*33+k] - clr[s*33+k];
        float di = cli[(CH-1)*33+k] - cli[s*33+k];
        float er = __expf(dr);
        float sn, cs; __sincosf(di, &sn, &cs);
        Cre[s*33+k] = er*cs;
        Cim[s*33+k] = er*sn;
    }
    __syncthreads();

    for (int e = tid; e < HD*NK; e += 256) {
        int p = e >> 5, k = e & 31;
        float ar = 0.f, ai = 0.f;
        #pragma unroll 8
        for (int s = 0; s < CH; s++) {
            float xv = xd[s*65+p];
            ar += xv * Cre[s*33+k];
            ai += xv * Cim[s*33+k];
        }
        float br = Bre[(CH-1)*33+k], bi = Bim[(CH-1)*33+k];
        size_t di_ = (size_t)bid*(HD*NK) + p*NK + k;
        g_Dr[di_] = br*ar - bi*ai;
        g_Di[di_] = br*ai + bi*ar;
    }
}

// ---------------- sequential scan over chunks (per b,h,p,k) ----------------------
__global__ void scan_kernel()
{
    int idx = blockIdx.x * blockDim.x + threadIdx.x;
    int k = idx & 31;
    int p = (idx >> 5) & 63;
    int h = (idx >> 11) & 31;
    int b = idx >> 16;
    float sr = 0.f, si = 0.f;
    for (int c = 0; c < NCH; c++) {
        int bidl = (b*NCH + c)*NH + h;
        size_t di_ = (size_t)bidl*(HD*NK) + p*NK + k;
        g_Sr[di_] = sr; g_Si[di_] = si;
        float er = g_Er[bidl*NK + k], ei = g_Ei[bidl*NK + k];
        float dr = g_Dr[di_], dimg = g_Di[di_];
        float nr = er*sr - ei*si + dr;
        float ni = er*si + ei*sr + dimg;
        sr = nr; si = ni;
    }
}

// ---------------- y += Re( P[t,k] * S_entry[p,k] ) -------------------------------
__global__ __launch_bounds__(256) void yinter_kernel()
{
    __shared__ float Pr[2112], Pi[2112], Sr[2112], Si[2112];
    int tid = threadIdx.x, bid = blockIdx.x;
    int h = bid & 31, c = (bid >> 5) & 31, b = bid >> 10;
    size_t base = (size_t)bid * (CH*NK);
    for (int e = tid; e < CH*NK; e += 256) {
        int t = e >> 5, k = e & 31;
        Pr[t*33+k] = g_Pr[base + e];
        Pi[t*33+k] = g_Pi[base + e];
        Sr[t*33+k] = g_Sr[base + e];
        Si[t*33+k] = g_Si[base + e];
    }
    __syncthreads();
    int blbase = b*SEQ + c*CH;
    for (int e = tid; e < CH*HD; e += 256) {
        int t = e >> 6, p = e & 63;
        float acc = 0.f;
        #pragma unroll 8
        for (int k = 0; k < NK; k++)
            acc += Pr[t*33+k]*Sr[p*33+k] - Pi[t*33+k]*Si[p*33+k];
        size_t yi = (size_t)(blbase + t)*DIN + h*HD + p;
        g_y[yi] += acc;
    }
}

// ---------------- gating + RMSNorm -> fp16 ---------------------------------------
__global__ __launch_bounds__(256) void gatenorm_kernel(const float* __restrict__ norm_w)
{
    __shared__ float red[8];
    int bl = blockIdx.x, tid = threadIdx.x;
    float gv[8];
    float local = 0.f;
    #pragma unroll
    for (int i = 0; i < 8; i++) {
        int j = tid + i*256;
        float z = g_zx[(size_t)bl*ZXSTR + j];
        float y = g_y[(size_t)bl*DIN + j];
        float sig = 1.f / (1.f + __expf(-z));
        float g = y * z * sig;
        gv[i] = g;
        local += g * g;
    }
    #pragma unroll
    for (int o = 16; o; o >>= 1) local += __shfl_xor_sync(0xffffffffu, local, o);
    if ((tid & 31) == 0) red[tid >> 5] = local;
    __syncthreads();
    if (tid == 0) {
        float s = 0.f;
        for (int i = 0; i < 8; i++) s += red[i];
        red[0] = rsqrtf(s / (float)DIN + 1e-5f);
    }
    __syncthreads();
    float sc = red[0];
    size_t ro = (size_t)bl * DIN;
    #pragma unroll
    for (int i = 0; i < 8; i++) {
        int j = tid + i*256;
        g_gh[ro + j] = __float2half(gv[i] * sc * norm_w[j]);
    }
}

// ---------------- launch ---------------------------------------------------------
extern "C" void kernel_launch(void* const* d_in, const int* in_sizes, int n_in,
                              void* d_out, int out_size)
{
    (void)in_sizes; (void)n_in; (void)out_size;
    const float* x       = (const float*)d_in[0];
    const float* in_w    = (const float*)d_in[1];
    const float* conv_w  = (const float*)d_in[2];
    const float* conv_b  = (const float*)d_in[3];
    const float* dt_bias = (const float*)d_in[4];
    const float* lam_b   = (const float*)d_in[5];
    const float* th_b    = (const float*)d_in[6];
    const float* w1      = (const float*)d_in[7];
    const float* w2      = (const float*)d_in[8];
    const float* eta     = (const float*)d_in[9];
    const float* Dv      = (const float*)d_in[10];
    const float* nw      = (const float*)d_in[11];
    const float* out_w   = (const float*)d_in[12];
    float* out = (float*)d_out;

    float *zx = nullptr;
    __half *xh, *wih, *gh, *woh;
    cudaGetSymbolAddress((void**)&zx,  g_zx);
    cudaGetSymbolAddress((void**)&xh,  g_xh);
    cudaGetSymbolAddress((void**)&wih, g_wih);
    cudaGetSymbolAddress((void**)&gh,  g_gh);
    cudaGetSymbolAddress((void**)&woh, g_woh);

    cudaFuncSetAttribute(gemm_half, cudaFuncAttributeMaxDynamicSharedMemorySize, GEMM_SMEM);

    // 0) converts
    tofp16_kernel<<<(BLTOT*DM/4+255)/256, 256>>>(x, xh, BLTOT*DM/4);
    tofp16_kernel<<<(DPROJ*DM/4+255)/256, 256>>>(in_w, wih, DPROJ*DM/4);
    splitW1_kernel<<<(DM*LR+255)/256, 256>>>(w1);
    tofp16_kernel<<<(DM*DIN/4+255)/256, 256>>>(out_w, woh, DM*DIN/4);

    // 1) in_proj (+fused lora1): [4096,1024] x [4352,1024]^T -> [4096,4352]
    gemm_half<<<dim3(NPAD_W/128, BLTOT/128), 256, GEMM_SMEM>>>(xh, wih, zx, BLTOT, ZXSTR, DM);
    // 2) dt
    dt_kernel<<<(BLTOT*NH + 255)/256, 256>>>(dt_bias);
    // 3) conv + silu + split
    conv_kernel<<<dim3((CONVD + 255)/256, BLTOT), 256>>>(conv_w, conv_b);
    // 4) lora stage 2 (tanh on load) + log_z
    lora2_kernel<<<dim3(4, BLTOT/64), 256>>>(w2, th_b, lam_b, eta);
    // 5) chunk-parallel heavy kernel
    cudaFuncSetAttribute(chunk_kernel, cudaFuncAttributeMaxDynamicSharedMemorySize, CHUNK_SMEM);
    chunk_kernel<<<BATCHN*NCH*NH, 256, CHUNK_SMEM>>>(Dv);
    // 6) inter-chunk state scan
    scan_kernel<<<(BATCHN*NH*HD*NK)/256, 256>>>();
    // 7) y += P * S_entry
    yinter_kernel<<<BATCHN*NCH*NH, 256>>>();
    // 8) gate + rmsnorm -> fp16
    gatenorm_kernel<<<BLTOT, 256>>>(nw);
    // 9) out_proj: [4096,2048] x [1024,2048]^T -> [4096,1024]
    gemm_half<<<dim3(DM/128, BLTOT/128), 256, GEMM_SMEM>>>(gh, woh, out, BLTOT, DM, DIN);
}

// round 11
// speedup vs baseline: 1.7861x; 1.1687x over previous
#include <cuda_runtime.h>
#include <cuda_fp16.h>
#include <math.h>

#define BATCHN 2
#define SEQ    2048
#define BLTOT  4096
#define DM     1024
#define DIN    2048
#define NH     32
#define HD     64
#define NK     32
#define CONVD  2176
#define DPROJ  4256
#define NCH    32
#define CH     64
#define LR     48
#define XBC_OFF 2048
#define DT_OFF  4224
#define T1_OFF  4256
#define ZXSTR   4352
#define THETA_CLIPF 1.5707963267948966f

#define NPAD_W 4352       // 34*128

// ---------------- scratch (static device globals; no allocation) ----------------
__device__ __align__(256) float g_zx [BLTOT*ZXSTR];
__device__ __align__(256) float g_dt [BLTOT*NH];
__device__ __align__(256) float g_xs [BLTOT*DIN];
__device__ __align__(256) float g_Br [BLTOT*NK];
__device__ __align__(256) float g_Bi [BLTOT*NK];
__device__ __align__(256) float g_Cr [BLTOT*NK];
__device__ __align__(256) float g_Ci [BLTOT*NK];
__device__ __align__(256) float g_lzr[BLTOT*NH*NK];
__device__ __align__(256) float g_lzi[BLTOT*NH*NK];
__device__ __align__(256) float g_Pr [BATCHN*NCH*NH*CH*NK];
__device__ __align__(256) float g_Pi [BATCHN*NCH*NH*CH*NK];
__device__ __align__(256) float g_Er [BATCHN*NCH*NH*NK];
__device__ __align__(256) float g_Ei [BATCHN*NCH*NH*NK];
__device__ __align__(256) float g_Dr [BATCHN*NCH*NH*HD*NK];
__device__ __align__(256) float g_Di [BATCHN*NCH*NH*HD*NK];
__device__ __align__(256) float g_Sr [BATCHN*NCH*NH*HD*NK];
__device__ __align__(256) float g_Si [BATCHN*NCH*NH*HD*NK];
__device__ __align__(256) float g_y  [BLTOT*DIN];

// fp16 buffers (zero-initialized => pad rows are 0)
__device__ __align__(256) __half g_xh [BLTOT*DM];
__device__ __align__(256) __half g_wih[NPAD_W*DM];
__device__ __align__(256) __half g_gh [BLTOT*DIN];
__device__ __align__(256) __half g_woh[DM*DIN];

// ================= asm helpers ==================================================
#define LDSM4(R0,R1,R2,R3,ADDR) \
    asm volatile("ldmatrix.sync.aligned.m8n8.x4.shared.b16 {%0,%1,%2,%3}, [%4];" \
                 : "=r"(R0),"=r"(R1),"=r"(R2),"=r"(R3) : "r"(ADDR))

#define CP_ASYNC16(DST,SRC) \
    asm volatile("cp.async.cg.shared.global [%0], [%1], 16;" :: "r"(DST), "l"(SRC))
#define CP_COMMIT asm volatile("cp.async.commit_group;")
#define CP_WAITP  asm volatile("cp.async.wait_group 0;")

__device__ __forceinline__ unsigned smem_u32(const void* p)
{
    return (unsigned)__cvta_generic_to_shared(p);
}

__device__ __forceinline__ void mma_f16(float* d, const unsigned* a,
                                        unsigned b0, unsigned b1)
{
    asm volatile("mma.sync.aligned.m16n8k16.row.col.f32.f16.f16.f32 "
                 "{%0,%1,%2,%3}, {%4,%5,%6,%7}, {%8,%9}, {%0,%1,%2,%3};"
                 : "+f"(d[0]), "+f"(d[1]), "+f"(d[2]), "+f"(d[3])
                 : "r"(a[0]), "r"(a[1]), "r"(a[2]), "r"(a[3]), "r"(b0), "r"(b1));
}

// ================= fp16 GEMM: C[M,N] = A[M,K] * B[N,K]^T ========================
#define GSTR 72
#define NSTG 2
#define STG_ELE (128*GSTR)
#define GEMM_SMEM (NSTG * 2 * STG_ELE * 2)  // 73728 bytes

__global__ __launch_bounds__(256, 2) void gemm_half(const __half* __restrict__ A,
                                                    const __half* __restrict__ B,
                                                    float* __restrict__ C,
                                                    int M, int N, int K)
{
    extern __shared__ __align__(16) __half smg[];
    __half* sA = smg;
    __half* sB = smg + NSTG*STG_ELE;

    int tid = threadIdx.x, lane = tid & 31, wid = tid >> 5;
    int wm = wid & 3;
    int wn = wid >> 2;
    int row0 = blockIdx.y * 128, col0 = blockIdx.x * 128;

    float acc[2][8][4];
    #pragma unroll
    for (int a = 0; a < 2; a++)
        #pragma unroll
        for (int b = 0; b < 8; b++)
            #pragma unroll
            for (int c = 0; c < 4; c++) acc[a][b][c] = 0.f;

    int NT = K >> 6;

    {
        #pragma unroll
        for (int i = 0; i < 4; i++) {
            int f = tid + i*256, r = f >> 3, kc = (f & 7) << 3;
            CP_ASYNC16(smem_u32(&sA[r*GSTR + kc]), A + (size_t)(row0+r)*K + kc);
            CP_ASYNC16(smem_u32(&sB[r*GSTR + kc]), B + (size_t)(col0+r)*K + kc);
        }
        CP_COMMIT;
    }

    for (int kt = 0; kt < NT; kt++) {
        CP_WAITP;
        __syncthreads();

        {
            int kf = kt + 1;
            if (kf < NT) {
                int s = kf & 1, k0 = kf << 6;
                #pragma unroll
                for (int i = 0; i < 4; i++) {
                    int f = tid + i*256, r = f >> 3, kc = (f & 7) << 3;
                    CP_ASYNC16(smem_u32(&sA[s*STG_ELE + r*GSTR + kc]), A + (size_t)(row0+r)*K + k0 + kc);
                    CP_ASYNC16(smem_u32(&sB[s*STG_ELE + r*GSTR + kc]), B + (size_t)(col0+r)*K + k0 + kc);
                }
                CP_COMMIT;
            }
        }

        const __half* a_s = sA + (kt & 1)*STG_ELE;
        const __half* b_s = sB + (kt & 1)*STG_ELE;

        #pragma unroll
        for (int kh = 0; kh < 64; kh += 16) {
            unsigned ah[2][4];
            #pragma unroll
            for (int mf = 0; mf < 2; mf++) {
                int r = wm*32 + mf*16 + (lane & 15);
                int cc = kh + ((lane >> 4) << 3);
                LDSM4(ah[mf][0], ah[mf][1], ah[mf][2], ah[mf][3],
                      smem_u32(&a_s[r*GSTR + cc]));
            }
            #pragma unroll
            for (int np = 0; np < 4; np++) {
                int nr  = wn*64 + np*16 + (lane & 7) + ((lane >> 4) << 3);
                int kof = kh + (((lane >> 3) & 1) << 3);
                unsigned bh[4];
                LDSM4(bh[0], bh[1], bh[2], bh[3], smem_u32(&b_s[nr*GSTR + kof]));
                #pragma unroll
                for (int mf = 0; mf < 2; mf++) {
                    mma_f16(acc[mf][np*2+0], ah[mf], bh[0], bh[1]);
                    mma_f16(acc[mf][np*2+1], ah[mf], bh[2], bh[3]);
                }
            }
        }
    }

    #pragma unroll
    for (int mf = 0; mf < 2; mf++) {
        int r = row0 + wm*32 + mf*16 + (lane >> 2);
        #pragma unroll
        for (int nf = 0; nf < 8; nf++) {
            int c = col0 + wn*64 + nf*8 + ((lane & 3) << 1);
            if (c + 1 < N) {
                *(float2*)&C[(size_t)r*N + c]     = make_float2(acc[mf][nf][0], acc[mf][nf][1]);
                *(float2*)&C[(size_t)(r+8)*N + c] = make_float2(acc[mf][nf][2], acc[mf][nf][3]);
            } else if (c < N) {
                C[(size_t)r*N + c]     = acc[mf][nf][0];
                C[(size_t)(r+8)*N + c] = acc[mf][nf][2];
            }
        }
    }
}

// ---------------- plain fp32 -> fp16 convert ------------------------------------
__global__ void tofp16_kernel(const float* __restrict__ src,
                              __half* __restrict__ dst, int n4)
{
    int i = blockIdx.x * blockDim.x + threadIdx.x;
    if (i >= n4) return;
    float4 v = *(const float4*)(src + i*4);
    __half2 a, b;
    a.x = __float2half(v.x); a.y = __float2half(v.y);
    b.x = __float2half(v.z); b.y = __float2half(v.w);
    ((__half2*)(dst + i*4))[0] = a;
    ((__half2*)(dst + i*4))[1] = b;
}

// ---------------- w1 (DM x LR) -> rows T1_OFF.. of g_wih ------------------------
__global__ void splitW1_kernel(const float* __restrict__ w1)
{
    int idx = blockIdx.x * blockDim.x + threadIdx.x;
    if (idx >= DM * LR) return;
    int k = idx / LR, n = idx % LR;
    g_wih[(size_t)(T1_OFF + n) * DM + k] = __float2half(w1[idx]);
}

// ---------------- dt = softplus(zx[:, DT_OFF+h] + dt_bias[h]) --------------------
__global__ void dt_kernel(const float* __restrict__ dt_bias)
{
    int idx = blockIdx.x * blockDim.x + threadIdx.x;
    if (idx >= BLTOT * NH) return;
    int bl = idx >> 5, hh = idx & 31;
    float v = g_zx[(size_t)bl * ZXSTR + DT_OFF + hh] + dt_bias[hh];
    float sp = (v > 20.f) ? v : log1pf(expf(v));
    g_dt[idx] = sp;
}

// ---------------- depthwise causal conv (width 4) + silu + split -----------------
__global__ void conv_kernel(const float* __restrict__ conv_w,
                            const float* __restrict__ conv_b)
{
    int c = blockIdx.x * blockDim.x + threadIdx.x;
    if (c >= CONVD) return;
    int bl = blockIdx.y;
    int l = bl & (SEQ - 1);
    float acc = conv_b[c];
    #pragma unroll
    for (int kk = 0; kk < 4; kk++) {
        int lt = l + kk - 3;
        if (lt >= 0)
            acc += g_zx[(size_t)(bl + kk - 3) * ZXSTR + XBC_OFF + c] * conv_w[c*4 + kk];
    }
    float a = acc / (1.f + __expf(-acc));
    if (c < DIN) {
        g_xs[(size_t)bl * DIN + c] = a;
    } else {
        int c2 = c - DIN;
        if (c2 < 64) {
            int k = c2 >> 1;
            if (c2 & 1) g_Bi[bl*NK + k] = a; else g_Br[bl*NK + k] = a;
        } else {
            int c3 = c2 - 64;
            int k = c3 >> 1;
            if (c3 & 1) g_Ci[bl*NK + k] = a; else g_Cr[bl*NK + k] = a;
        }
    }
}

// ---------------- lora2 (tanh applied on load, t1 from zx columns) ---------------
__global__ __launch_bounds__(256) void lora2_kernel(const float* __restrict__ w2,
                                                    const float* __restrict__ theta_base,
                                                    const float* __restrict__ lambda_base,
                                                    const float* __restrict__ eta)
{
    __shared__ float t1s[64][LR];
    __shared__ float w2s[LR][256];
    int tid = threadIdx.x;
    int row0 = blockIdx.y * 64;
    int col0 = blockIdx.x * 256;
    int n = col0 + tid;

    for (int idx = tid; idx < 64*LR; idx += 256) {
        int r = idx / LR, j = idx % LR;
        t1s[r][j] = tanhf(g_zx[(size_t)(row0 + r)*ZXSTR + T1_OFF + j]);
    }
    for (int idx = tid; idx < LR*256; idx += 256) {
        int j = idx >> 8, cc = idx & 255;
        w2s[j][cc] = w2[(size_t)j*(NH*NK) + col0 + cc];
    }
    __syncthreads();

    float tb = theta_base[n];
    float lb = lambda_base[n];
    float et = eta[n];
    int hh = n >> 5;

    for (int r = 0; r < 64; r++) {
        float acc = 0.f;
        #pragma unroll
        for (int j = 0; j < LR; j++) acc += t1s[r][j] * w2s[j][tid];
        float th = tb + acc;
        th = fminf(fmaxf(th, -THETA_CLIPF), THETA_CLIPF);
        float lam = lb + et * th * th;
        int bl = row0 + r;
        float dtv = g_dt[bl*NH + hh];
        g_lzr[(size_t)bl*(NH*NK) + n] = -lam * dtv;
        g_lzi[(size_t)bl*(NH*NK) + n] =  th * dtv;
    }
}

// ---------------- per-chunk kernel (factorized exponentials) ---------------------
// smem float offsets
#define O_CLR 0
#define O_CLI 2112
#define O_CST 4224
#define O_SNT 6336
#define O_WRE 8448
#define O_WIM 10560
#define O_VR  12672
#define O_VI  14784
#define O_XD  16896
#define O_G   (16896+4160)
#define O_B63 (16896+2*4160)
#define CHUNK_FLOATS (O_B63 + 64)
#define CHUNK_SMEM (CHUNK_FLOATS*4)   // 101120 B

__global__ __launch_bounds__(256) void chunk_kernel(const float* __restrict__ Dvec)
{
    extern __shared__ float sm[];
    float* clr = sm + O_CLR;   // 64 x 33 cumsum(lzr)
    float* cli = sm + O_CLI;
    float* csT = sm + O_CST;   // cos(cli), sin(cli)
    float* snT = sm + O_SNT;
    float* wre = sm + O_WRE;   // first C, then w = C*B*U
    float* wim = sm + O_WIM;
    float* vr  = sm + O_VR;    // first B, then per-I v table, then D weights
    float* vi  = sm + O_VI;
    float* xd  = sm + O_XD;    // 64 x 65
    float* G   = sm + O_G;     // 64 x 65
    float* b63 = sm + O_B63;   // B row 63: [0..31]=re, [32..63]=im

    int tid = threadIdx.x;
    int bid = blockIdx.x;
    int h = bid & 31;
    int c = (bid >> 5) & 31;
    int b = bid >> 10;
    int blbase = b * SEQ + c * CH;

    for (int e = tid; e < CH*NK; e += 256) {
        int t = e >> 5, k = e & 31;
        int bl = blbase + t;
        clr[t*33+k] = g_lzr[(size_t)bl*(NH*NK) + h*NK + k];
        cli[t*33+k] = g_lzi[(size_t)bl*(NH*NK) + h*NK + k];
        wre[t*33+k] = g_Cr[bl*NK + k];
        wim[t*33+k] = g_Ci[bl*NK + k];
        vr [t*33+k] = g_Br[bl*NK + k];
        vi [t*33+k] = g_Bi[bl*NK + k];
    }
    for (int e = tid; e < CH*HD; e += 256) {
        int t = e >> 6, p = e & 63;
        int bl = blbase + t;
        xd[t*65+p] = g_xs[(size_t)bl*DIN + h*HD + p] * g_dt[bl*NH + h];
    }
    __syncthreads();

    // cumsum of log_z over t (warp 0, lane = k)
    if (tid < 32) {
        float sr = 0.f, si = 0.f;
        for (int t = 0; t < CH; t++) {
            sr += clr[t*33+tid]; si += cli[t*33+tid];
            clr[t*33+tid] = sr;  cli[t*33+tid] = si;
        }
    }
    __syncthreads();

    // per (t,k): trig cache, P/E outputs, w = (C*B)*U   (U ref = block start)
    for (int e = tid; e < CH*NK; e += 256) {
        int t = e >> 5, k = e & 31;
        float cs, sn; __sincosf(cli[t*33+k], &sn, &cs);
        csT[t*33+k] = cs; snT[t*33+k] = sn;
        float er = __expf(clr[t*33+k]);
        float exr = er*cs, exi = er*sn;
        float cr = wre[t*33+k], ci = wim[t*33+k];
        size_t base = (size_t)bid*(CH*NK) + t*NK + k;
        g_Pr[base] = cr*exr - ci*exi;
        g_Pi[base] = cr*exi + ci*exr;
        float br = vr[t*33+k], bi = vi[t*33+k];
        if (t == CH-1) {
            g_Er[bid*NK + k] = exr; g_Ei[bid*NK + k] = exi;
            b63[k] = br; b63[32+k] = bi;
        }
        // cb = C*B
        float cbr = cr*br - ci*bi;
        float cbi = cr*bi + ci*br;
        // U = exp(clr - ref)*cis(cli),  ref = clr[blockstart-1]
        int bs = t & ~15;
        float refI = (bs > 0) ? clr[(bs-1)*33+k] : 0.f;
        float eu = __expf(clr[t*33+k] - refI);
        float Ur = eu*cs, Ui = eu*sn;
        wre[t*33+k] = cbr*Ur - cbi*Ui;
        wim[t*33+k] = cbr*Ui + cbi*Ur;
    }
    __syncthreads();

    // G block rows: for each t-block I, build v_I then G[t,s] = Re(w[t]*v[s])
    for (int I = 0; I < 4; I++) {
        int tI0 = I << 4;
        for (int e = tid; e < CH*NK; e += 256) {
            int s = e >> 5, k = e & 31;
            float vre = 0.f, vim_ = 0.f;
            if (s < tI0 + 16) {
                float refI = (I > 0) ? clr[(tI0-1)*33+k] : 0.f;
                float ev = __expf(refI - clr[s*33+k]);
                vre  =  ev * csT[s*33+k];
                vim_ = -ev * snT[s*33+k];
            }
            vr[s*33+k] = vre;
            vi[s*33+k] = vim_;
        }
        __syncthreads();
        for (int e = tid; e < 16*CH; e += 256) {
            int t = tI0 + (e >> 6), s = e & 63;
            float acc = 0.f;
            if (s <= t) {
                #pragma unroll 8
                for (int k = 0; k < NK; k++)
                    acc += wre[t*33+k]*vr[s*33+k] - wim[t*33+k]*vi[s*33+k];
            }
            G[t*65+s] = acc;
        }
        __syncthreads();
    }

    // y_intra + D skip
    float Dh = Dvec[h];
    for (int e = tid; e < CH*HD; e += 256) {
        int t = e >> 6, p = e & 63;
        float acc = 0.f;
        for (int s = 0; s <= t; s++) acc += G[t*65+s] * xd[s*65+p];
        size_t yi = (size_t)(blbase + t)*DIN + h*HD + p;
        g_y[yi] = acc + Dh * g_xs[yi];
    }
    __syncthreads();

    // D weights: w2[s,k] = exp(cl63 - cl s) (complex), trig via cached cos/sin
    for (int e = tid; e < CH*NK; e += 256) {
        int s = e >> 5, k = e & 31;
        float er = __expf(clr[(CH-1)*33+k] - clr[s*33+k]);
        float c63 = csT[(CH-1)*33+k], s63 = snT[(CH-1)*33+k];
        float css = csT[s*33+k],      sns = snT[s*33+k];
        vr[s*33+k] = er * (c63*css + s63*sns);   // cos(a-b)
        vi[s*33+k] = er * (s63*css - c63*sns);   // sin(a-b)
    }
    __syncthreads();

    // D_c[p,k] = B63[k] * sum_s w2[s,k]*xd[s,p]
    for (int e = tid; e < HD*NK; e += 256) {
        int p = e >> 5, k = e & 31;
        float ar = 0.f, ai = 0.f;
        #pragma unroll 8
        for (int s = 0; s < CH; s++) {
            float xv = xd[s*65+p];
            ar += xv * vr[s*33+k];
            ai += xv * vi[s*33+k];
        }
        float br = b63[k], bi = b63[32+k];
        size_t di_ = (size_t)bid*(HD*NK) + p*NK + k;
        g_Dr[di_] = br*ar - bi*ai;
        g_Di[di_] = br*ai + bi*ar;
    }
}

// ---------------- sequential scan over chunks (per b,h,p,k) ----------------------
__global__ void scan_kernel()
{
    int idx = blockIdx.x * blockDim.x + threadIdx.x;
    int k = idx & 31;
    int p = (idx >> 5) & 63;
    int h = (idx >> 11) & 31;
    int b = idx >> 16;
    float sr = 0.f, si = 0.f;
    for (int c = 0; c < NCH; c++) {
        int bidl = (b*NCH + c)*NH + h;
        size_t di_ = (size_t)bidl*(HD*NK) + p*NK + k;
        g_Sr[di_] = sr; g_Si[di_] = si;
        float er = g_Er[bidl*NK + k], ei = g_Ei[bidl*NK + k];
        float dr = g_Dr[di_], dimg = g_Di[di_];
        float nr = er*sr - ei*si + dr;
        float ni = er*si + ei*sr + dimg;
        sr = nr; si = ni;
    }
}

// ---------------- y += Re( P[t,k] * S_entry[p,k] ) -------------------------------
__global__ __launch_bounds__(256) void yinter_kernel()
{
    __shared__ float Pr[2112], Pi[2112], Sr[2112], Si[2112];
    int tid = threadIdx.x, bid = blockIdx.x;
    int h = bid & 31, c = (bid >> 5) & 31, b = bid >> 10;
    size_t base = (size_t)bid * (CH*NK);
    for (int e = tid; e < CH*NK; e += 256) {
        int t = e >> 5, k = e & 31;
        Pr[t*33+k] = g_Pr[base + e];
        Pi[t*33+k] = g_Pi[base + e];
        Sr[t*33+k] = g_Sr[base + e];
        Si[t*33+k] = g_Si[base + e];
    }
    __syncthreads();
    int blbase = b*SEQ + c*CH;
    for (int e = tid; e < CH*HD; e += 256) {
        int t = e >> 6, p = e & 63;
        float acc = 0.f;
        #pragma unroll 8
        for (int k = 0; k < NK; k++)
            acc += Pr[t*33+k]*Sr[p*33+k] - Pi[t*33+k]*Si[p*33+k];
        size_t yi = (size_t)(blbase + t)*DIN + h*HD + p;
        g_y[yi] += acc;
    }
}

// ---------------- gating + RMSNorm -> fp16 ---------------------------------------
__global__ __launch_bounds__(256) void gatenorm_kernel(const float* __restrict__ norm_w)
{
    __shared__ float red[8];
    int bl = blockIdx.x, tid = threadIdx.x;
    float gv[8];
    float local = 0.f;
    #pragma unroll
    for (int i = 0; i < 8; i++) {
        int j = tid + i*256;
        float z = g_zx[(size_t)bl*ZXSTR + j];
        float y = g_y[(size_t)bl*DIN + j];
        float sig = 1.f / (1.f + __expf(-z));
        float g = y * z * sig;
        gv[i] = g;
        local += g * g;
    }
    #pragma unroll
    for (int o = 16; o; o >>= 1) local += __shfl_xor_sync(0xffffffffu, local, o);
    if ((tid & 31) == 0) red[tid >> 5] = local;
    __syncthreads();
    if (tid == 0) {
        float s = 0.f;
        for (int i = 0; i < 8; i++) s += red[i];
        red[0] = rsqrtf(s / (float)DIN + 1e-5f);
    }
    __syncthreads();
    float sc = red[0];
    size_t ro = (size_t)bl * DIN;
    #pragma unroll
    for (int i = 0; i < 8; i++) {
        int j = tid + i*256;
        g_gh[ro + j] = __float2half(gv[i] * sc * norm_w[j]);
    }
}

// ---------------- launch ---------------------------------------------------------
extern "C" void kernel_launch(void* const* d_in, const int* in_sizes, int n_in,
                              void* d_out, int out_size)
{
    (void)in_sizes; (void)n_in; (void)out_size;
    const float* x       = (const float*)d_in[0];
    const float* in_w    = (const float*)d_in[1];
    const float* conv_w  = (const float*)d_in[2];
    const float* conv_b  = (const float*)d_in[3];
    const float* dt_bias = (const float*)d_in[4];
    const float* lam_b   = (const float*)d_in[5];
    const float* th_b    = (const float*)d_in[6];
    const float* w1      = (const float*)d_in[7];
    const float* w2      = (const float*)d_in[8];
    const float* eta     = (const float*)d_in[9];
    const float* Dv      = (const float*)d_in[10];
    const float* nw      = (const float*)d_in[11];
    const float* out_w   = (const float*)d_in[12];
    float* out = (float*)d_out;

    float *zx = nullptr;
    __half *xh, *wih, *gh, *woh;
    cudaGetSymbolAddress((void**)&zx,  g_zx);
    cudaGetSymbolAddress((void**)&xh,  g_xh);
    cudaGetSymbolAddress((void**)&wih, g_wih);
    cudaGetSymbolAddress((void**)&gh,  g_gh);
    cudaGetSymbolAddress((void**)&woh, g_woh);

    cudaFuncSetAttribute(gemm_half, cudaFuncAttributeMaxDynamicSharedMemorySize, GEMM_SMEM);
    cudaFuncSetAttribute(chunk_kernel, cudaFuncAttributeMaxDynamicSharedMemorySize, CHUNK_SMEM);

    // 0) converts
    tofp16_kernel<<<(BLTOT*DM/4+255)/256, 256>>>(x, xh, BLTOT*DM/4);
    tofp16_kernel<<<(DPROJ*DM/4+255)/256, 256>>>(in_w, wih, DPROJ*DM/4);
    splitW1_kernel<<<(DM*LR+255)/256, 256>>>(w1);
    tofp16_kernel<<<(DM*DIN/4+255)/256, 256>>>(out_w, woh, DM*DIN/4);

    // 1) in_proj (+fused lora1)
    gemm_half<<<dim3(NPAD_W/128, BLTOT/128), 256, GEMM_SMEM>>>(xh, wih, zx, BLTOT, ZXSTR, DM);
    // 2) dt
    dt_kernel<<<(BLTOT*NH + 255)/256, 256>>>(dt_bias);
    // 3) conv + silu + split
    conv_kernel<<<dim3((CONVD + 255)/256, BLTOT), 256>>>(conv_w, conv_b);
    // 4) lora stage 2 + log_z
    lora2_kernel<<<dim3(4, BLTOT/64), 256>>>(w2, th_b, lam_b, eta);
    // 5) chunk-parallel heavy kernel (factorized)
    chunk_kernel<<<BATCHN*NCH*NH, 256, CHUNK_SMEM>>>(Dv);
    // 6) inter-chunk state scan
    scan_kernel<<<(BATCHN*NH*HD*NK)/256, 256>>>();
    // 7) y += P * S_entry
    yinter_kernel<<<BATCHN*NCH*NH, 256>>>();
    // 8) gate + rmsnorm -> fp16
    gatenorm_kernel<<<BLTOT, 256>>>(nw);
    // 9) out_proj
    gemm_half<<<dim3(DM/128, BLTOT/128), 256, GEMM_SMEM>>>(gh, woh, out, BLTOT, DM, DIN);
}

// round 12
// speedup vs baseline: 1.9279x; 1.0794x over previous
#include <cuda_runtime.h>
#include <cuda_fp16.h>
#include <math.h>

#define BATCHN 2
#define SEQ    2048
#define BLTOT  4096
#define DM     1024
#define DIN    2048
#define NH     32
#define HD     64
#define NK     32
#define CONVD  2176
#define DPROJ  4256
#define NCH    32
#define CH     64
#define LR     48
#define XBC_OFF 2048
#define DT_OFF  4224
#define T1_OFF  4256
#define ZXSTR   4352
#define THETA_CLIPF 1.5707963267948966f

#define NPAD_W 4352       // 34*128

typedef unsigned long long ull;

// ---------------- scratch (static device globals; no allocation) ----------------
__device__ __align__(256) float g_zx [BLTOT*ZXSTR];
__device__ __align__(256) float g_dt [BLTOT*NH];
__device__ __align__(256) float g_xs [BLTOT*DIN];
__device__ __align__(256) float g_Br [BLTOT*NK];
__device__ __align__(256) float g_Bi [BLTOT*NK];
__device__ __align__(256) float g_Cr [BLTOT*NK];
__device__ __align__(256) float g_Ci [BLTOT*NK];
__device__ __align__(256) float g_lzr[BLTOT*NH*NK];
__device__ __align__(256) float g_lzi[BLTOT*NH*NK];
__device__ __align__(256) float g_Pr [BATCHN*NCH*NH*CH*NK];
__device__ __align__(256) float g_Pi [BATCHN*NCH*NH*CH*NK];
__device__ __align__(256) float g_Er [BATCHN*NCH*NH*NK];
__device__ __align__(256) float g_Ei [BATCHN*NCH*NH*NK];
__device__ __align__(256) float g_Dr [BATCHN*NCH*NH*HD*NK];
__device__ __align__(256) float g_Di [BATCHN*NCH*NH*HD*NK];
__device__ __align__(256) float g_Sr [BATCHN*NCH*NH*HD*NK];
__device__ __align__(256) float g_Si [BATCHN*NCH*NH*HD*NK];
__device__ __align__(256) float g_y  [BLTOT*DIN];

// fp16 buffers (zero-initialized => pad rows are 0)
__device__ __align__(256) __half g_xh [BLTOT*DM];
__device__ __align__(256) __half g_wih[NPAD_W*DM];
__device__ __align__(256) __half g_gh [BLTOT*DIN];
__device__ __align__(256) __half g_woh[DM*DIN];

// ================= asm helpers ==================================================
#define LDSM4(R0,R1,R2,R3,ADDR) \
    asm volatile("ldmatrix.sync.aligned.m8n8.x4.shared.b16 {%0,%1,%2,%3}, [%4];" \
                 : "=r"(R0),"=r"(R1),"=r"(R2),"=r"(R3) : "r"(ADDR))

#define CP_ASYNC16(DST,SRC) \
    asm volatile("cp.async.cg.shared.global [%0], [%1], 16;" :: "r"(DST), "l"(SRC))
#define CP_COMMIT asm volatile("cp.async.commit_group;")
#define CP_WAITP  asm volatile("cp.async.wait_group 0;")

// packed f32x2 FMA: acc += a*b (elementwise)
#define FFMA2(ACC,A,B) \
    asm("fma.rn.f32x2 %0, %1, %2, %0;" : "+l"(ACC) : "l"(A), "l"(B))

__device__ __forceinline__ ull pack2(float x, float y)
{
    ull r; asm("mov.b64 %0, {%1, %2};" : "=l"(r) : "f"(x), "f"(y)); return r;
}
__device__ __forceinline__ float2 unpack2(ull v)
{
    float2 r; asm("mov.b64 {%0, %1}, %2;" : "=f"(r.x), "=f"(r.y) : "l"(v)); return r;
}

__device__ __forceinline__ unsigned smem_u32(const void* p)
{
    return (unsigned)__cvta_generic_to_shared(p);
}

__device__ __forceinline__ void mma_f16(float* d, const unsigned* a,
                                        unsigned b0, unsigned b1)
{
    asm volatile("mma.sync.aligned.m16n8k16.row.col.f32.f16.f16.f32 "
                 "{%0,%1,%2,%3}, {%4,%5,%6,%7}, {%8,%9}, {%0,%1,%2,%3};"
                 : "+f"(d[0]), "+f"(d[1]), "+f"(d[2]), "+f"(d[3])
                 : "r"(a[0]), "r"(a[1]), "r"(a[2]), "r"(a[3]), "r"(b0), "r"(b1));
}

// ================= fp16 GEMM: C[M,N] = A[M,K] * B[N,K]^T ========================
#define GSTR 72
#define NSTG 2
#define STG_ELE (128*GSTR)
#define GEMM_SMEM (NSTG * 2 * STG_ELE * 2)  // 73728 bytes

__global__ __launch_bounds__(256, 2) void gemm_half(const __half* __restrict__ A,
                                                    const __half* __restrict__ B,
                                                    float* __restrict__ C,
                                                    int M, int N, int K)
{
    extern __shared__ __align__(16) __half smg[];
    __half* sA = smg;
    __half* sB = smg + NSTG*STG_ELE;

    int tid = threadIdx.x, lane = tid & 31, wid = tid >> 5;
    int wm = wid & 3;
    int wn = wid >> 2;
    int row0 = blockIdx.y * 128, col0 = blockIdx.x * 128;

    float acc[2][8][4];
    #pragma unroll
    for (int a = 0; a < 2; a++)
        #pragma unroll
        for (int b = 0; b < 8; b++)
            #pragma unroll
            for (int c = 0; c < 4; c++) acc[a][b][c] = 0.f;

    int NT = K >> 6;

    {
        #pragma unroll
        for (int i = 0; i < 4; i++) {
            int f = tid + i*256, r = f >> 3, kc = (f & 7) << 3;
            CP_ASYNC16(smem_u32(&sA[r*GSTR + kc]), A + (size_t)(row0+r)*K + kc);
            CP_ASYNC16(smem_u32(&sB[r*GSTR + kc]), B + (size_t)(col0+r)*K + kc);
        }
        CP_COMMIT;
    }

    for (int kt = 0; kt < NT; kt++) {
        CP_WAITP;
        __syncthreads();

        {
            int kf = kt + 1;
            if (kf < NT) {
                int s = kf & 1, k0 = kf << 6;
                #pragma unroll
                for (int i = 0; i < 4; i++) {
                    int f = tid + i*256, r = f >> 3, kc = (f & 7) << 3;
                    CP_ASYNC16(smem_u32(&sA[s*STG_ELE + r*GSTR + kc]), A + (size_t)(row0+r)*K + k0 + kc);
                    CP_ASYNC16(smem_u32(&sB[s*STG_ELE + r*GSTR + kc]), B + (size_t)(col0+r)*K + k0 + kc);
                }
                CP_COMMIT;
            }
        }

        const __half* a_s = sA + (kt & 1)*STG_ELE;
        const __half* b_s = sB + (kt & 1)*STG_ELE;

        #pragma unroll
        for (int kh = 0; kh < 64; kh += 16) {
            unsigned ah[2][4];
            #pragma unroll
            for (int mf = 0; mf < 2; mf++) {
                int r = wm*32 + mf*16 + (lane & 15);
                int cc = kh + ((lane >> 4) << 3);
                LDSM4(ah[mf][0], ah[mf][1], ah[mf][2], ah[mf][3],
                      smem_u32(&a_s[r*GSTR + cc]));
            }
            #pragma unroll
            for (int np = 0; np < 4; np++) {
                int nr  = wn*64 + np*16 + (lane & 7) + ((lane >> 4) << 3);
                int kof = kh + (((lane >> 3) & 1) << 3);
                unsigned bh[4];
                LDSM4(bh[0], bh[1], bh[2], bh[3], smem_u32(&b_s[nr*GSTR + kof]));
                #pragma unroll
                for (int mf = 0; mf < 2; mf++) {
                    mma_f16(acc[mf][np*2+0], ah[mf], bh[0], bh[1]);
                    mma_f16(acc[mf][np*2+1], ah[mf], bh[2], bh[3]);
                }
            }
        }
    }

    #pragma unroll
    for (int mf = 0; mf < 2; mf++) {
        int r = row0 + wm*32 + mf*16 + (lane >> 2);
        #pragma unroll
        for (int nf = 0; nf < 8; nf++) {
            int c = col0 + wn*64 + nf*8 + ((lane & 3) << 1);
            if (c + 1 < N) {
                *(float2*)&C[(size_t)r*N + c]     = make_float2(acc[mf][nf][0], acc[mf][nf][1]);
                *(float2*)&C[(size_t)(r+8)*N + c] = make_float2(acc[mf][nf][2], acc[mf][nf][3]);
            } else if (c < N) {
                C[(size_t)r*N + c]     = acc[mf][nf][0];
                C[(size_t)(r+8)*N + c] = acc[mf][nf][2];
            }
        }
    }
}

// ---------------- plain fp32 -> fp16 convert ------------------------------------
__global__ void tofp16_kernel(const float* __restrict__ src,
                              __half* __restrict__ dst, int n4)
{
    int i = blockIdx.x * blockDim.x + threadIdx.x;
    if (i >= n4) return;
    float4 v = *(const float4*)(src + i*4);
    __half2 a, b;
    a.x = __float2half(v.x); a.y = __float2half(v.y);
    b.x = __float2half(v.z); b.y = __float2half(v.w);
    ((__half2*)(dst + i*4))[0] = a;
    ((__half2*)(dst + i*4))[1] = b;
}

// ---------------- w1 (DM x LR) -> rows T1_OFF.. of g_wih ------------------------
__global__ void splitW1_kernel(const float* __restrict__ w1)
{
    int idx = blockIdx.x * blockDim.x + threadIdx.x;
    if (idx >= DM * LR) return;
    int k = idx / LR, n = idx % LR;
    g_wih[(size_t)(T1_OFF + n) * DM + k] = __float2half(w1[idx]);
}

// ---------------- dt = softplus(zx[:, DT_OFF+h] + dt_bias[h]) --------------------
__global__ void dt_kernel(const float* __restrict__ dt_bias)
{
    int idx = blockIdx.x * blockDim.x + threadIdx.x;
    if (idx >= BLTOT * NH) return;
    int bl = idx >> 5, hh = idx & 31;
    float v = g_zx[(size_t)bl * ZXSTR + DT_OFF + hh] + dt_bias[hh];
    float sp = (v > 20.f) ? v : log1pf(expf(v));
    g_dt[idx] = sp;
}

// ---------------- depthwise causal conv (width 4) + silu + split -----------------
__global__ void conv_kernel(const float* __restrict__ conv_w,
                            const float* __restrict__ conv_b)
{
    int c = blockIdx.x * blockDim.x + threadIdx.x;
    if (c >= CONVD) return;
    int bl = blockIdx.y;
    int l = bl & (SEQ - 1);
    float acc = conv_b[c];
    #pragma unroll
    for (int kk = 0; kk < 4; kk++) {
        int lt = l + kk - 3;
        if (lt >= 0)
            acc += g_zx[(size_t)(bl + kk - 3) * ZXSTR + XBC_OFF + c] * conv_w[c*4 + kk];
    }
    float a = acc / (1.f + __expf(-acc));
    if (c < DIN) {
        g_xs[(size_t)bl * DIN + c] = a;
    } else {
        int c2 = c - DIN;
        if (c2 < 64) {
            int k = c2 >> 1;
            if (c2 & 1) g_Bi[bl*NK + k] = a; else g_Br[bl*NK + k] = a;
        } else {
            int c3 = c2 - 64;
            int k = c3 >> 1;
            if (c3 & 1) g_Ci[bl*NK + k] = a; else g_Cr[bl*NK + k] = a;
        }
    }
}

// ---------------- lora2 (tanh applied on load, t1 from zx columns) ---------------
__global__ __launch_bounds__(256) void lora2_kernel(const float* __restrict__ w2,
                                                    const float* __restrict__ theta_base,
                                                    const float* __restrict__ lambda_base,
                                                    const float* __restrict__ eta)
{
    __shared__ float t1s[64][LR];
    __shared__ float w2s[LR][256];
    int tid = threadIdx.x;
    int row0 = blockIdx.y * 64;
    int col0 = blockIdx.x * 256;
    int n = col0 + tid;

    for (int idx = tid; idx < 64*LR; idx += 256) {
        int r = idx / LR, j = idx % LR;
        t1s[r][j] = tanhf(g_zx[(size_t)(row0 + r)*ZXSTR + T1_OFF + j]);
    }
    for (int idx = tid; idx < LR*256; idx += 256) {
        int j = idx >> 8, cc = idx & 255;
        w2s[j][cc] = w2[(size_t)j*(NH*NK) + col0 + cc];
    }
    __syncthreads();

    float tb = theta_base[n];
    float lb = lambda_base[n];
    float et = eta[n];
    int hh = n >> 5;

    for (int r = 0; r < 64; r++) {
        float acc = 0.f;
        #pragma unroll
        for (int j = 0; j < LR; j++) acc += t1s[r][j] * w2s[j][tid];
        float th = tb + acc;
        th = fminf(fmaxf(th, -THETA_CLIPF), THETA_CLIPF);
        float lam = lb + et * th * th;
        int bl = row0 + r;
        float dtv = g_dt[bl*NH + hh];
        g_lzr[(size_t)bl*(NH*NK) + n] = -lam * dtv;
        g_lzi[(size_t)bl*(NH*NK) + n] =  th * dtv;
    }
}

// ---------------- per-chunk kernel (factorized + packed f32x2) -------------------
// k-arrays stride 34 (8B-aligned rows, conflict-free float2), xd stride 66.
#define KS 34
#define O_CLR 0
#define O_CLI (1*64*KS)
#define O_CST (2*64*KS)
#define O_SNT (3*64*KS)
#define O_WRE (4*64*KS)
#define O_WIM (5*64*KS)
#define O_VR  (6*64*KS)
#define O_VI  (7*64*KS)
#define O_XD  (8*64*KS)            // 64x66
#define O_G   (8*64*KS + 64*66)    // 64x65
#define O_B63 (8*64*KS + 64*66 + 64*65)
#define CHUNK_FLOATS (O_B63 + 64)
#define CHUNK_SMEM (CHUNK_FLOATS*4)

__global__ __launch_bounds__(256) void chunk_kernel(const float* __restrict__ Dvec)
{
    extern __shared__ float sm[];
    float* clr = sm + O_CLR;
    float* cli = sm + O_CLI;
    float* csT = sm + O_CST;
    float* snT = sm + O_SNT;
    float* wre = sm + O_WRE;   // first C, then w = C*B*U (wim stored NEGATED)
    float* wim = sm + O_WIM;
    float* vr  = sm + O_VR;    // first B, then v tables / D weights
    float* vi  = sm + O_VI;
    float* xd  = sm + O_XD;
    float* G   = sm + O_G;
    float* b63 = sm + O_B63;

    int tid = threadIdx.x;
    int bid = blockIdx.x;
    int h = bid & 31;
    int c = (bid >> 5) & 31;
    int b = bid >> 10;
    int blbase = b * SEQ + c * CH;

    for (int e = tid; e < CH*NK; e += 256) {
        int t = e >> 5, k = e & 31;
        int bl = blbase + t;
        clr[t*KS+k] = g_lzr[(size_t)bl*(NH*NK) + h*NK + k];
        cli[t*KS+k] = g_lzi[(size_t)bl*(NH*NK) + h*NK + k];
        wre[t*KS+k] = g_Cr[bl*NK + k];
        wim[t*KS+k] = g_Ci[bl*NK + k];
        vr [t*KS+k] = g_Br[bl*NK + k];
        vi [t*KS+k] = g_Bi[bl*NK + k];
    }
    for (int e = tid; e < CH*HD; e += 256) {
        int t = e >> 6, p = e & 63;
        int bl = blbase + t;
        xd[t*66+p] = g_xs[(size_t)bl*DIN + h*HD + p] * g_dt[bl*NH + h];
    }
    __syncthreads();

    if (tid < 32) {
        float sr = 0.f, si = 0.f;
        for (int t = 0; t < CH; t++) {
            sr += clr[t*KS+tid]; si += cli[t*KS+tid];
            clr[t*KS+tid] = sr;  cli[t*KS+tid] = si;
        }
    }
    __syncthreads();

    // per (t,k): trig cache, P/E outputs, w = (C*B)*U (wim negated)
    for (int e = tid; e < CH*NK; e += 256) {
        int t = e >> 5, k = e & 31;
        float cs, sn; __sincosf(cli[t*KS+k], &sn, &cs);
        csT[t*KS+k] = cs; snT[t*KS+k] = sn;
        float er = __expf(clr[t*KS+k]);
        float exr = er*cs, exi = er*sn;
        float cr = wre[t*KS+k], ci = wim[t*KS+k];
        size_t base = (size_t)bid*(CH*NK) + t*NK + k;
        g_Pr[base] = cr*exr - ci*exi;
        g_Pi[base] = cr*exi + ci*exr;
        float br = vr[t*KS+k], bi = vi[t*KS+k];
        if (t == CH-1) {
            g_Er[bid*NK + k] = exr; g_Ei[bid*NK + k] = exi;
            b63[k] = br; b63[32+k] = bi;
        }
        float cbr = cr*br - ci*bi;
        float cbi = cr*bi + ci*br;
        int bs = t & ~15;
        float refI = (bs > 0) ? clr[(bs-1)*KS+k] : 0.f;
        float eu = __expf(clr[t*KS+k] - refI);
        float Ur = eu*cs, Ui = eu*sn;
        wre[t*KS+k] =  cbr*Ur - cbi*Ui;
        wim[t*KS+k] = -(cbr*Ui + cbi*Ur);   // negated for packed add
    }
    __syncthreads();

    // G blocks
    for (int I = 0; I < 4; I++) {
        int tI0 = I << 4;
        for (int e = tid; e < CH*NK; e += 256) {
            int s = e >> 5, k = e & 31;
            float vre = 0.f, vim_ = 0.f;
            if (s < tI0 + 16) {
                float refI = (I > 0) ? clr[(tI0-1)*KS+k] : 0.f;
                float ev = __expf(refI - clr[s*KS+k]);
                vre  =  ev * csT[s*KS+k];
                vim_ = -ev * snT[s*KS+k];
            }
            vr[s*KS+k] = vre;
            vi[s*KS+k] = vim_;
        }
        __syncthreads();
        for (int e = tid; e < 16*CH; e += 256) {
            int t = tI0 + (e >> 6), s = e & 63;
            float g = 0.f;
            if (s <= t) {
                ull acc = 0ULL;
                #pragma unroll 4
                for (int k = 0; k < NK; k += 2) {
                    ull wr2 = *(const ull*)&wre[t*KS+k];
                    ull wi2 = *(const ull*)&wim[t*KS+k];
                    ull v_r = *(const ull*)&vr[s*KS+k];
                    ull v_i = *(const ull*)&vi[s*KS+k];
                    FFMA2(acc, wr2, v_r);
                    FFMA2(acc, wi2, v_i);
                }
                float2 a = unpack2(acc);
                g = a.x + a.y;
            }
            G[t*65+s] = g;
        }
        __syncthreads();
    }

    // y_intra + D skip (4-wide p tile, packed)
    float Dh = Dvec[h];
    for (int e = tid; e < CH*16; e += 256) {
        int t = e >> 4, pq = (e & 15) << 2;
        ull a0 = 0ULL, a1 = 0ULL;
        for (int s = 0; s <= t; s++) {
            float gv = G[t*65+s];
            ull g2 = pack2(gv, gv);
            ull x0 = *(const ull*)&xd[s*66+pq];
            ull x1 = *(const ull*)&xd[s*66+pq+2];
            FFMA2(a0, g2, x0);
            FFMA2(a1, g2, x1);
        }
        float2 r0 = unpack2(a0), r1 = unpack2(a1);
        size_t yi = (size_t)(blbase + t)*DIN + h*HD + pq;
        float4 xv = *(const float4*)&g_xs[yi];
        float4 out4 = make_float4(r0.x + Dh*xv.x, r0.y + Dh*xv.y,
                                  r1.x + Dh*xv.z, r1.y + Dh*xv.w);
        *(float4*)&g_y[yi] = out4;
    }
    __syncthreads();

    // D weights: v[s,k] = exp(cl63 - cls) (complex) via cached trig
    for (int e = tid; e < CH*NK; e += 256) {
        int s = e >> 5, k = e & 31;
        float er = __expf(clr[(CH-1)*KS+k] - clr[s*KS+k]);
        float c63 = csT[(CH-1)*KS+k], s63 = snT[(CH-1)*KS+k];
        float css = csT[s*KS+k],      sns = snT[s*KS+k];
        vr[s*KS+k] = er * (c63*css + s63*sns);
        vi[s*KS+k] = er * (s63*css - c63*sns);
    }
    __syncthreads();

    // D_c[p,k] = B63[k] * sum_s v[s,k]*xd[s,p]   (k-pair tile, packed)
    for (int e = tid; e < HD*16; e += 256) {
        int p = e >> 4, k = (e & 15) << 1;
        ull ar = 0ULL, ai = 0ULL;
        for (int s = 0; s < CH; s++) {
            float xv = xd[s*66+p];
            ull x2 = pack2(xv, xv);
            ull v_r = *(const ull*)&vr[s*KS+k];
            ull v_i = *(const ull*)&vi[s*KS+k];
            FFMA2(ar, x2, v_r);
            FFMA2(ai, x2, v_i);
        }
        float2 arf = unpack2(ar), aif = unpack2(ai);
        float br0 = b63[k],   bi0 = b63[32+k];
        float br1 = b63[k+1], bi1 = b63[32+k+1];
        size_t di_ = (size_t)bid*(HD*NK) + p*NK + k;
        g_Dr[di_]   = br0*arf.x - bi0*aif.x;
        g_Di[di_]   = br0*aif.x + bi0*arf.x;
        g_Dr[di_+1] = br1*arf.y - bi1*aif.y;
        g_Di[di_+1] = br1*aif.y + bi1*arf.y;
    }
}

// ---------------- sequential scan over chunks (per b,h,p,k) ----------------------
__global__ void scan_kernel()
{
    int idx = blockIdx.x * blockDim.x + threadIdx.x;
    int k = idx & 31;
    int p = (idx >> 5) & 63;
    int h = (idx >> 11) & 31;
    int b = idx >> 16;
    float sr = 0.f, si = 0.f;
    for (int c = 0; c < NCH; c++) {
        int bidl = (b*NCH + c)*NH + h;
        size_t di_ = (size_t)bidl*(HD*NK) + p*NK + k;
        g_Sr[di_] = sr; g_Si[di_] = si;
        float er = g_Er[bidl*NK + k], ei = g_Ei[bidl*NK + k];
        float dr = g_Dr[di_], dimg = g_Di[di_];
        float nr = er*sr - ei*si + dr;
        float ni = er*si + ei*sr + dimg;
        sr = nr; si = ni;
    }
}

// ---------------- y += Re( P[t,k] * S_entry[p,k] )  (packed) ---------------------
__global__ __launch_bounds__(256) void yinter_kernel()
{
    __shared__ float Pr[CH*KS], Pi[CH*KS], Sr[CH*KS], Si[CH*KS];
    int tid = threadIdx.x, bid = blockIdx.x;
    int h = bid & 31, c = (bid >> 5) & 31, b = bid >> 10;
    size_t base = (size_t)bid * (CH*NK);
    for (int e = tid; e < CH*NK; e += 256) {
        int t = e >> 5, k = e & 31;
        Pr[t*KS+k] =  g_Pr[base + e];
        Pi[t*KS+k] = -g_Pi[base + e];   // negated: both terms become adds
        Sr[t*KS+k] =  g_Sr[base + e];   // rows here are p
        Si[t*KS+k] =  g_Si[base + e];
    }
    __syncthreads();
    int blbase = b*SEQ + c*CH;
    for (int e = tid; e < CH*(HD/2); e += 256) {
        int t = e >> 5, p = (e & 31) << 1;
        ull a0 = 0ULL, a1 = 0ULL;
        #pragma unroll 4
        for (int k = 0; k < NK; k += 2) {
            ull pr2 = *(const ull*)&Pr[t*KS+k];
            ull pi2 = *(const ull*)&Pi[t*KS+k];
            ull sr0 = *(const ull*)&Sr[p*KS+k];
            ull si0 = *(const ull*)&Si[p*KS+k];
            ull sr1 = *(const ull*)&Sr[(p+1)*KS+k];
            ull si1 = *(const ull*)&Si[(p+1)*KS+k];
            FFMA2(a0, pr2, sr0); FFMA2(a0, pi2, si0);
            FFMA2(a1, pr2, sr1); FFMA2(a1, pi2, si1);
        }
        float2 f0 = unpack2(a0), f1 = unpack2(a1);
        size_t yi = (size_t)(blbase + t)*DIN + h*HD + p;
        float2 yv = *(float2*)&g_y[yi];
        yv.x += f0.x + f0.y;
        yv.y += f1.x + f1.y;
        *(float2*)&g_y[yi] = yv;
    }
}

// ---------------- gating + RMSNorm -> fp16 ---------------------------------------
__global__ __launch_bounds__(256) void gatenorm_kernel(const float* __restrict__ norm_w)
{
    __shared__ float red[8];
    int bl = blockIdx.x, tid = threadIdx.x;
    float gv[8];
    float local = 0.f;
    #pragma unroll
    for (int i = 0; i < 8; i++) {
        int j = tid + i*256;
        float z = g_zx[(size_t)bl*ZXSTR + j];
        float y = g_y[(size_t)bl*DIN + j];
        float sig = 1.f / (1.f + __expf(-z));
        float g = y * z * sig;
        gv[i] = g;
        local += g * g;
    }
    #pragma unroll
    for (int o = 16; o; o >>= 1) local += __shfl_xor_sync(0xffffffffu, local, o);
    if ((tid & 31) == 0) red[tid >> 5] = local;
    __syncthreads();
    if (tid == 0) {
        float s = 0.f;
        for (int i = 0; i < 8; i++) s += red[i];
        red[0] = rsqrtf(s / (float)DIN + 1e-5f);
    }
    __syncthreads();
    float sc = red[0];
    size_t ro = (size_t)bl * DIN;
    #pragma unroll
    for (int i = 0; i < 8; i++) {
        int j = tid + i*256;
        g_gh[ro + j] = __float2half(gv[i] * sc * norm_w[j]);
    }
}

// ---------------- launch ---------------------------------------------------------
extern "C" void kernel_launch(void* const* d_in, const int* in_sizes, int n_in,
                              void* d_out, int out_size)
{
    (void)in_sizes; (void)n_in; (void)out_size;
    const float* x       = (const float*)d_in[0];
    const float* in_w    = (const float*)d_in[1];
    const float* conv_w  = (const float*)d_in[2];
    const float* conv_b  = (const float*)d_in[3];
    const float* dt_bias = (const float*)d_in[4];
    const float* lam_b   = (const float*)d_in[5];
    const float* th_b    = (const float*)d_in[6];
    const float* w1      = (const float*)d_in[7];
    const float* w2      = (const float*)d_in[8];
    const float* eta     = (const float*)d_in[9];
    const float* Dv      = (const float*)d_in[10];
    const float* nw      = (const float*)d_in[11];
    const float* out_w   = (const float*)d_in[12];
    float* out = (float*)d_out;

    float *zx = nullptr;
    __half *xh, *wih, *gh, *woh;
    cudaGetSymbolAddress((void**)&zx,  g_zx);
    cudaGetSymbolAddress((void**)&xh,  g_xh);
    cudaGetSymbolAddress((void**)&wih, g_wih);
    cudaGetSymbolAddress((void**)&gh,  g_gh);
    cudaGetSymbolAddress((void**)&woh, g_woh);

    cudaFuncSetAttribute(gemm_half, cudaFuncAttributeMaxDynamicSharedMemorySize, GEMM_SMEM);
    cudaFuncSetAttribute(chunk_kernel, cudaFuncAttributeMaxDynamicSharedMemorySize, CHUNK_SMEM);

    // 0) converts
    tofp16_kernel<<<(BLTOT*DM/4+255)/256, 256>>>(x, xh, BLTOT*DM/4);
    tofp16_kernel<<<(DPROJ*DM/4+255)/256, 256>>>(in_w, wih, DPROJ*DM/4);
    splitW1_kernel<<<(DM*LR+255)/256, 256>>>(w1);
    tofp16_kernel<<<(DM*DIN/4+255)/256, 256>>>(out_w, woh, DM*DIN/4);

    // 1) in_proj (+fused lora1)
    gemm_half<<<dim3(NPAD_W/128, BLTOT/128), 256, GEMM_SMEM>>>(xh, wih, zx, BLTOT, ZXSTR, DM);
    // 2) dt
    dt_kernel<<<(BLTOT*NH + 255)/256, 256>>>(dt_bias);
    // 3) conv + silu + split
    conv_kernel<<<dim3((CONVD + 255)/256, BLTOT), 256>>>(conv_w, conv_b);
    // 4) lora stage 2 + log_z
    lora2_kernel<<<dim3(4, BLTOT/64), 256>>>(w2, th_b, lam_b, eta);
    // 5) chunk-parallel heavy kernel (factorized + packed)
    chunk_kernel<<<BATCHN*NCH*NH, 256, CHUNK_SMEM>>>(Dv);
    // 6) inter-chunk state scan
    scan_kernel<<<(BATCHN*NH*HD*NK)/256, 256>>>();
    // 7) y += P * S_entry
    yinter_kernel<<<BATCHN*NCH*NH, 256>>>();
    // 8) gate + rmsnorm -> fp16
    gatenorm_kernel<<<BLTOT, 256>>>(nw);
    // 9) out_proj
    gemm_half<<<dim3(DM/128, BLTOT/128), 256, GEMM_SMEM>>>(gh, woh, out, BLTOT, DM, DIN);
}

// round 13
// speedup vs baseline: 2.2343x; 1.1589x over previous
#include <cuda_runtime.h>
#include <cuda_fp16.h>
#include <math.h>

#define BATCHN 2
#define SEQ    2048
#define BLTOT  4096
#define DM     1024
#define DIN    2048
#define NH     32
#define HD     64
#define NK     32
#define CONVD  2176
#define DPROJ  4256
#define NCH    32
#define CH     64
#define LR     48
#define XBC_OFF 2048
#define DT_OFF  4224
#define T1_OFF  4256
#define ZXSTR   4352
#define THETA_CLIPF 1.5707963267948966f

#define NPAD_W 4352       // 34*128

typedef unsigned long long ull;

// ---------------- scratch (static device globals; no allocation) ----------------
__device__ __align__(256) float g_zx [BLTOT*ZXSTR];
__device__ __align__(256) float g_dt [BLTOT*NH];
__device__ __align__(256) float g_xs [BLTOT*DIN];
__device__ __align__(256) float g_Br [BLTOT*NK];
__device__ __align__(256) float g_Bi [BLTOT*NK];
__device__ __align__(256) float g_Cr [BLTOT*NK];
__device__ __align__(256) float g_Ci [BLTOT*NK];
__device__ __align__(256) float g_lzr[BLTOT*NH*NK];
__device__ __align__(256) float g_lzi[BLTOT*NH*NK];
__device__ __align__(256) float g_Pr [BATCHN*NCH*NH*CH*NK];
__device__ __align__(256) float g_Pi [BATCHN*NCH*NH*CH*NK];
__device__ __align__(256) float g_Er [BATCHN*NCH*NH*NK];
__device__ __align__(256) float g_Ei [BATCHN*NCH*NH*NK];
__device__ __align__(256) float g_Dr [BATCHN*NCH*NH*HD*NK];
__device__ __align__(256) float g_Di [BATCHN*NCH*NH*HD*NK];
__device__ __align__(256) float g_Sr [BATCHN*NCH*NH*HD*NK];
__device__ __align__(256) float g_Si [BATCHN*NCH*NH*HD*NK];
__device__ __align__(256) float g_y  [BLTOT*DIN];

// fp16 buffers (zero-initialized => pad rows are 0)
__device__ __align__(256) __half g_xh [BLTOT*DM];
__device__ __align__(256) __half g_wih[NPAD_W*DM];
__device__ __align__(256) __half g_gh [BLTOT*DIN];
__device__ __align__(256) __half g_woh[DM*DIN];

// ================= asm helpers ==================================================
#define LDSM4(R0,R1,R2,R3,ADDR) \
    asm volatile("ldmatrix.sync.aligned.m8n8.x4.shared.b16 {%0,%1,%2,%3}, [%4];" \
                 : "=r"(R0),"=r"(R1),"=r"(R2),"=r"(R3) : "r"(ADDR))

#define CP_ASYNC16(DST,SRC) \
    asm volatile("cp.async.cg.shared.global [%0], [%1], 16;" :: "r"(DST), "l"(SRC))
#define CP_COMMIT asm volatile("cp.async.commit_group;")
#define CP_WAITP  asm volatile("cp.async.wait_group 0;")

// packed f32x2 FMA: acc += a*b (elementwise)
#define FFMA2(ACC,A,B) \
    asm("fma.rn.f32x2 %0, %1, %2, %0;" : "+l"(ACC) : "l"(A), "l"(B))

__device__ __forceinline__ ull pack2(float x, float y)
{
    ull r; asm("mov.b64 %0, {%1, %2};" : "=l"(r) : "f"(x), "f"(y)); return r;
}
__device__ __forceinline__ float2 unpack2(ull v)
{
    float2 r; asm("mov.b64 {%0, %1}, %2;" : "=f"(r.x), "=f"(r.y) : "l"(v)); return r;
}

__device__ __forceinline__ unsigned smem_u32(const void* p)
{
    return (unsigned)__cvta_generic_to_shared(p);
}

__device__ __forceinline__ void mma_f16(float* d, const unsigned* a,
                                        unsigned b0, unsigned b1)
{
    asm volatile("mma.sync.aligned.m16n8k16.row.col.f32.f16.f16.f32 "
                 "{%0,%1,%2,%3}, {%4,%5,%6,%7}, {%8,%9}, {%0,%1,%2,%3};"
                 : "+f"(d[0]), "+f"(d[1]), "+f"(d[2]), "+f"(d[3])
                 : "r"(a[0]), "r"(a[1]), "r"(a[2]), "r"(a[3]), "r"(b0), "r"(b1));
}

// ================= fp16 GEMM: C[M,N] = A[M,K] * B[N,K]^T ========================
#define GSTR 72
#define NSTG 2
#define STG_ELE (128*GSTR)
#define GEMM_SMEM (NSTG * 2 * STG_ELE * 2)  // 73728 bytes

__global__ __launch_bounds__(256, 2) void gemm_half(const __half* __restrict__ A,
                                                    const __half* __restrict__ B,
                                                    float* __restrict__ C,
                                                    int M, int N, int K)
{
    extern __shared__ __align__(16) __half smg[];
    __half* sA = smg;
    __half* sB = smg + NSTG*STG_ELE;

    int tid = threadIdx.x, lane = tid & 31, wid = tid >> 5;
    int wm = wid & 3;
    int wn = wid >> 2;
    int row0 = blockIdx.y * 128, col0 = blockIdx.x * 128;

    float acc[2][8][4];
    #pragma unroll
    for (int a = 0; a < 2; a++)
        #pragma unroll
        for (int b = 0; b < 8; b++)
            #pragma unroll
            for (int c = 0; c < 4; c++) acc[a][b][c] = 0.f;

    int NT = K >> 6;

    {
        #pragma unroll
        for (int i = 0; i < 4; i++) {
            int f = tid + i*256, r = f >> 3, kc = (f & 7) << 3;
            CP_ASYNC16(smem_u32(&sA[r*GSTR + kc]), A + (size_t)(row0+r)*K + kc);
            CP_ASYNC16(smem_u32(&sB[r*GSTR + kc]), B + (size_t)(col0+r)*K + kc);
        }
        CP_COMMIT;
    }

    for (int kt = 0; kt < NT; kt++) {
        CP_WAITP;
        __syncthreads();

        {
            int kf = kt + 1;
            if (kf < NT) {
                int s = kf & 1, k0 = kf << 6;
                #pragma unroll
                for (int i = 0; i < 4; i++) {
                    int f = tid + i*256, r = f >> 3, kc = (f & 7) << 3;
                    CP_ASYNC16(smem_u32(&sA[s*STG_ELE + r*GSTR + kc]), A + (size_t)(row0+r)*K + k0 + kc);
                    CP_ASYNC16(smem_u32(&sB[s*STG_ELE + r*GSTR + kc]), B + (size_t)(col0+r)*K + k0 + kc);
                }
                CP_COMMIT;
            }
        }

        const __half* a_s = sA + (kt & 1)*STG_ELE;
        const __half* b_s = sB + (kt & 1)*STG_ELE;

        #pragma unroll
        for (int kh = 0; kh < 64; kh += 16) {
            unsigned ah[2][4];
            #pragma unroll
            for (int mf = 0; mf < 2; mf++) {
                int r = wm*32 + mf*16 + (lane & 15);
                int cc = kh + ((lane >> 4) << 3);
                LDSM4(ah[mf][0], ah[mf][1], ah[mf][2], ah[mf][3],
                      smem_u32(&a_s[r*GSTR + cc]));
            }
            #pragma unroll
            for (int np = 0; np < 4; np++) {
                int nr  = wn*64 + np*16 + (lane & 7) + ((lane >> 4) << 3);
                int kof = kh + (((lane >> 3) & 1) << 3);
                unsigned bh[4];
                LDSM4(bh[0], bh[1], bh[2], bh[3], smem_u32(&b_s[nr*GSTR + kof]));
                #pragma unroll
                for (int mf = 0; mf < 2; mf++) {
                    mma_f16(acc[mf][np*2+0], ah[mf], bh[0], bh[1]);
                    mma_f16(acc[mf][np*2+1], ah[mf], bh[2], bh[3]);
                }
            }
        }
    }

    #pragma unroll
    for (int mf = 0; mf < 2; mf++) {
        int r = row0 + wm*32 + mf*16 + (lane >> 2);
        #pragma unroll
        for (int nf = 0; nf < 8; nf++) {
            int c = col0 + wn*64 + nf*8 + ((lane & 3) << 1);
            if (c + 1 < N) {
                *(float2*)&C[(size_t)r*N + c]     = make_float2(acc[mf][nf][0], acc[mf][nf][1]);
                *(float2*)&C[(size_t)(r+8)*N + c] = make_float2(acc[mf][nf][2], acc[mf][nf][3]);
            } else if (c < N) {
                C[(size_t)r*N + c]     = acc[mf][nf][0];
                C[(size_t)(r+8)*N + c] = acc[mf][nf][2];
            }
        }
    }
}

// ---------------- plain fp32 -> fp16 convert ------------------------------------
__global__ void tofp16_kernel(const float* __restrict__ src,
                              __half* __restrict__ dst, int n4)
{
    int i = blockIdx.x * blockDim.x + threadIdx.x;
    if (i >= n4) return;
    float4 v = *(const float4*)(src + i*4);
    __half2 a, b;
    a.x = __float2half(v.x); a.y = __float2half(v.y);
    b.x = __float2half(v.z); b.y = __float2half(v.w);
    ((__half2*)(dst + i*4))[0] = a;
    ((__half2*)(dst + i*4))[1] = b;
}

// ---------------- w1 (DM x LR) -> rows T1_OFF.. of g_wih ------------------------
__global__ void splitW1_kernel(const float* __restrict__ w1)
{
    int idx = blockIdx.x * blockDim.x + threadIdx.x;
    if (idx >= DM * LR) return;
    int k = idx / LR, n = idx % LR;
    g_wih[(size_t)(T1_OFF + n) * DM + k] = __float2half(w1[idx]);
}

// ---------------- dt = softplus(zx[:, DT_OFF+h] + dt_bias[h]) --------------------
__global__ void dt_kernel(const float* __restrict__ dt_bias)
{
    int idx = blockIdx.x * blockDim.x + threadIdx.x;
    if (idx >= BLTOT * NH) return;
    int bl = idx >> 5, hh = idx & 31;
    float v = g_zx[(size_t)bl * ZXSTR + DT_OFF + hh] + dt_bias[hh];
    float sp = (v > 20.f) ? v : log1pf(expf(v));
    g_dt[idx] = sp;
}

// ---------------- depthwise causal conv (smem-tiled) + silu + split --------------
// block: 256 channels x 8 timesteps; halo 3 rows.
__global__ __launch_bounds__(256) void conv_kernel(const float* __restrict__ conv_w,
                                                   const float* __restrict__ conv_b)
{
    __shared__ float tile[11][256];
    int tid = threadIdx.x;
    int c0 = blockIdx.x * 256;
    int bl0 = blockIdx.y * 8;
    int lblk = bl0 & (SEQ - 1);          // within-batch position of row 0

    int c = c0 + tid;
    #pragma unroll
    for (int r = 0; r < 11; r++) {
        float v = 0.f;
        int off = r - 3;
        if (c < CONVD && lblk + off >= 0)
            v = g_zx[(size_t)(bl0 + off) * ZXSTR + XBC_OFF + c];
        tile[r][tid] = v;
    }
    __syncthreads();

    if (c >= CONVD) return;
    float w0 = conv_w[c*4+0], w1 = conv_w[c*4+1], w2 = conv_w[c*4+2], w3 = conv_w[c*4+3];
    float bias = conv_b[c];

    #pragma unroll
    for (int r = 0; r < 8; r++) {
        float acc = bias + tile[r][tid]*w0 + tile[r+1][tid]*w1
                         + tile[r+2][tid]*w2 + tile[r+3][tid]*w3;
        float a = acc / (1.f + __expf(-acc));
        int bl = bl0 + r;
        if (c < DIN) {
            g_xs[(size_t)bl * DIN + c] = a;
        } else {
            int c2 = c - DIN;
            if (c2 < 64) {
                int k = c2 >> 1;
                if (c2 & 1) g_Bi[bl*NK + k] = a; else g_Br[bl*NK + k] = a;
            } else {
                int c3 = c2 - 64;
                int k = c3 >> 1;
                if (c3 & 1) g_Ci[bl*NK + k] = a; else g_Cr[bl*NK + k] = a;
            }
        }
    }
}

// ---------------- lora2 (tanh applied on load, t1 from zx columns) ---------------
__global__ __launch_bounds__(256) void lora2_kernel(const float* __restrict__ w2,
                                                    const float* __restrict__ theta_base,
                                                    const float* __restrict__ lambda_base,
                                                    const float* __restrict__ eta)
{
    __shared__ float t1s[64][LR];
    __shared__ float w2s[LR][256];
    int tid = threadIdx.x;
    int row0 = blockIdx.y * 64;
    int col0 = blockIdx.x * 256;
    int n = col0 + tid;

    for (int idx = tid; idx < 64*LR; idx += 256) {
        int r = idx / LR, j = idx % LR;
        t1s[r][j] = tanhf(g_zx[(size_t)(row0 + r)*ZXSTR + T1_OFF + j]);
    }
    for (int idx = tid; idx < LR*256; idx += 256) {
        int j = idx >> 8, cc = idx & 255;
        w2s[j][cc] = w2[(size_t)j*(NH*NK) + col0 + cc];
    }
    __syncthreads();

    float tb = theta_base[n];
    float lb = lambda_base[n];
    float et = eta[n];
    int hh = n >> 5;

    for (int r = 0; r < 64; r++) {
        float acc = 0.f;
        #pragma unroll
        for (int j = 0; j < LR; j++) acc += t1s[r][j] * w2s[j][tid];
        float th = tb + acc;
        th = fminf(fmaxf(th, -THETA_CLIPF), THETA_CLIPF);
        float lam = lb + et * th * th;
        int bl = row0 + r;
        float dtv = g_dt[bl*NH + hh];
        g_lzr[(size_t)bl*(NH*NK) + n] = -lam * dtv;
        g_lzi[(size_t)bl*(NH*NK) + n] =  th * dtv;
    }
}

// ---------------- per-chunk kernel (factorized, transposed-v G loop) -------------
#define KS 34
#define O_CLR 0
#define O_CLI (1*64*KS)
#define O_CST (2*64*KS)
#define O_SNT (3*64*KS)
#define O_WRE (4*64*KS)
#define O_WIM (5*64*KS)
#define O_VR  (6*64*KS)            // B, then vT[k*66+s] (2112<=2176), then D weights
#define O_VI  (7*64*KS)
#define O_XD  (8*64*KS)            // 64x66
#define O_G   (8*64*KS + 64*66)    // 64x66
#define O_B63 (8*64*KS + 2*64*66)
#define CHUNK_FLOATS (O_B63 + 64)
#define CHUNK_SMEM (CHUNK_FLOATS*4)   // 103,680 B

__global__ __launch_bounds__(256) void chunk_kernel(const float* __restrict__ Dvec)
{
    extern __shared__ float sm[];
    float* clr = sm + O_CLR;
    float* cli = sm + O_CLI;
    float* csT = sm + O_CST;
    float* snT = sm + O_SNT;
    float* wre = sm + O_WRE;   // first C, then w = C*B*U (wim stored NEGATED)
    float* wim = sm + O_WIM;
    float* vr  = sm + O_VR;
    float* vi  = sm + O_VI;
    float* xd  = sm + O_XD;
    float* G   = sm + O_G;
    float* b63 = sm + O_B63;

    int tid = threadIdx.x;
    int bid = blockIdx.x;
    int h = bid & 31;
    int c = (bid >> 5) & 31;
    int b = bid >> 10;
    int blbase = b * SEQ + c * CH;

    for (int e = tid; e < CH*NK; e += 256) {
        int t = e >> 5, k = e & 31;
        int bl = blbase + t;
        clr[t*KS+k] = g_lzr[(size_t)bl*(NH*NK) + h*NK + k];
        cli[t*KS+k] = g_lzi[(size_t)bl*(NH*NK) + h*NK + k];
        wre[t*KS+k] = g_Cr[bl*NK + k];
        wim[t*KS+k] = g_Ci[bl*NK + k];
        vr [t*KS+k] = g_Br[bl*NK + k];
        vi [t*KS+k] = g_Bi[bl*NK + k];
    }
    for (int e = tid; e < CH*HD; e += 256) {
        int t = e >> 6, p = e & 63;
        int bl = blbase + t;
        xd[t*66+p] = g_xs[(size_t)bl*DIN + h*HD + p] * g_dt[bl*NH + h];
    }
    __syncthreads();

    if (tid < 32) {
        float sr = 0.f, si = 0.f;
        for (int t = 0; t < CH; t++) {
            sr += clr[t*KS+tid]; si += cli[t*KS+tid];
            clr[t*KS+tid] = sr;  cli[t*KS+tid] = si;
        }
    }
    __syncthreads();

    // per (t,k): trig cache, P/E outputs, w = (C*B)*U (wim negated)
    for (int e = tid; e < CH*NK; e += 256) {
        int t = e >> 5, k = e & 31;
        float cs, sn; __sincosf(cli[t*KS+k], &sn, &cs);
        csT[t*KS+k] = cs; snT[t*KS+k] = sn;
        float er = __expf(clr[t*KS+k]);
        float exr = er*cs, exi = er*sn;
        float cr = wre[t*KS+k], ci = wim[t*KS+k];
        size_t base = (size_t)bid*(CH*NK) + t*NK + k;
        g_Pr[base] = cr*exr - ci*exi;
        g_Pi[base] = cr*exi + ci*exr;
        float br = vr[t*KS+k], bi = vi[t*KS+k];
        if (t == CH-1) {
            g_Er[bid*NK + k] = exr; g_Ei[bid*NK + k] = exi;
            b63[k] = br; b63[32+k] = bi;
        }
        float cbr = cr*br - ci*bi;
        float cbi = cr*bi + ci*br;
        int bs = t & ~15;
        float refI = (bs > 0) ? clr[(bs-1)*KS+k] : 0.f;
        float eu = __expf(clr[t*KS+k] - refI);
        float Ur = eu*cs, Ui = eu*sn;
        wre[t*KS+k] =  cbr*Ur - cbi*Ui;
        wim[t*KS+k] = -(cbr*Ui + cbi*Ur);   // negated for packed add
    }
    __syncthreads();

    // G blocks: vT transposed [k][66], w broadcast, 2-t tiles, packed s-pairs
    int sp = tid & 31, tg = tid >> 5;
    for (int I = 0; I < 4; I++) {
        int tI0 = I << 4;
        for (int e = tid; e < NK*CH; e += 256) {
            int k = e >> 6, s = e & 63;
            float vre = 0.f, vim_ = 0.f;
            if (s < tI0 + 16) {
                float refI = (I > 0) ? clr[(tI0-1)*KS+k] : 0.f;
                float ev = __expf(refI - clr[s*KS+k]);
                vre  =  ev * csT[s*KS+k];
                vim_ = -ev * snT[s*KS+k];
            }
            vr[k*66+s] = vre;
            vi[k*66+s] = vim_;
        }
        __syncthreads();

        {
            int tA = tI0 + tg, tB = tA + 8;
            int s2 = sp << 1;
            ull accA = 0ULL, accB = 0ULL;
            #pragma unroll 4
            for (int k = 0; k < NK; k++) {
                ull v_r = *(const ull*)&vr[k*66 + s2];
                ull v_i = *(const ull*)&vi[k*66 + s2];
                float wrA = wre[tA*KS+k], wiA = wim[tA*KS+k];
                float wrB = wre[tB*KS+k], wiB = wim[tB*KS+k];
                FFMA2(accA, pack2(wrA, wrA), v_r);
                FFMA2(accA, pack2(wiA, wiA), v_i);
                FFMA2(accB, pack2(wrB, wrB), v_r);
                FFMA2(accB, pack2(wiB, wiB), v_i);
            }
            float2 aA = unpack2(accA), aB = unpack2(accB);
            float2 gA = make_float2((s2   <= tA) ? aA.x : 0.f,
                                    (s2+1 <= tA) ? aA.y : 0.f);
            float2 gB = make_float2((s2   <= tB) ? aB.x : 0.f,
                                    (s2+1 <= tB) ? aB.y : 0.f);
            *(float2*)&G[tA*66 + s2] = gA;
            *(float2*)&G[tB*66 + s2] = gB;
        }
        __syncthreads();
    }

    // y_intra + D skip (4-wide p tile, packed)
    float Dh = Dvec[h];
    for (int e = tid; e < CH*16; e += 256) {
        int t = e >> 4, pq = (e & 15) << 2;
        ull a0 = 0ULL, a1 = 0ULL;
        for (int s = 0; s <= t; s++) {
            float gv = G[t*66+s];
            ull g2 = pack2(gv, gv);
            ull x0 = *(const ull*)&xd[s*66+pq];
            ull x1 = *(const ull*)&xd[s*66+pq+2];
            FFMA2(a0, g2, x0);
            FFMA2(a1, g2, x1);
        }
        float2 r0 = unpack2(a0), r1 = unpack2(a1);
        size_t yi = (size_t)(blbase + t)*DIN + h*HD + pq;
        float4 xv = *(const float4*)&g_xs[yi];
        float4 out4 = make_float4(r0.x + Dh*xv.x, r0.y + Dh*xv.y,
                                  r1.x + Dh*xv.z, r1.y + Dh*xv.w);
        *(float4*)&g_y[yi] = out4;
    }
    __syncthreads();

    // D weights: v[s,k] = exp(cl63 - cls) (complex) via cached trig  ([s][KS] layout)
    for (int e = tid; e < CH*NK; e += 256) {
        int s = e >> 5, k = e & 31;
        float er = __expf(clr[(CH-1)*KS+k] - clr[s*KS+k]);
        float c63 = csT[(CH-1)*KS+k], s63 = snT[(CH-1)*KS+k];
        float css = csT[s*KS+k],      sns = snT[s*KS+k];
        vr[s*KS+k] = er * (c63*css + s63*sns);
        vi[s*KS+k] = er * (s63*css - c63*sns);
    }
    __syncthreads();

    // D_c[p,k] = B63[k] * sum_s v[s,k]*xd[s,p]   (k-pair tile, packed)
    for (int e = tid; e < HD*16; e += 256) {
        int p = e >> 4, k = (e & 15) << 1;
        ull ar = 0ULL, ai = 0ULL;
        for (int s = 0; s < CH; s++) {
            float xv = xd[s*66+p];
            ull x2 = pack2(xv, xv);
            ull v_r = *(const ull*)&vr[s*KS+k];
            ull v_i = *(const ull*)&vi[s*KS+k];
            FFMA2(ar, x2, v_r);
            FFMA2(ai, x2, v_i);
        }
        float2 arf = unpack2(ar), aif = unpack2(ai);
        float br0 = b63[k],   bi0 = b63[32+k];
        float br1 = b63[k+1], bi1 = b63[32+k+1];
        size_t di_ = (size_t)bid*(HD*NK) + p*NK + k;
        g_Dr[di_]   = br0*arf.x - bi0*aif.x;
        g_Di[di_]   = br0*aif.x + bi0*arf.x;
        g_Dr[di_+1] = br1*arf.y - bi1*aif.y;
        g_Di[di_+1] = br1*aif.y + bi1*arf.y;
    }
}

// ---------------- sequential scan over chunks (per b,h,p,k) ----------------------
__global__ void scan_kernel()
{
    int idx = blockIdx.x * blockDim.x + threadIdx.x;
    int k = idx & 31;
    int p = (idx >> 5) & 63;
    int h = (idx >> 11) & 31;
    int b = idx >> 16;
    float sr = 0.f, si = 0.f;
    for (int c = 0; c < NCH; c++) {
        int bidl = (b*NCH + c)*NH + h;
        size_t di_ = (size_t)bidl*(HD*NK) + p*NK + k;
        g_Sr[di_] = sr; g_Si[di_] = si;
        float er = g_Er[bidl*NK + k], ei = g_Ei[bidl*NK + k];
        float dr = g_Dr[di_], dimg = g_Di[di_];
        float nr = er*sr - ei*si + dr;
        float ni = er*si + ei*sr + dimg;
        sr = nr; si = ni;
    }
}

// ---------------- y += Re( P[t,k] * S_entry[p,k] )  (transposed S, packed) -------
__global__ __launch_bounds__(256) void yinter_kernel()
{
    __shared__ float Pr[CH*KS], Pi[CH*KS];
    __shared__ float SrT[NK*66], SiT[NK*66];
    int tid = threadIdx.x, bid = blockIdx.x;
    int h = bid & 31, c = (bid >> 5) & 31, b = bid >> 10;
    size_t base = (size_t)bid * (CH*NK);
    for (int e = tid; e < CH*NK; e += 256) {
        int t = e >> 5, k = e & 31;
        Pr[t*KS+k] =  g_Pr[base + e];
        Pi[t*KS+k] = -g_Pi[base + e];     // negated: both terms add
        // S rows indexed by p: transpose into [k][66+p]
        SrT[k*66+t] = g_Sr[base + e];     // here e's "t" is really p
        SiT[k*66+t] = g_Si[base + e];
    }
    __syncthreads();
    int blbase = b*SEQ + c*CH;
    int sp = tid & 31, tg = tid >> 5;
    int p2 = sp << 1;
    #pragma unroll
    for (int it = 0; it < 4; it++) {
        int tA = 2*tg + 16*it, tB = tA + 1;
        ull aA = 0ULL, aB = 0ULL;
        #pragma unroll 4
        for (int k = 0; k < NK; k++) {
            ull s_r = *(const ull*)&SrT[k*66 + p2];
            ull s_i = *(const ull*)&SiT[k*66 + p2];
            float prA = Pr[tA*KS+k], piA = Pi[tA*KS+k];
            float prB = Pr[tB*KS+k], piB = Pi[tB*KS+k];
            FFMA2(aA, pack2(prA, prA), s_r);
            FFMA2(aA, pack2(piA, piA), s_i);
            FFMA2(aB, pack2(prB, prB), s_r);
            FFMA2(aB, pack2(piB, piB), s_i);
        }
        float2 fA = unpack2(aA), fB = unpack2(aB);
        size_t yA = (size_t)(blbase + tA)*DIN + h*HD + p2;
        size_t yB = (size_t)(blbase + tB)*DIN + h*HD + p2;
        float2 yvA = *(float2*)&g_y[yA];
        float2 yvB = *(float2*)&g_y[yB];
        yvA.x += fA.x; yvA.y += fA.y;
        yvB.x += fB.x; yvB.y += fB.y;
        *(float2*)&g_y[yA] = yvA;
        *(float2*)&g_y[yB] = yvB;
    }
}

// ---------------- gating + RMSNorm -> fp16 ---------------------------------------
__global__ __launch_bounds__(256) void gatenorm_kernel(const float* __restrict__ norm_w)
{
    __shared__ float red[8];
    int bl = blockIdx.x, tid = threadIdx.x;
    float gv[8];
    float local = 0.f;
    #pragma unroll
    for (int i = 0; i < 8; i++) {
        int j = tid + i*256;
        float z = g_zx[(size_t)bl*ZXSTR + j];
        float y = g_y[(size_t)bl*DIN + j];
        float sig = 1.f / (1.f + __expf(-z));
        float g = y * z * sig;
        gv[i] = g;
        local += g * g;
    }
    #pragma unroll
    for (int o = 16; o; o >>= 1) local += __shfl_xor_sync(0xffffffffu, local, o);
    if ((tid & 31) == 0) red[tid >> 5] = local;
    __syncthreads();
    if (tid == 0) {
        float s = 0.f;
        for (int i = 0; i < 8; i++) s += red[i];
        red[0] = rsqrtf(s / (float)DIN + 1e-5f);
    }
    __syncthreads();
    float sc = red[0];
    size_t ro = (size_t)bl * DIN;
    #pragma unroll
    for (int i = 0; i < 8; i++) {
        int j = tid + i*256;
        g_gh[ro + j] = __float2half(gv[i] * sc * norm_w[j]);
    }
}

// ---------------- launch ---------------------------------------------------------
extern "C" void kernel_launch(void* const* d_in, const int* in_sizes, int n_in,
                              void* d_out, int out_size)
{
    (void)in_sizes; (void)n_in; (void)out_size;
    const float* x       = (const float*)d_in[0];
    const float* in_w    = (const float*)d_in[1];
    const float* conv_w  = (const float*)d_in[2];
    const float* conv_b  = (const float*)d_in[3];
    const float* dt_bias = (const float*)d_in[4];
    const float* lam_b   = (const float*)d_in[5];
    const float* th_b    = (const float*)d_in[6];
    const float* w1      = (const float*)d_in[7];
    const float* w2      = (const float*)d_in[8];
    const float* eta     = (const float*)d_in[9];
    const float* Dv      = (const float*)d_in[10];
    const float* nw      = (const float*)d_in[11];
    const float* out_w   = (const float*)d_in[12];
    float* out = (float*)d_out;

    float *zx = nullptr;
    __half *xh, *wih, *gh, *woh;
    cudaGetSymbolAddress((void**)&zx,  g_zx);
    cudaGetSymbolAddress((void**)&xh,  g_xh);
    cudaGetSymbolAddress((void**)&wih, g_wih);
    cudaGetSymbolAddress((void**)&gh,  g_gh);
    cudaGetSymbolAddress((void**)&woh, g_woh);

    cudaFuncSetAttribute(gemm_half, cudaFuncAttributeMaxDynamicSharedMemorySize, GEMM_SMEM);
    cudaFuncSetAttribute(chunk_kernel, cudaFuncAttributeMaxDynamicSharedMemorySize, CHUNK_SMEM);

    // 0) converts
    tofp16_kernel<<<(BLTOT*DM/4+255)/256, 256>>>(x, xh, BLTOT*DM/4);
    tofp16_kernel<<<(DPROJ*DM/4+255)/256, 256>>>(in_w, wih, DPROJ*DM/4);
    splitW1_kernel<<<(DM*LR+255)/256, 256>>>(w1);
    tofp16_kernel<<<(DM*DIN/4+255)/256, 256>>>(out_w, woh, DM*DIN/4);

    // 1) in_proj (+fused lora1)
    gemm_half<<<dim3(NPAD_W/128, BLTOT/128), 256, GEMM_SMEM>>>(xh, wih, zx, BLTOT, ZXSTR, DM);
    // 2) dt
    dt_kernel<<<(BLTOT*NH + 255)/256, 256>>>(dt_bias);
    // 3) conv (tiled) + silu + split
    conv_kernel<<<dim3(9, BLTOT/8), 256>>>(conv_w, conv_b);
    // 4) lora stage 2 + log_z
    lora2_kernel<<<dim3(4, BLTOT/64), 256>>>(w2, th_b, lam_b, eta);
    // 5) chunk-parallel heavy kernel
    chunk_kernel<<<BATCHN*NCH*NH, 256, CHUNK_SMEM>>>(Dv);
    // 6) inter-chunk state scan
    scan_kernel<<<(BATCHN*NH*HD*NK)/256, 256>>>();
    // 7) y += P * S_entry
    yinter_kernel<<<BATCHN*NCH*NH, 256>>>();
    // 8) gate + rmsnorm -> fp16
    gatenorm_kernel<<<BLTOT, 256>>>(nw);
    // 9) out_proj
    gemm_half<<<dim3(DM/128, BLTOT/128), 256, GEMM_SMEM>>>(gh, woh, out, BLTOT, DM, DIN);
}